// round 10
// baseline (speedup 1.0000x reference)
#include <cuda_runtime.h>
#include <cuda_bf16.h>
#include <cstdint>
#include <math.h>

#define Bc 4
#define Sc 4096
#define Dc 1024
#define Hc 16
#define Rc 256
#define HDc 64
#define Mtot (Bc * Sc)
#define BK 32
#define RS 40      // smem row stride in u16 (32 data + 8 pad = 80B)

typedef unsigned short u16;
typedef uint32_t u32;

// ---------------- scratch (device globals) ----------------
__device__ u16 g_xh[(size_t)Mtot * Dc],  g_xl[(size_t)Mtot * Dc];
__device__ u16 g_wqh[Dc * Dc], g_wql[Dc * Dc];
__device__ u16 g_wkh[Dc * Dc], g_wkl[Dc * Dc];
__device__ u16 g_wvh[Dc * Dc], g_wvl[Dc * Dc];
__device__ u16 g_woh[Dc * Dc], g_wol[Dc * Dc];
__device__ u16 g_rfh[(size_t)Hc * Rc * HDc], g_rfl[(size_t)Hc * Rc * HDc];
__device__ u16 g_qh[(size_t)Mtot * Dc],  g_ql[(size_t)Mtot * Dc];
__device__ u16 g_kh[(size_t)Mtot * Dc],  g_kl[(size_t)Mtot * Dc];
__device__ u16 g_vth[(size_t)Mtot * Dc], g_vtl[(size_t)Mtot * Dc];   // V^T [d][m]
__device__ float g_nq[(size_t)Bc * Hc * Sc], g_nk[(size_t)Bc * Hc * Sc];
__device__ u16 g_qph[(size_t)Bc * Hc * Sc * Rc], g_qpl[(size_t)Bc * Hc * Sc * Rc];
__device__ u16 g_kpth[(size_t)Bc * Hc * Rc * Sc], g_kptl[(size_t)Bc * Hc * Rc * Sc]; // kp^T
__device__ float g_kvp[(size_t)Bc * Hc * 4 * Rc * HDc];   // kv split-K partials
__device__ float g_ksp[(size_t)Bc * Hc * 4 * Rc];
__device__ u16 g_kvth[(size_t)Bc * Hc * HDc * Rc], g_kvtl[(size_t)Bc * Hc * HDc * Rc];
__device__ float g_ksum[(size_t)Bc * Hc * Rc];
__device__ u16 g_ath[(size_t)Mtot * Dc], g_atl[(size_t)Mtot * Dc];

// ---------------- helpers ----------------
__device__ __forceinline__ u32 smem_u32(const void* p) {
    u32 a;
    asm("{ .reg .u64 t; cvta.to.shared.u64 t, %1; cvt.u32.u64 %0, t; }" : "=r"(a) : "l"(p));
    return a;
}
__device__ __forceinline__ void bsplit(float a, u16& h, u16& l) {
    __nv_bfloat16 hb = __float2bfloat16_rn(a);
    float lf = a - __bfloat162float(hb);
    __nv_bfloat16 lb = __float2bfloat16_rn(lf);
    h = __bfloat16_as_ushort(hb);
    l = __bfloat16_as_ushort(lb);
}
__device__ __forceinline__ void cpa16(u32 dst, const void* src) {
    asm volatile("cp.async.cg.shared.global [%0], [%1], 16;"
                 :: "r"(dst), "l"(__cvta_generic_to_global(src)) : "memory");
}
__device__ __forceinline__ void mma_bf16(float* c, const u32* A, const u32* B) {
    asm volatile(
        "mma.sync.aligned.m16n8k16.row.col.f32.bf16.bf16.f32 "
        "{%0,%1,%2,%3}, {%4,%5,%6,%7}, {%8,%9}, {%0,%1,%2,%3};"
        : "+f"(c[0]), "+f"(c[1]), "+f"(c[2]), "+f"(c[3])
        : "r"(A[0]), "r"(A[1]), "r"(A[2]), "r"(A[3]), "r"(B[0]), "r"(B[1]));
}
__device__ __forceinline__ void ldsm4(u32& r0, u32& r1, u32& r2, u32& r3, u32 addr) {
    asm volatile("ldmatrix.sync.aligned.m8n8.x4.shared.b16 {%0,%1,%2,%3}, [%4];"
                 : "=r"(r0), "=r"(r1), "=r"(r2), "=r"(r3) : "r"(addr));
}

// ---------------- split / transpose prep ----------------
__global__ void split_kernel(const float4* __restrict__ src, u16* __restrict__ hi,
                             u16* __restrict__ lo, int n4)
{
    for (int i = blockIdx.x * blockDim.x + threadIdx.x; i < n4; i += gridDim.x * blockDim.x) {
        float4 a = src[i];
        ushort4 hv, lv;
        bsplit(a.x, hv.x, lv.x); bsplit(a.y, hv.y, lv.y);
        bsplit(a.z, hv.z, lv.z); bsplit(a.w, hv.w, lv.w);
        *(ushort4*)(hi + (size_t)i * 4) = hv;
        *(ushort4*)(lo + (size_t)i * 4) = lv;
    }
}
__global__ void rft_kernel(const float* __restrict__ rf, u16* __restrict__ oh,
                           u16* __restrict__ ol)
{
    int idx = blockIdx.x * blockDim.x + threadIdx.x;
    if (idx >= Hc * Rc * HDc) return;
    int d = idx & 63, r = (idx >> 6) & 255, h = idx >> 14;
    float a = rf[((size_t)(h * HDc + d)) * Rc + r];
    u16 hv, lv; bsplit(a, hv, lv);
    oh[idx] = hv; ol[idx] = lv;
}

// ---------------- bf16x3 tensor GEMM engine (ldmatrix, BK=32, 3-stage) ---------
// C[128 x NTILE] per CTA; C = A * B^T (fp32 accum), 3-pass bf16 (hh+lh+hl).
// EPI: 0 +bias(col)->f32 | 1 +bias(col)->split + per-head rownorm
//      2 exp(v-0.5*norm[row])->split | 4 normalize by in-loop (A.ksum)->split
//      5 exp(v-0.5*norm[col])->split | 6 +bias(row)->split
//      8 split-K partial: raw f32 out + in-loop A-rowsum partial (chunk=blockIdx.x)
struct TGP {
    const u16 *ah, *al, *bh, *bl;
    long long a_ob, a_oh, b_ob, b_oh, o_ob, o_oh;
    int a_st, b_st, o_st, K;
    const float *bias, *norm, *ksum;
    float* o0;
    u16 *o_hi, *o_lo;
    float* nrm_out;
};

template<int NTILE, int EPI>
__global__ void __launch_bounds__(256, 2) tgemm(TGP p)
{
    extern __shared__ char smc[];
    const int tid = threadIdx.x, lane = tid & 31, wid = tid >> 5;
    const int z = blockIdx.z;
    const int m0 = blockIdx.y << 7;
    const int chunk = (EPI == 8) ? blockIdx.x : 0;
    const int n0 = (EPI == 8) ? 0 : blockIdx.x * NTILE;

    constexpr int MT = (NTILE == 128) ? 4 : 2;
    const int wm0 = (NTILE == 128) ? ((wid & 1) << 6) : ((wid & 3) << 5);
    const int wn0 = (NTILE == 128) ? ((wid >> 1) << 5) : ((wid >> 2) << 5);

    constexpr int APL = 128 * RS * 2;       // bytes per A plane (80B rows)
    constexpr int BPL = NTILE * RS * 2;
    constexpr int BLK = 2 * APL + 2 * BPL;  // one stage
    const u32 su = smem_u32(smc);
    float* const ksums = (float*)(smc + 3 * BLK);   // 256 f
    float* const snorm = ksums + 256;               // 256 f

    size_t aoff = (size_t)p.a_ob * (z >> 4) + (size_t)p.a_oh * (z & 15);
    size_t boff = (size_t)p.b_ob * (z >> 4) + (size_t)p.b_oh * (z & 15);
    const size_t ooff = (size_t)p.o_ob * (z >> 4) + (size_t)p.o_oh * (z & 15);
    if (EPI == 8) { aoff += (size_t)chunk * 1024; boff += (size_t)chunk * 1024; }

    if (EPI == 4) ksums[tid] = p.ksum[(size_t)z * Rc + tid];

    const int steps = p.K / BK;

    auto issue = [&](int step) {
        const int k0 = step * BK;
        const u32 sb = su + (step % 3) * BLK;
        const u16* agh = p.ah + aoff + k0;
        const u16* agl = p.al + aoff + k0;
        const u16* bgh = p.bh + boff + k0;
        const u16* bgl = p.bl + boff + k0;
        #pragma unroll
        for (int j = tid; j < 512; j += 256) {
            int row = j >> 2, ch = j & 3;
            size_t gs = (size_t)(m0 + row) * p.a_st + ch * 8;
            u32 so = row * (RS * 2) + ch * 16;
            cpa16(sb + so, agh + gs);
            cpa16(sb + APL + so, agl + gs);
        }
        #pragma unroll
        for (int j = tid; j < NTILE * 4; j += 256) {
            int row = j >> 2, ch = j & 3;
            size_t gs = (size_t)(n0 + row) * p.b_st + ch * 8;
            u32 so = row * (RS * 2) + ch * 16;
            cpa16(sb + 2 * APL + so, bgh + gs);
            cpa16(sb + 2 * APL + BPL + so, bgl + gs);
        }
        asm volatile("cp.async.commit_group;" ::: "memory");
    };

    issue(0);
    if (steps > 1) issue(1);

    float acc[MT][4][4];
    #pragma unroll
    for (int i = 0; i < MT; i++)
        #pragma unroll
        for (int j = 0; j < 4; j++)
            #pragma unroll
            for (int c = 0; c < 4; c++) acc[i][j][c] = 0.0f;
    float nacc = 0.0f;

    const u32 aoff_lane = (lane & 15) * (RS * 2) + (lane >> 4) * 16;
    const u32 boff_lane = ((lane & 7) + ((lane >> 4) << 3)) * (RS * 2) + ((lane >> 3) & 1) * 16;

    for (int i = 0; i < steps; i++) {
        if (i + 1 < steps) asm volatile("cp.async.wait_group 1;" ::: "memory");
        else               asm volatile("cp.async.wait_group 0;" ::: "memory");
        __syncthreads();
        // single sync per step: prefetch i+2 writes stage (i+2)%3 == (i-1)%3,
        // whose readers (step i-1 compute) all passed the sync above.
        if (i + 2 < steps) issue(i + 2);

        const int buf = i % 3;
        const u32 sb = su + buf * BLK;

        if (EPI == 4 || EPI == 8) {
            int row = tid >> 1, half16 = tid & 1;
            const __nv_bfloat162* xh = (const __nv_bfloat162*)(smc + buf * BLK
                                        + row * (RS * 2) + half16 * 32);
            const __nv_bfloat162* xl = (const __nv_bfloat162*)(smc + buf * BLK + APL
                                        + row * (RS * 2) + half16 * 32);
            if (EPI == 4) {
                const float* kv = ksums + i * BK + half16 * 16;
                #pragma unroll
                for (int t = 0; t < 8; t++) {
                    float2 h2 = __bfloat1622float2(xh[t]);
                    float2 l2 = __bfloat1622float2(xl[t]);
                    nacc += (h2.x + l2.x) * kv[2 * t] + (h2.y + l2.y) * kv[2 * t + 1];
                }
            } else {
                #pragma unroll
                for (int t = 0; t < 8; t++) {
                    float2 h2 = __bfloat1622float2(xh[t]);
                    float2 l2 = __bfloat1622float2(xl[t]);
                    nacc += h2.x + l2.x + h2.y + l2.y;
                }
            }
        }

        #pragma unroll
        for (int half = 0; half < 2; half++) {
            const u32 kb = half * 32;
            u32 ahr[MT][4], alr[MT][4];
            #pragma unroll
            for (int im = 0; im < MT; im++) {
                u32 abase = sb + (wm0 + im * 16) * (RS * 2) + kb + aoff_lane;
                ldsm4(ahr[im][0], ahr[im][1], ahr[im][2], ahr[im][3], abase);
                ldsm4(alr[im][0], alr[im][1], alr[im][2], alr[im][3], abase + APL);
            }
            #pragma unroll
            for (int npair = 0; npair < 2; npair++) {
                u32 bbase = sb + 2 * APL + (wn0 + npair * 16) * (RS * 2) + kb + boff_lane;
                u32 bh0, bh1, bh2_, bh3, bl0, bl1, bl2_, bl3;
                ldsm4(bh0, bh1, bh2_, bh3, bbase);
                ldsm4(bl0, bl1, bl2_, bl3, bbase + BPL);
                u32 bhA[2] = { bh0, bh1 }, bhB[2] = { bh2_, bh3 };
                u32 blA[2] = { bl0, bl1 }, blB[2] = { bl2_, bl3 };
                const int iA = npair * 2, iB = npair * 2 + 1;
                #pragma unroll
                for (int im = 0; im < MT; im++) mma_bf16(acc[im][iA], ahr[im], bhA);
                #pragma unroll
                for (int im = 0; im < MT; im++) mma_bf16(acc[im][iB], ahr[im], bhB);
                #pragma unroll
                for (int im = 0; im < MT; im++) mma_bf16(acc[im][iA], alr[im], bhA);
                #pragma unroll
                for (int im = 0; im < MT; im++) mma_bf16(acc[im][iB], alr[im], bhB);
                #pragma unroll
                for (int im = 0; im < MT; im++) mma_bf16(acc[im][iA], ahr[im], blA);
                #pragma unroll
                for (int im = 0; im < MT; im++) mma_bf16(acc[im][iB], ahr[im], blB);
            }
        }
    }
    __syncthreads();

    if (EPI == 4 || EPI == 8) { snorm[tid] = nacc; __syncthreads(); }
    if (EPI == 1) { ksums[tid] = 0.0f; __syncthreads(); }

    // ---------------- epilogue ----------------
    const int lh = wn0 >> 6;
    #pragma unroll
    for (int im = 0; im < MT; im++) {
        const int la = wm0 + im * 16 + (lane >> 2);
        const int lb = la + 8;
        const int rA = m0 + la, rB = m0 + lb;
        float hnA = 0.0f, hnB = 0.0f, invA = 1.0f, invB = 1.0f;
        float bA = 0.0f, bB = 0.0f;
        if (EPI == 2) {
            hnA = 0.5f * p.norm[(size_t)z * Sc + rA];
            hnB = 0.5f * p.norm[(size_t)z * Sc + rB];
        }
        if (EPI == 6) {
            bA = __ldg(p.bias + rA);
            bB = __ldg(p.bias + rB);
        }
        if (EPI == 4) {
            invA = 1.0f / (snorm[2 * la] + snorm[2 * la + 1] + 1e-6f);
            invB = 1.0f / (snorm[2 * lb] + snorm[2 * lb + 1] + 1e-6f);
        }
        float sA = 0.0f, sB = 0.0f;
        #pragma unroll
        for (int in_ = 0; in_ < 4; in_++) {
            const int n = n0 + wn0 + in_ * 8 + ((lane & 3) << 1);
            float v0 = acc[im][in_][0], v1 = acc[im][in_][1];
            float v2 = acc[im][in_][2], v3 = acc[im][in_][3];
            if (EPI == 0 || EPI == 1) {
                float b0 = __ldg(p.bias + n), b1 = __ldg(p.bias + n + 1);
                v0 += b0; v1 += b1; v2 += b0; v3 += b1;
            } else if (EPI == 6) {
                v0 += bA; v1 += bA; v2 += bB; v3 += bB;
            } else if (EPI == 2) {
                v0 = __expf(v0 - hnA); v1 = __expf(v1 - hnA);
                v2 = __expf(v2 - hnB); v3 = __expf(v3 - hnB);
            } else if (EPI == 5) {
                float hn0 = 0.5f * __ldg(p.norm + (size_t)z * Sc + n);
                float hn1 = 0.5f * __ldg(p.norm + (size_t)z * Sc + n + 1);
                v0 = __expf(v0 - hn0); v1 = __expf(v1 - hn1);
                v2 = __expf(v2 - hn0); v3 = __expf(v3 - hn1);
            } else if (EPI == 4) {
                v0 *= invA; v1 *= invA; v2 *= invB; v3 *= invB;
            }
            if (EPI == 1) { sA += v0 * v0 + v1 * v1; sB += v2 * v2 + v3 * v3; }
            if (EPI == 0) {
                *(float2*)(p.o0 + ooff + (size_t)rA * p.o_st + n) = make_float2(v0, v1);
                *(float2*)(p.o0 + ooff + (size_t)rB * p.o_st + n) = make_float2(v2, v3);
            } else if (EPI == 8) {
                float* b8 = p.o0 + (((size_t)z * 4 + chunk) << 14);
                *(float2*)(b8 + (size_t)rA * 64 + n) = make_float2(v0, v1);
                *(float2*)(b8 + (size_t)rB * 64 + n) = make_float2(v2, v3);
            } else {
                u16 h0, l0, h1, l1, h2, l2, h3, l3;
                bsplit(v0, h0, l0); bsplit(v1, h1, l1);
                bsplit(v2, h2, l2); bsplit(v3, h3, l3);
                size_t oA = ooff + (size_t)rA * p.o_st + n;
                size_t oB = ooff + (size_t)rB * p.o_st + n;
                *(u32*)(p.o_hi + oA) = (u32)h0 | ((u32)h1 << 16);
                *(u32*)(p.o_lo + oA) = (u32)l0 | ((u32)l1 << 16);
                *(u32*)(p.o_hi + oB) = (u32)h2 | ((u32)h3 << 16);
                *(u32*)(p.o_lo + oB) = (u32)l2 | ((u32)l3 << 16);
            }
        }
        if (EPI == 1) {
            atomicAdd(&ksums[la * 2 + lh], sA);
            atomicAdd(&ksums[lb * 2 + lh], sB);
        }
    }

    if (EPI == 1) {
        __syncthreads();
        int row = tid >> 1, hloc = tid & 1;
        int rg = m0 + row, b = rg >> 12, s = rg & 4095;
        int head = (n0 >> 6) + hloc;
        p.nrm_out[(size_t)(b * 16 + head) * Sc + s] = ksums[tid];
    }
    if (EPI == 8) {
        if (tid < 128)
            p.nrm_out[(((size_t)z * 4 + chunk) << 8) + m0 + tid] =
                snorm[2 * tid] + snorm[2 * tid + 1];
    }
}

// ---------------- kv final reduce ----------------
__global__ void kvfinal_kernel(const float* __restrict__ kvp, const float* __restrict__ ksp,
                               u16* __restrict__ kvth, u16* __restrict__ kvtl,
                               float* __restrict__ ks)
{
    size_t idx = (size_t)blockIdx.x * 256 + threadIdx.x;
    int r = (int)(idx & 255), d = (int)((idx >> 8) & 63), bh = (int)(idx >> 14);
    float s = 0.0f;
    #pragma unroll
    for (int c = 0; c < 4; c++)
        s += kvp[(((size_t)bh * 4 + c) << 14) + (r << 6) + d];
    u16 hv, lv; bsplit(s, hv, lv);
    size_t o = ((size_t)bh << 14) + (d << 8) + r;
    kvth[o] = hv; kvtl[o] = lv;
    if (idx < (size_t)64 * 256) {
        int bh2 = (int)(idx >> 8), r2 = (int)(idx & 255);
        float t = 0.0f;
        #pragma unroll
        for (int c = 0; c < 4; c++) t += ksp[((size_t)(bh2 * 4 + c) << 8) + r2];
        ks[idx] = t;
    }
}

// ---------------- launch ----------------
extern "C" void kernel_launch(void* const* d_in, const int* in_sizes, int n_in,
                              void* d_out, int out_size)
{
    (void)in_sizes; (void)n_in; (void)out_size;
    const float* x  = (const float*)d_in[0];
    const float* wq = (const float*)d_in[1];
    const float* bq = (const float*)d_in[2];
    const float* wk = (const float*)d_in[3];
    const float* bk = (const float*)d_in[4];
    const float* wv = (const float*)d_in[5];
    const float* bv = (const float*)d_in[6];
    const float* wo = (const float*)d_in[7];
    const float* bo = (const float*)d_in[8];
    const float* rf = (const float*)d_in[9];
    float* out = (float*)d_out;

    u16 *xh, *xl, *wqh, *wql, *wkh, *wkl, *wvh, *wvl, *woh, *wol;
    u16 *rfh, *rfl, *qh, *ql, *kh, *kl, *vth, *vtl, *qph, *qpl;
    u16 *kpth, *kptl, *kvth, *kvtl, *ath, *atl;
    float *nq, *nk, *kvp, *ksp, *ksum;
    cudaGetSymbolAddress((void**)&xh,  g_xh);   cudaGetSymbolAddress((void**)&xl,  g_xl);
    cudaGetSymbolAddress((void**)&wqh, g_wqh);  cudaGetSymbolAddress((void**)&wql, g_wql);
    cudaGetSymbolAddress((void**)&wkh, g_wkh);  cudaGetSymbolAddress((void**)&wkl, g_wkl);
    cudaGetSymbolAddress((void**)&wvh, g_wvh);  cudaGetSymbolAddress((void**)&wvl, g_wvl);
    cudaGetSymbolAddress((void**)&woh, g_woh);  cudaGetSymbolAddress((void**)&wol, g_wol);
    cudaGetSymbolAddress((void**)&rfh, g_rfh);  cudaGetSymbolAddress((void**)&rfl, g_rfl);
    cudaGetSymbolAddress((void**)&qh,  g_qh);   cudaGetSymbolAddress((void**)&ql,  g_ql);
    cudaGetSymbolAddress((void**)&kh,  g_kh);   cudaGetSymbolAddress((void**)&kl,  g_kl);
    cudaGetSymbolAddress((void**)&vth, g_vth);  cudaGetSymbolAddress((void**)&vtl, g_vtl);
    cudaGetSymbolAddress((void**)&nq,  g_nq);   cudaGetSymbolAddress((void**)&nk,  g_nk);
    cudaGetSymbolAddress((void**)&qph, g_qph);  cudaGetSymbolAddress((void**)&qpl, g_qpl);
    cudaGetSymbolAddress((void**)&kpth, g_kpth);cudaGetSymbolAddress((void**)&kptl, g_kptl);
    cudaGetSymbolAddress((void**)&kvp, g_kvp);  cudaGetSymbolAddress((void**)&ksp, g_ksp);
    cudaGetSymbolAddress((void**)&kvth, g_kvth);cudaGetSymbolAddress((void**)&kvtl, g_kvtl);
    cudaGetSymbolAddress((void**)&ksum, g_ksum);
    cudaGetSymbolAddress((void**)&ath, g_ath);  cudaGetSymbolAddress((void**)&atl, g_atl);

    // smem: 3 stages + 2KB epilogue scratch
    const int SM128 = 3 * (2 * 128 * RS * 2 + 2 * 128 * RS * 2) + 2048;  // 124928
    const int SM64  = 3 * (2 * 128 * RS * 2 + 2 * 64 * RS * 2) + 2048;   // 94208
    cudaFuncSetAttribute(tgemm<128, 0>, cudaFuncAttributeMaxDynamicSharedMemorySize, SM128);
    cudaFuncSetAttribute(tgemm<128, 1>, cudaFuncAttributeMaxDynamicSharedMemorySize, SM128);
    cudaFuncSetAttribute(tgemm<128, 2>, cudaFuncAttributeMaxDynamicSharedMemorySize, SM128);
    cudaFuncSetAttribute(tgemm<128, 5>, cudaFuncAttributeMaxDynamicSharedMemorySize, SM128);
    cudaFuncSetAttribute(tgemm<128, 6>, cudaFuncAttributeMaxDynamicSharedMemorySize, SM128);
    cudaFuncSetAttribute(tgemm<64, 4>,  cudaFuncAttributeMaxDynamicSharedMemorySize, SM64);
    cudaFuncSetAttribute(tgemm<64, 8>,  cudaFuncAttributeMaxDynamicSharedMemorySize, SM64);

    // splits
    split_kernel<<<2048, 256>>>((const float4*)x, xh, xl, Mtot * Dc / 4);
    split_kernel<<<512, 256>>>((const float4*)wq, wqh, wql, Dc * Dc / 4);
    split_kernel<<<512, 256>>>((const float4*)wk, wkh, wkl, Dc * Dc / 4);
    split_kernel<<<512, 256>>>((const float4*)wv, wvh, wvl, Dc * Dc / 4);
    split_kernel<<<512, 256>>>((const float4*)wo, woh, wol, Dc * Dc / 4);
    rft_kernel<<<(Hc * Rc * HDc + 255) / 256, 256>>>(rf, rfh, rfl);

    // Q/K projections (M=16384, N=1024, K=1024)
    dim3 gproj(Dc / 128, Mtot / 128, 1);
    TGP pj = {};
    pj.ah = xh; pj.al = xl; pj.a_ob = 0; pj.a_oh = 0; pj.a_st = Dc;
    pj.b_ob = 0; pj.b_oh = 0; pj.b_st = Dc; pj.K = Dc;
    pj.o_ob = 0; pj.o_oh = 0; pj.o_st = Dc;

    TGP pq = pj; pq.bh = wqh; pq.bl = wql; pq.bias = bq;
    pq.o_hi = qh; pq.o_lo = ql; pq.nrm_out = nq;
    tgemm<128, 1><<<gproj, 256, SM128>>>(pq);
    TGP pk = pj; pk.bh = wkh; pk.bl = wkl; pk.bias = bk;
    pk.o_hi = kh; pk.o_lo = kl; pk.nrm_out = nk;
    tgemm<128, 1><<<gproj, 256, SM128>>>(pk);

    // V projection TRANSPOSED: C[d, m] = wv * x^T
    dim3 gvt(Mtot / 128, Dc / 128, 1);
    TGP pv = {};
    pv.ah = wvh; pv.al = wvl; pv.a_ob = 0; pv.a_oh = 0; pv.a_st = Dc;
    pv.bh = xh;  pv.bl = xl;  pv.b_ob = 0; pv.b_oh = 0; pv.b_st = Dc;
    pv.K = Dc; pv.bias = bv;
    pv.o_hi = vth; pv.o_lo = vtl; pv.o_ob = 0; pv.o_oh = 0; pv.o_st = Mtot;
    tgemm<128, 6><<<gvt, 256, SM128>>>(pv);

    // feature-Q (per bh: M=4096 s, N=256 r, K=64)
    dim3 gfeat(Rc / 128, Sc / 128, Bc * Hc);
    TGP pfq = {};
    pfq.ah = qh; pfq.al = ql;
    pfq.a_ob = (long long)Sc * Dc; pfq.a_oh = HDc; pfq.a_st = Dc;
    pfq.bh = rfh; pfq.bl = rfl;
    pfq.b_ob = 0; pfq.b_oh = (long long)Rc * HDc; pfq.b_st = HDc;
    pfq.K = HDc; pfq.norm = nq;
    pfq.o_hi = qph; pfq.o_lo = qpl;
    pfq.o_ob = (long long)16 * Sc * Rc; pfq.o_oh = (long long)Sc * Rc; pfq.o_st = Rc;
    tgemm<128, 2><<<gfeat, 256, SM128>>>(pfq);

    // feature-K TRANSPOSED (per bh: M=256 r, N=4096 s, K=64) -> kp^T split
    dim3 gfkt(Sc / 128, Rc / 128, Bc * Hc);
    TGP pfk = {};
    pfk.ah = rfh; pfk.al = rfl;
    pfk.a_ob = 0; pfk.a_oh = (long long)Rc * HDc; pfk.a_st = HDc;
    pfk.bh = kh; pfk.bl = kl;
    pfk.b_ob = (long long)Sc * Dc; pfk.b_oh = HDc; pfk.b_st = Dc;
    pfk.K = HDc; pfk.norm = nk;
    pfk.o_hi = kpth; pfk.o_lo = kptl;
    pfk.o_ob = (long long)16 * Rc * Sc; pfk.o_oh = (long long)Rc * Sc; pfk.o_st = Sc;
    tgemm<128, 5><<<gfkt, 256, SM128>>>(pfk);

    // kv aggregation GEMM (per bh: M=256 r, N=64 d, K=4096 s, split-K x4)
    dim3 gkv(4, Rc / 128, Bc * Hc);
    TGP pkv = {};
    pkv.ah = kpth; pkv.al = kptl;
    pkv.a_ob = (long long)16 * Rc * Sc; pkv.a_oh = (long long)Rc * Sc; pkv.a_st = Sc;
    pkv.bh = vth; pkv.bl = vtl;
    pkv.b_ob = 4096; pkv.b_oh = (long long)64 * Mtot; pkv.b_st = Mtot;
    pkv.K = 1024;
    pkv.o0 = kvp; pkv.nrm_out = ksp;
    tgemm<64, 8><<<gkv, 256, SM64>>>(pkv);

    kvfinal_kernel<<<4096, 256>>>(kvp, ksp, kvth, kvtl, ksum);

    // attention readout (per bh: M=4096 s, N=64 d, K=256 r) + normalize
    dim3 gat(1, Sc / 128, Bc * Hc);
    TGP pa = {};
    pa.ah = qph; pa.al = qpl;
    pa.a_ob = (long long)16 * Sc * Rc; pa.a_oh = (long long)Sc * Rc; pa.a_st = Rc;
    pa.bh = kvth; pa.bl = kvtl;
    pa.b_ob = (long long)16 * HDc * Rc; pa.b_oh = (long long)HDc * Rc; pa.b_st = Rc;
    pa.K = Rc; pa.ksum = ksum;
    pa.o_hi = ath; pa.o_lo = atl;
    pa.o_ob = (long long)Sc * Dc; pa.o_oh = HDc; pa.o_st = Dc;
    tgemm<64, 4><<<gat, 256, SM64>>>(pa);

    // output projection
    TGP po = pj; po.ah = ath; po.al = atl; po.bh = woh; po.bl = wol;
    po.bias = bo; po.o0 = out;
    tgemm<128, 0><<<gproj, 256, SM128>>>(po);
}

// round 11
// speedup vs baseline: 1.1815x; 1.1815x over previous
#include <cuda_runtime.h>
#include <cuda_bf16.h>
#include <cstdint>
#include <math.h>

#define Bc 4
#define Sc 4096
#define Dc 1024
#define Hc 16
#define Rc 256
#define HDc 64
#define Mtot (Bc * Sc)
#define BK 32
#define RS 40      // smem row stride in u16 (32 data + 8 pad = 80B)

typedef unsigned short u16;
typedef uint32_t u32;

// ---------------- scratch (device globals) ----------------
__device__ u16 g_xh[(size_t)Mtot * Dc],  g_xl[(size_t)Mtot * Dc];
__device__ u16 g_wqh[Dc * Dc], g_wql[Dc * Dc];
__device__ u16 g_wkh[Dc * Dc], g_wkl[Dc * Dc];
__device__ u16 g_wvh[Dc * Dc], g_wvl[Dc * Dc];
__device__ u16 g_woh[Dc * Dc], g_wol[Dc * Dc];
__device__ u16 g_rfh[(size_t)Hc * Rc * HDc], g_rfl[(size_t)Hc * Rc * HDc];
__device__ u16 g_qh[(size_t)Mtot * Dc],  g_ql[(size_t)Mtot * Dc];
__device__ u16 g_kh[(size_t)Mtot * Dc],  g_kl[(size_t)Mtot * Dc];
__device__ u16 g_vth[(size_t)Mtot * Dc], g_vtl[(size_t)Mtot * Dc];   // V^T [d][m]
__device__ float g_nq[(size_t)Bc * Hc * Sc], g_nk[(size_t)Bc * Hc * Sc];
__device__ u16 g_qph[(size_t)Bc * Hc * Sc * Rc], g_qpl[(size_t)Bc * Hc * Sc * Rc];
__device__ u16 g_kpth[(size_t)Bc * Hc * Rc * Sc], g_kptl[(size_t)Bc * Hc * Rc * Sc]; // kp^T
__device__ float g_kvp[(size_t)Bc * Hc * 4 * Rc * HDc];   // kv split-K partials
__device__ float g_ksp[(size_t)Bc * Hc * 4 * Rc];
__device__ u16 g_kvth[(size_t)Bc * Hc * HDc * Rc], g_kvtl[(size_t)Bc * Hc * HDc * Rc];
__device__ float g_ksum[(size_t)Bc * Hc * Rc];
__device__ u16 g_ath[(size_t)Mtot * Dc], g_atl[(size_t)Mtot * Dc];

// ---------------- helpers ----------------
__device__ __forceinline__ u32 smem_u32(const void* p) {
    u32 a;
    asm("{ .reg .u64 t; cvta.to.shared.u64 t, %1; cvt.u32.u64 %0, t; }" : "=r"(a) : "l"(p));
    return a;
}
__device__ __forceinline__ void bsplit(float a, u16& h, u16& l) {
    __nv_bfloat16 hb = __float2bfloat16_rn(a);
    float lf = a - __bfloat162float(hb);
    __nv_bfloat16 lb = __float2bfloat16_rn(lf);
    h = __bfloat16_as_ushort(hb);
    l = __bfloat16_as_ushort(lb);
}
__device__ __forceinline__ void cpa16(u32 dst, const void* src) {
    asm volatile("cp.async.cg.shared.global [%0], [%1], 16;"
                 :: "r"(dst), "l"(__cvta_generic_to_global(src)) : "memory");
}
__device__ __forceinline__ void mma_bf16(float* c, const u32* A, const u32* B) {
    asm volatile(
        "mma.sync.aligned.m16n8k16.row.col.f32.bf16.bf16.f32 "
        "{%0,%1,%2,%3}, {%4,%5,%6,%7}, {%8,%9}, {%0,%1,%2,%3};"
        : "+f"(c[0]), "+f"(c[1]), "+f"(c[2]), "+f"(c[3])
        : "r"(A[0]), "r"(A[1]), "r"(A[2]), "r"(A[3]), "r"(B[0]), "r"(B[1]));
}
__device__ __forceinline__ void ldsm4(u32& r0, u32& r1, u32& r2, u32& r3, u32 addr) {
    asm volatile("ldmatrix.sync.aligned.m8n8.x4.shared.b16 {%0,%1,%2,%3}, [%4];"
                 : "=r"(r0), "=r"(r1), "=r"(r2), "=r"(r3) : "r"(addr));
}

// ---------------- split / transpose prep ----------------
__global__ void split_kernel(const float4* __restrict__ src, u16* __restrict__ hi,
                             u16* __restrict__ lo, int n4)
{
    for (int i = blockIdx.x * blockDim.x + threadIdx.x; i < n4; i += gridDim.x * blockDim.x) {
        float4 a = src[i];
        ushort4 hv, lv;
        bsplit(a.x, hv.x, lv.x); bsplit(a.y, hv.y, lv.y);
        bsplit(a.z, hv.z, lv.z); bsplit(a.w, hv.w, lv.w);
        *(ushort4*)(hi + (size_t)i * 4) = hv;
        *(ushort4*)(lo + (size_t)i * 4) = lv;
    }
}
__global__ void rft_kernel(const float* __restrict__ rf, u16* __restrict__ oh,
                           u16* __restrict__ ol)
{
    int idx = blockIdx.x * blockDim.x + threadIdx.x;
    if (idx >= Hc * Rc * HDc) return;
    int d = idx & 63, r = (idx >> 6) & 255, h = idx >> 14;
    float a = rf[((size_t)(h * HDc + d)) * Rc + r];
    u16 hv, lv; bsplit(a, hv, lv);
    oh[idx] = hv; ol[idx] = lv;
}

// ---------------- bf16x3 tensor GEMM engine (ldmatrix, BK=32, 2-stage) ---------
// C[128 x NTILE] per CTA; C = A * B^T (fp32 accum), 3-pass bf16 (hh+lh+hl).
// Single __syncthreads per K-step: {wait_all; sync; issue(i+1); compute(i)}.
// EPI: 0 +bias(col)->f32 | 1 +bias(col)->split + per-head rownorm
//      2 exp(v-0.5*norm[row])->split | 4 normalize by in-loop (A.ksum)->split
//      5 exp(v-0.5*norm[col])->split | 6 +bias(row)->split
//      8 split-K partial: raw f32 out + in-loop A-rowsum partial (chunk=blockIdx.x)
struct TGP {
    const u16 *ah, *al, *bh, *bl;
    long long a_ob, a_oh, b_ob, b_oh, o_ob, o_oh;
    int a_st, b_st, o_st, K;
    const float *bias, *norm, *ksum;
    float* o0;
    u16 *o_hi, *o_lo;
    float* nrm_out;
};

template<int NTILE, int EPI>
__global__ void __launch_bounds__(256, 2) tgemm(TGP p)
{
    extern __shared__ char smc[];
    const int tid = threadIdx.x, lane = tid & 31, wid = tid >> 5;
    const int z = blockIdx.z;
    const int m0 = blockIdx.y << 7;
    const int chunk = (EPI == 8) ? blockIdx.x : 0;
    const int n0 = (EPI == 8) ? 0 : blockIdx.x * NTILE;

    constexpr int MT = (NTILE == 128) ? 4 : 2;
    const int wm0 = (NTILE == 128) ? ((wid & 1) << 6) : ((wid & 3) << 5);
    const int wn0 = (NTILE == 128) ? ((wid >> 1) << 5) : ((wid >> 2) << 5);

    constexpr int APL = 128 * RS * 2;       // bytes per A plane (80B rows)
    constexpr int BPL = NTILE * RS * 2;
    constexpr int BLK = 2 * APL + 2 * BPL;  // one stage
    const u32 su = smem_u32(smc);
    float* const ksums = (float*)(smc + 2 * BLK);   // 256 f
    float* const snorm = ksums + 256;               // 256 f

    size_t aoff = (size_t)p.a_ob * (z >> 4) + (size_t)p.a_oh * (z & 15);
    size_t boff = (size_t)p.b_ob * (z >> 4) + (size_t)p.b_oh * (z & 15);
    const size_t ooff = (size_t)p.o_ob * (z >> 4) + (size_t)p.o_oh * (z & 15);
    if (EPI == 8) { aoff += (size_t)chunk * 1024; boff += (size_t)chunk * 1024; }

    if (EPI == 4) ksums[tid] = p.ksum[(size_t)z * Rc + tid];

    const int steps = p.K / BK;

    auto issue = [&](int step) {
        const int k0 = step * BK;
        const u32 sb = su + (step & 1) * BLK;
        const u16* agh = p.ah + aoff + k0;
        const u16* agl = p.al + aoff + k0;
        const u16* bgh = p.bh + boff + k0;
        const u16* bgl = p.bl + boff + k0;
        #pragma unroll
        for (int j = tid; j < 512; j += 256) {
            int row = j >> 2, ch = j & 3;
            size_t gs = (size_t)(m0 + row) * p.a_st + ch * 8;
            u32 so = row * (RS * 2) + ch * 16;
            cpa16(sb + so, agh + gs);
            cpa16(sb + APL + so, agl + gs);
        }
        #pragma unroll
        for (int j = tid; j < NTILE * 4; j += 256) {
            int row = j >> 2, ch = j & 3;
            size_t gs = (size_t)(n0 + row) * p.b_st + ch * 8;
            u32 so = row * (RS * 2) + ch * 16;
            cpa16(sb + 2 * APL + so, bgh + gs);
            cpa16(sb + 2 * APL + BPL + so, bgl + gs);
        }
        asm volatile("cp.async.commit_group;" ::: "memory");
    };

    issue(0);

    float acc[MT][4][4];
    #pragma unroll
    for (int i = 0; i < MT; i++)
        #pragma unroll
        for (int j = 0; j < 4; j++)
            #pragma unroll
            for (int c = 0; c < 4; c++) acc[i][j][c] = 0.0f;
    float nacc = 0.0f;

    const u32 aoff_lane = (lane & 15) * (RS * 2) + (lane >> 4) * 16;
    const u32 boff_lane = ((lane & 7) + ((lane >> 4) << 3)) * (RS * 2) + ((lane >> 3) & 1) * 16;

    for (int i = 0; i < steps; i++) {
        asm volatile("cp.async.wait_group 0;" ::: "memory");
        __syncthreads();
        // buffer (i+1)&1 was last read by compute(i-1); every warp passed the
        // sync above after finishing it, so refilling it now is race-free and
        // the copy overlaps the whole of compute(i).
        if (i + 1 < steps) issue(i + 1);

        const int buf = i & 1;
        const u32 sb = su + buf * BLK;

        if (EPI == 4 || EPI == 8) {
            int row = tid >> 1, half16 = tid & 1;
            const __nv_bfloat162* xh = (const __nv_bfloat162*)(smc + buf * BLK
                                        + row * (RS * 2) + half16 * 32);
            const __nv_bfloat162* xl = (const __nv_bfloat162*)(smc + buf * BLK + APL
                                        + row * (RS * 2) + half16 * 32);
            if (EPI == 4) {
                const float* kv = ksums + i * BK + half16 * 16;
                #pragma unroll
                for (int t = 0; t < 8; t++) {
                    float2 h2 = __bfloat1622float2(xh[t]);
                    float2 l2 = __bfloat1622float2(xl[t]);
                    nacc += (h2.x + l2.x) * kv[2 * t] + (h2.y + l2.y) * kv[2 * t + 1];
                }
            } else {
                #pragma unroll
                for (int t = 0; t < 8; t++) {
                    float2 h2 = __bfloat1622float2(xh[t]);
                    float2 l2 = __bfloat1622float2(xl[t]);
                    nacc += h2.x + l2.x + h2.y + l2.y;
                }
            }
        }

        #pragma unroll
        for (int half = 0; half < 2; half++) {
            const u32 kb = half * 32;
            u32 ahr[MT][4], alr[MT][4];
            #pragma unroll
            for (int im = 0; im < MT; im++) {
                u32 abase = sb + (wm0 + im * 16) * (RS * 2) + kb + aoff_lane;
                ldsm4(ahr[im][0], ahr[im][1], ahr[im][2], ahr[im][3], abase);
                ldsm4(alr[im][0], alr[im][1], alr[im][2], alr[im][3], abase + APL);
            }
            #pragma unroll
            for (int npair = 0; npair < 2; npair++) {
                u32 bbase = sb + 2 * APL + (wn0 + npair * 16) * (RS * 2) + kb + boff_lane;
                u32 bh0, bh1, bh2_, bh3, bl0, bl1, bl2_, bl3;
                ldsm4(bh0, bh1, bh2_, bh3, bbase);
                ldsm4(bl0, bl1, bl2_, bl3, bbase + BPL);
                u32 bhA[2] = { bh0, bh1 }, bhB[2] = { bh2_, bh3 };
                u32 blA[2] = { bl0, bl1 }, blB[2] = { bl2_, bl3 };
                const int iA = npair * 2, iB = npair * 2 + 1;
                #pragma unroll
                for (int im = 0; im < MT; im++) mma_bf16(acc[im][iA], ahr[im], bhA);
                #pragma unroll
                for (int im = 0; im < MT; im++) mma_bf16(acc[im][iB], ahr[im], bhB);
                #pragma unroll
                for (int im = 0; im < MT; im++) mma_bf16(acc[im][iA], alr[im], bhA);
                #pragma unroll
                for (int im = 0; im < MT; im++) mma_bf16(acc[im][iB], alr[im], bhB);
                #pragma unroll
                for (int im = 0; im < MT; im++) mma_bf16(acc[im][iA], ahr[im], blA);
                #pragma unroll
                for (int im = 0; im < MT; im++) mma_bf16(acc[im][iB], ahr[im], blB);
            }
        }
    }
    __syncthreads();

    if (EPI == 4 || EPI == 8) { snorm[tid] = nacc; __syncthreads(); }
    if (EPI == 1) { ksums[tid] = 0.0f; __syncthreads(); }

    // ---------------- epilogue ----------------
    const int lh = wn0 >> 6;
    #pragma unroll
    for (int im = 0; im < MT; im++) {
        const int la = wm0 + im * 16 + (lane >> 2);
        const int lb = la + 8;
        const int rA = m0 + la, rB = m0 + lb;
        float hnA = 0.0f, hnB = 0.0f, invA = 1.0f, invB = 1.0f;
        float bA = 0.0f, bB = 0.0f;
        if (EPI == 2) {
            hnA = 0.5f * p.norm[(size_t)z * Sc + rA];
            hnB = 0.5f * p.norm[(size_t)z * Sc + rB];
        }
        if (EPI == 6) {
            bA = __ldg(p.bias + rA);
            bB = __ldg(p.bias + rB);
        }
        if (EPI == 4) {
            invA = 1.0f / (snorm[2 * la] + snorm[2 * la + 1] + 1e-6f);
            invB = 1.0f / (snorm[2 * lb] + snorm[2 * lb + 1] + 1e-6f);
        }
        float sA = 0.0f, sB = 0.0f;
        #pragma unroll
        for (int in_ = 0; in_ < 4; in_++) {
            const int n = n0 + wn0 + in_ * 8 + ((lane & 3) << 1);
            float v0 = acc[im][in_][0], v1 = acc[im][in_][1];
            float v2 = acc[im][in_][2], v3 = acc[im][in_][3];
            if (EPI == 0 || EPI == 1) {
                float b0 = __ldg(p.bias + n), b1 = __ldg(p.bias + n + 1);
                v0 += b0; v1 += b1; v2 += b0; v3 += b1;
            } else if (EPI == 6) {
                v0 += bA; v1 += bA; v2 += bB; v3 += bB;
            } else if (EPI == 2) {
                v0 = __expf(v0 - hnA); v1 = __expf(v1 - hnA);
                v2 = __expf(v2 - hnB); v3 = __expf(v3 - hnB);
            } else if (EPI == 5) {
                float hn0 = 0.5f * __ldg(p.norm + (size_t)z * Sc + n);
                float hn1 = 0.5f * __ldg(p.norm + (size_t)z * Sc + n + 1);
                v0 = __expf(v0 - hn0); v1 = __expf(v1 - hn1);
                v2 = __expf(v2 - hn0); v3 = __expf(v3 - hn1);
            } else if (EPI == 4) {
                v0 *= invA; v1 *= invA; v2 *= invB; v3 *= invB;
            }
            if (EPI == 1) { sA += v0 * v0 + v1 * v1; sB += v2 * v2 + v3 * v3; }
            if (EPI == 0) {
                *(float2*)(p.o0 + ooff + (size_t)rA * p.o_st + n) = make_float2(v0, v1);
                *(float2*)(p.o0 + ooff + (size_t)rB * p.o_st + n) = make_float2(v2, v3);
            } else if (EPI == 8) {
                float* b8 = p.o0 + (((size_t)z * 4 + chunk) << 14);
                *(float2*)(b8 + (size_t)rA * 64 + n) = make_float2(v0, v1);
                *(float2*)(b8 + (size_t)rB * 64 + n) = make_float2(v2, v3);
            } else {
                u16 h0, l0, h1, l1, h2, l2, h3, l3;
                bsplit(v0, h0, l0); bsplit(v1, h1, l1);
                bsplit(v2, h2, l2); bsplit(v3, h3, l3);
                size_t oA = ooff + (size_t)rA * p.o_st + n;
                size_t oB = ooff + (size_t)rB * p.o_st + n;
                *(u32*)(p.o_hi + oA) = (u32)h0 | ((u32)h1 << 16);
                *(u32*)(p.o_lo + oA) = (u32)l0 | ((u32)l1 << 16);
                *(u32*)(p.o_hi + oB) = (u32)h2 | ((u32)h3 << 16);
                *(u32*)(p.o_lo + oB) = (u32)l2 | ((u32)l3 << 16);
            }
        }
        if (EPI == 1) {
            atomicAdd(&ksums[la * 2 + lh], sA);
            atomicAdd(&ksums[lb * 2 + lh], sB);
        }
    }

    if (EPI == 1) {
        __syncthreads();
        int row = tid >> 1, hloc = tid & 1;
        int rg = m0 + row, b = rg >> 12, s = rg & 4095;
        int head = (n0 >> 6) + hloc;
        p.nrm_out[(size_t)(b * 16 + head) * Sc + s] = ksums[tid];
    }
    if (EPI == 8) {
        if (tid < 128)
            p.nrm_out[(((size_t)z * 4 + chunk) << 8) + m0 + tid] =
                snorm[2 * tid] + snorm[2 * tid + 1];
    }
}

// ---------------- kv final reduce ----------------
__global__ void kvfinal_kernel(const float* __restrict__ kvp, const float* __restrict__ ksp,
                               u16* __restrict__ kvth, u16* __restrict__ kvtl,
                               float* __restrict__ ks)
{
    size_t idx = (size_t)blockIdx.x * 256 + threadIdx.x;
    int r = (int)(idx & 255), d = (int)((idx >> 8) & 63), bh = (int)(idx >> 14);
    float s = 0.0f;
    #pragma unroll
    for (int c = 0; c < 4; c++)
        s += kvp[(((size_t)bh * 4 + c) << 14) + (r << 6) + d];
    u16 hv, lv; bsplit(s, hv, lv);
    size_t o = ((size_t)bh << 14) + (d << 8) + r;
    kvth[o] = hv; kvtl[o] = lv;
    if (idx < (size_t)64 * 256) {
        int bh2 = (int)(idx >> 8), r2 = (int)(idx & 255);
        float t = 0.0f;
        #pragma unroll
        for (int c = 0; c < 4; c++) t += ksp[((size_t)(bh2 * 4 + c) << 8) + r2];
        ks[idx] = t;
    }
}

// ---------------- launch ----------------
extern "C" void kernel_launch(void* const* d_in, const int* in_sizes, int n_in,
                              void* d_out, int out_size)
{
    (void)in_sizes; (void)n_in; (void)out_size;
    const float* x  = (const float*)d_in[0];
    const float* wq = (const float*)d_in[1];
    const float* bq = (const float*)d_in[2];
    const float* wk = (const float*)d_in[3];
    const float* bk = (const float*)d_in[4];
    const float* wv = (const float*)d_in[5];
    const float* bv = (const float*)d_in[6];
    const float* wo = (const float*)d_in[7];
    const float* bo = (const float*)d_in[8];
    const float* rf = (const float*)d_in[9];
    float* out = (float*)d_out;

    u16 *xh, *xl, *wqh, *wql, *wkh, *wkl, *wvh, *wvl, *woh, *wol;
    u16 *rfh, *rfl, *qh, *ql, *kh, *kl, *vth, *vtl, *qph, *qpl;
    u16 *kpth, *kptl, *kvth, *kvtl, *ath, *atl;
    float *nq, *nk, *kvp, *ksp, *ksum;
    cudaGetSymbolAddress((void**)&xh,  g_xh);   cudaGetSymbolAddress((void**)&xl,  g_xl);
    cudaGetSymbolAddress((void**)&wqh, g_wqh);  cudaGetSymbolAddress((void**)&wql, g_wql);
    cudaGetSymbolAddress((void**)&wkh, g_wkh);  cudaGetSymbolAddress((void**)&wkl, g_wkl);
    cudaGetSymbolAddress((void**)&wvh, g_wvh);  cudaGetSymbolAddress((void**)&wvl, g_wvl);
    cudaGetSymbolAddress((void**)&woh, g_woh);  cudaGetSymbolAddress((void**)&wol, g_wol);
    cudaGetSymbolAddress((void**)&rfh, g_rfh);  cudaGetSymbolAddress((void**)&rfl, g_rfl);
    cudaGetSymbolAddress((void**)&qh,  g_qh);   cudaGetSymbolAddress((void**)&ql,  g_ql);
    cudaGetSymbolAddress((void**)&kh,  g_kh);   cudaGetSymbolAddress((void**)&kl,  g_kl);
    cudaGetSymbolAddress((void**)&vth, g_vth);  cudaGetSymbolAddress((void**)&vtl, g_vtl);
    cudaGetSymbolAddress((void**)&nq,  g_nq);   cudaGetSymbolAddress((void**)&nk,  g_nk);
    cudaGetSymbolAddress((void**)&qph, g_qph);  cudaGetSymbolAddress((void**)&qpl, g_qpl);
    cudaGetSymbolAddress((void**)&kpth, g_kpth);cudaGetSymbolAddress((void**)&kptl, g_kptl);
    cudaGetSymbolAddress((void**)&kvp, g_kvp);  cudaGetSymbolAddress((void**)&ksp, g_ksp);
    cudaGetSymbolAddress((void**)&kvth, g_kvth);cudaGetSymbolAddress((void**)&kvtl, g_kvtl);
    cudaGetSymbolAddress((void**)&ksum, g_ksum);
    cudaGetSymbolAddress((void**)&ath, g_ath);  cudaGetSymbolAddress((void**)&atl, g_atl);

    // smem: 2 stages + 2KB epilogue scratch (occupancy 2)
    const int SM128 = 2 * (2 * 128 * RS * 2 + 2 * 128 * RS * 2) + 2048;  // 83968
    const int SM64  = 2 * (2 * 128 * RS * 2 + 2 * 64 * RS * 2) + 2048;   // 63488
    cudaFuncSetAttribute(tgemm<128, 0>, cudaFuncAttributeMaxDynamicSharedMemorySize, SM128);
    cudaFuncSetAttribute(tgemm<128, 1>, cudaFuncAttributeMaxDynamicSharedMemorySize, SM128);
    cudaFuncSetAttribute(tgemm<128, 2>, cudaFuncAttributeMaxDynamicSharedMemorySize, SM128);
    cudaFuncSetAttribute(tgemm<128, 5>, cudaFuncAttributeMaxDynamicSharedMemorySize, SM128);
    cudaFuncSetAttribute(tgemm<128, 6>, cudaFuncAttributeMaxDynamicSharedMemorySize, SM128);
    cudaFuncSetAttribute(tgemm<64, 4>,  cudaFuncAttributeMaxDynamicSharedMemorySize, SM64);
    cudaFuncSetAttribute(tgemm<64, 8>,  cudaFuncAttributeMaxDynamicSharedMemorySize, SM64);

    // splits
    split_kernel<<<2048, 256>>>((const float4*)x, xh, xl, Mtot * Dc / 4);
    split_kernel<<<512, 256>>>((const float4*)wq, wqh, wql, Dc * Dc / 4);
    split_kernel<<<512, 256>>>((const float4*)wk, wkh, wkl, Dc * Dc / 4);
    split_kernel<<<512, 256>>>((const float4*)wv, wvh, wvl, Dc * Dc / 4);
    split_kernel<<<512, 256>>>((const float4*)wo, woh, wol, Dc * Dc / 4);
    rft_kernel<<<(Hc * Rc * HDc + 255) / 256, 256>>>(rf, rfh, rfl);

    // Q/K projections (M=16384, N=1024, K=1024)
    dim3 gproj(Dc / 128, Mtot / 128, 1);
    TGP pj = {};
    pj.ah = xh; pj.al = xl; pj.a_ob = 0; pj.a_oh = 0; pj.a_st = Dc;
    pj.b_ob = 0; pj.b_oh = 0; pj.b_st = Dc; pj.K = Dc;
    pj.o_ob = 0; pj.o_oh = 0; pj.o_st = Dc;

    TGP pq = pj; pq.bh = wqh; pq.bl = wql; pq.bias = bq;
    pq.o_hi = qh; pq.o_lo = ql; pq.nrm_out = nq;
    tgemm<128, 1><<<gproj, 256, SM128>>>(pq);
    TGP pk = pj; pk.bh = wkh; pk.bl = wkl; pk.bias = bk;
    pk.o_hi = kh; pk.o_lo = kl; pk.nrm_out = nk;
    tgemm<128, 1><<<gproj, 256, SM128>>>(pk);

    // V projection TRANSPOSED: C[d, m] = wv * x^T
    dim3 gvt(Mtot / 128, Dc / 128, 1);
    TGP pv = {};
    pv.ah = wvh; pv.al = wvl; pv.a_ob = 0; pv.a_oh = 0; pv.a_st = Dc;
    pv.bh = xh;  pv.bl = xl;  pv.b_ob = 0; pv.b_oh = 0; pv.b_st = Dc;
    pv.K = Dc; pv.bias = bv;
    pv.o_hi = vth; pv.o_lo = vtl; pv.o_ob = 0; pv.o_oh = 0; pv.o_st = Mtot;
    tgemm<128, 6><<<gvt, 256, SM128>>>(pv);

    // feature-Q (per bh: M=4096 s, N=256 r, K=64)
    dim3 gfeat(Rc / 128, Sc / 128, Bc * Hc);
    TGP pfq = {};
    pfq.ah = qh; pfq.al = ql;
    pfq.a_ob = (long long)Sc * Dc; pfq.a_oh = HDc; pfq.a_st = Dc;
    pfq.bh = rfh; pfq.bl = rfl;
    pfq.b_ob = 0; pfq.b_oh = (long long)Rc * HDc; pfq.b_st = HDc;
    pfq.K = HDc; pfq.norm = nq;
    pfq.o_hi = qph; pfq.o_lo = qpl;
    pfq.o_ob = (long long)16 * Sc * Rc; pfq.o_oh = (long long)Sc * Rc; pfq.o_st = Rc;
    tgemm<128, 2><<<gfeat, 256, SM128>>>(pfq);

    // feature-K TRANSPOSED (per bh: M=256 r, N=4096 s, K=64) -> kp^T split
    dim3 gfkt(Sc / 128, Rc / 128, Bc * Hc);
    TGP pfk = {};
    pfk.ah = rfh; pfk.al = rfl;
    pfk.a_ob = 0; pfk.a_oh = (long long)Rc * HDc; pfk.a_st = HDc;
    pfk.bh = kh; pfk.bl = kl;
    pfk.b_ob = (long long)Sc * Dc; pfk.b_oh = HDc; pfk.b_st = Dc;
    pfk.K = HDc; pfk.norm = nk;
    pfk.o_hi = kpth; pfk.o_lo = kptl;
    pfk.o_ob = (long long)16 * Rc * Sc; pfk.o_oh = (long long)Rc * Sc; pfk.o_st = Sc;
    tgemm<128, 5><<<gfkt, 256, SM128>>>(pfk);

    // kv aggregation GEMM (per bh: M=256 r, N=64 d, K=4096 s, split-K x4)
    dim3 gkv(4, Rc / 128, Bc * Hc);
    TGP pkv = {};
    pkv.ah = kpth; pkv.al = kptl;
    pkv.a_ob = (long long)16 * Rc * Sc; pkv.a_oh = (long long)Rc * Sc; pkv.a_st = Sc;
    pkv.bh = vth; pkv.bl = vtl;
    pkv.b_ob = 4096; pkv.b_oh = (long long)64 * Mtot; pkv.b_st = Mtot;
    pkv.K = 1024;
    pkv.o0 = kvp; pkv.nrm_out = ksp;
    tgemm<64, 8><<<gkv, 256, SM64>>>(pkv);

    kvfinal_kernel<<<4096, 256>>>(kvp, ksp, kvth, kvtl, ksum);

    // attention readout (per bh: M=4096 s, N=64 d, K=256 r) + normalize
    dim3 gat(1, Sc / 128, Bc * Hc);
    TGP pa = {};
    pa.ah = qph; pa.al = qpl;
    pa.a_ob = (long long)16 * Sc * Rc; pa.a_oh = (long long)Sc * Rc; pa.a_st = Rc;
    pa.bh = kvth; pa.bl = kvtl;
    pa.b_ob = (long long)16 * HDc * Rc; pa.b_oh = (long long)HDc * Rc; pa.b_st = Rc;
    pa.K = Rc; pa.ksum = ksum;
    pa.o_hi = ath; pa.o_lo = atl;
    pa.o_ob = (long long)Sc * Dc; pa.o_oh = HDc; pa.o_st = Dc;
    tgemm<64, 4><<<gat, 256, SM64>>>(pa);

    // output projection
    TGP po = pj; po.ah = ath; po.al = atl; po.bh = woh; po.bl = wol;
    po.bias = bo; po.o0 = out;
    tgemm<128, 0><<<gproj, 256, SM128>>>(po);
}

// round 12
// speedup vs baseline: 1.3111x; 1.1097x over previous
#include <cuda_runtime.h>
#include <cuda_bf16.h>
#include <cuda_fp16.h>
#include <cstdint>
#include <math.h>

#define Bc 4
#define Sc 4096
#define Dc 1024
#define Hc 16
#define Rc 256
#define HDc 64
#define Mtot (Bc * Sc)
#define BK 32
#define RS 40      // smem row stride in u16 (32 data + 8 pad = 80B)

typedef unsigned short u16;
typedef uint32_t u32;

// ---------------- scratch (device globals) ----------------
// fp16 split planes (inputs / linear intermediates)
__device__ u16 g_xh[(size_t)Mtot * Dc],  g_xl[(size_t)Mtot * Dc];
__device__ u16 g_wqh[Dc * Dc], g_wql[Dc * Dc];
__device__ u16 g_wkh[Dc * Dc], g_wkl[Dc * Dc];
__device__ u16 g_wvh[Dc * Dc], g_wvl[Dc * Dc];
__device__ u16 g_woh[Dc * Dc], g_wol[Dc * Dc];
__device__ u16 g_rfh[(size_t)Hc * Rc * HDc], g_rfl[(size_t)Hc * Rc * HDc];
__device__ u16 g_qh[(size_t)Mtot * Dc],  g_ql[(size_t)Mtot * Dc];
__device__ u16 g_kh[(size_t)Mtot * Dc],  g_kl[(size_t)Mtot * Dc];
__device__ u16 g_ath[(size_t)Mtot * Dc], g_atl[(size_t)Mtot * Dc];
// bf16 split planes (exp outputs can exceed fp16 range; kv path consumes them)
__device__ u16 g_vth[(size_t)Mtot * Dc], g_vtl[(size_t)Mtot * Dc];   // V^T [d][m]
__device__ u16 g_qph[(size_t)Bc * Hc * Sc * Rc], g_qpl[(size_t)Bc * Hc * Sc * Rc];
__device__ u16 g_kpth[(size_t)Bc * Hc * Rc * Sc], g_kptl[(size_t)Bc * Hc * Rc * Sc];
__device__ u16 g_kvth[(size_t)Bc * Hc * HDc * Rc], g_kvtl[(size_t)Bc * Hc * HDc * Rc];
// fp32
__device__ float g_nq[(size_t)Bc * Hc * Sc], g_nk[(size_t)Bc * Hc * Sc];
__device__ float g_kvp[(size_t)Bc * Hc * 4 * Rc * HDc];
__device__ float g_ksp[(size_t)Bc * Hc * 4 * Rc];
__device__ float g_ksum[(size_t)Bc * Hc * Rc];

// ---------------- helpers ----------------
__device__ __forceinline__ u32 smem_u32(const void* p) {
    u32 a;
    asm("{ .reg .u64 t; cvta.to.shared.u64 t, %1; cvt.u32.u64 %0, t; }" : "=r"(a) : "l"(p));
    return a;
}
__device__ __forceinline__ void bsplit(float a, u16& h, u16& l) {
    __nv_bfloat16 hb = __float2bfloat16_rn(a);
    float lf = a - __bfloat162float(hb);
    __nv_bfloat16 lb = __float2bfloat16_rn(lf);
    h = __bfloat16_as_ushort(hb);
    l = __bfloat16_as_ushort(lb);
}
__device__ __forceinline__ void hsplit(float a, u16& h, u16& l) {
    __half hb = __float2half_rn(a);
    float lf = a - __half2float(hb);
    __half lb = __float2half_rn(lf);
    h = __half_as_ushort(hb);
    l = __half_as_ushort(lb);
}
__device__ __forceinline__ void cpa16(u32 dst, const void* src) {
    asm volatile("cp.async.cg.shared.global [%0], [%1], 16;"
                 :: "r"(dst), "l"(__cvta_generic_to_global(src)) : "memory");
}
__device__ __forceinline__ void mma_bf16(float* c, const u32* A, const u32* B) {
    asm volatile(
        "mma.sync.aligned.m16n8k16.row.col.f32.bf16.bf16.f32 "
        "{%0,%1,%2,%3}, {%4,%5,%6,%7}, {%8,%9}, {%0,%1,%2,%3};"
        : "+f"(c[0]), "+f"(c[1]), "+f"(c[2]), "+f"(c[3])
        : "r"(A[0]), "r"(A[1]), "r"(A[2]), "r"(A[3]), "r"(B[0]), "r"(B[1]));
}
__device__ __forceinline__ void mma_f16(float* c, const u32* A, const u32* B) {
    asm volatile(
        "mma.sync.aligned.m16n8k16.row.col.f32.f16.f16.f32 "
        "{%0,%1,%2,%3}, {%4,%5,%6,%7}, {%8,%9}, {%0,%1,%2,%3};"
        : "+f"(c[0]), "+f"(c[1]), "+f"(c[2]), "+f"(c[3])
        : "r"(A[0]), "r"(A[1]), "r"(A[2]), "r"(A[3]), "r"(B[0]), "r"(B[1]));
}
template<int FT>
__device__ __forceinline__ void mma16(float* c, const u32* A, const u32* B) {
    if (FT == 0) mma_bf16(c, A, B);
    else         mma_f16(c, A, B);
}
__device__ __forceinline__ void ldsm4(u32& r0, u32& r1, u32& r2, u32& r3, u32 addr) {
    asm volatile("ldmatrix.sync.aligned.m8n8.x4.shared.b16 {%0,%1,%2,%3}, [%4];"
                 : "=r"(r0), "=r"(r1), "=r"(r2), "=r"(r3) : "r"(addr));
}

// ---------------- split / transpose prep (fp16 planes) ----------------
__global__ void split_kernel(const float4* __restrict__ src, u16* __restrict__ hi,
                             u16* __restrict__ lo, int n4)
{
    for (int i = blockIdx.x * blockDim.x + threadIdx.x; i < n4; i += gridDim.x * blockDim.x) {
        float4 a = src[i];
        ushort4 hv, lv;
        hsplit(a.x, hv.x, lv.x); hsplit(a.y, hv.y, lv.y);
        hsplit(a.z, hv.z, lv.z); hsplit(a.w, hv.w, lv.w);
        *(ushort4*)(hi + (size_t)i * 4) = hv;
        *(ushort4*)(lo + (size_t)i * 4) = lv;
    }
}
__global__ void rft_kernel(const float* __restrict__ rf, u16* __restrict__ oh,
                           u16* __restrict__ ol)
{
    int idx = blockIdx.x * blockDim.x + threadIdx.x;
    if (idx >= Hc * Rc * HDc) return;
    int d = idx & 63, r = (idx >> 6) & 255, h = idx >> 14;
    float a = rf[((size_t)(h * HDc + d)) * Rc + r];
    u16 hv, lv; hsplit(a, hv, lv);
    oh[idx] = hv; ol[idx] = lv;
}

// ---------------- split-precision tensor GEMM engine ----------------
// C[128 x NTILE] per CTA; C = A * B^T (fp32 accum).
// FT: 0=bf16 operands, 1=fp16 operands.  XN: 3 = hh+lh+hl, 2 = hh+lh.
// EPI: 0 +bias(col)->f32 | 1 +bias(col)->fp16 split + per-head rownorm
//      2 exp(v-0.5*norm[row])->bf16 split | 4 normalize by in-loop (A.ksum)->fp16 split
//      5 exp(v-0.5*norm[col])->bf16 split | 6 +bias(row)->bf16 split
//      8 split-K partial: raw f32 out + in-loop A-rowsum partial (chunk=blockIdx.x)
struct TGP {
    const u16 *ah, *al, *bh, *bl;
    long long a_ob, a_oh, b_ob, b_oh, o_ob, o_oh;
    int a_st, b_st, o_st, K;
    const float *bias, *norm, *ksum;
    float* o0;
    u16 *o_hi, *o_lo;
    float* nrm_out;
};

template<int NTILE, int EPI, int FT, int XN>
__global__ void __launch_bounds__(256, 2) tgemm(TGP p)
{
    extern __shared__ char smc[];
    const int tid = threadIdx.x, lane = tid & 31, wid = tid >> 5;
    const int z = blockIdx.z;
    const int m0 = blockIdx.y << 7;
    const int chunk = (EPI == 8) ? blockIdx.x : 0;
    const int n0 = (EPI == 8) ? 0 : blockIdx.x * NTILE;

    constexpr int MT = (NTILE == 128) ? 4 : 2;
    constexpr bool OUT_BF = (EPI == 2 || EPI == 5 || EPI == 6);
    const int wm0 = (NTILE == 128) ? ((wid & 1) << 6) : ((wid & 3) << 5);
    const int wn0 = (NTILE == 128) ? ((wid >> 1) << 5) : ((wid >> 2) << 5);

    constexpr int APL = 128 * RS * 2;       // bytes per A plane (80B rows)
    constexpr int BPL = NTILE * RS * 2;
    constexpr int BLK = 2 * APL + 2 * BPL;  // one stage
    const u32 su = smem_u32(smc);
    float* const ksums = (float*)(smc + 2 * BLK);   // 256 f
    float* const snorm = ksums + 256;               // 256 f

    size_t aoff = (size_t)p.a_ob * (z >> 4) + (size_t)p.a_oh * (z & 15);
    size_t boff = (size_t)p.b_ob * (z >> 4) + (size_t)p.b_oh * (z & 15);
    const size_t ooff = (size_t)p.o_ob * (z >> 4) + (size_t)p.o_oh * (z & 15);
    if (EPI == 8) { aoff += (size_t)chunk * 1024; boff += (size_t)chunk * 1024; }

    if (EPI == 4) ksums[tid] = p.ksum[(size_t)z * Rc + tid];

    const int steps = p.K / BK;

    auto issue = [&](int step) {
        const int k0 = step * BK;
        const u32 sb = su + (step & 1) * BLK;
        const u16* agh = p.ah + aoff + k0;
        const u16* agl = p.al + aoff + k0;
        const u16* bgh = p.bh + boff + k0;
        const u16* bgl = p.bl + boff + k0;
        #pragma unroll
        for (int j = tid; j < 512; j += 256) {
            int row = j >> 2, ch = j & 3;
            size_t gs = (size_t)(m0 + row) * p.a_st + ch * 8;
            u32 so = row * (RS * 2) + ch * 16;
            cpa16(sb + so, agh + gs);
            cpa16(sb + APL + so, agl + gs);
        }
        #pragma unroll
        for (int j = tid; j < NTILE * 4; j += 256) {
            int row = j >> 2, ch = j & 3;
            size_t gs = (size_t)(n0 + row) * p.b_st + ch * 8;
            u32 so = row * (RS * 2) + ch * 16;
            cpa16(sb + 2 * APL + so, bgh + gs);
            if (XN == 3) cpa16(sb + 2 * APL + BPL + so, bgl + gs);
        }
        asm volatile("cp.async.commit_group;" ::: "memory");
    };

    issue(0);

    float acc[MT][4][4];
    #pragma unroll
    for (int i = 0; i < MT; i++)
        #pragma unroll
        for (int j = 0; j < 4; j++)
            #pragma unroll
            for (int c = 0; c < 4; c++) acc[i][j][c] = 0.0f;
    float nacc = 0.0f;

    const u32 aoff_lane = (lane & 15) * (RS * 2) + (lane >> 4) * 16;
    const u32 boff_lane = ((lane & 7) + ((lane >> 4) << 3)) * (RS * 2) + ((lane >> 3) & 1) * 16;

    for (int i = 0; i < steps; i++) {
        asm volatile("cp.async.wait_group 0;" ::: "memory");
        __syncthreads();
        if (i + 1 < steps) issue(i + 1);

        const int buf = i & 1;
        const u32 sb = su + buf * BLK;

        if (EPI == 4 || EPI == 8) {
            // A operand is bf16 in these EPIs (FT==0 paths)
            int row = tid >> 1, half16 = tid & 1;
            const __nv_bfloat162* xh = (const __nv_bfloat162*)(smc + buf * BLK
                                        + row * (RS * 2) + half16 * 32);
            const __nv_bfloat162* xl = (const __nv_bfloat162*)(smc + buf * BLK + APL
                                        + row * (RS * 2) + half16 * 32);
            if (EPI == 4) {
                const float* kv = ksums + i * BK + half16 * 16;
                #pragma unroll
                for (int t = 0; t < 8; t++) {
                    float2 h2 = __bfloat1622float2(xh[t]);
                    float2 l2 = __bfloat1622float2(xl[t]);
                    nacc += (h2.x + l2.x) * kv[2 * t] + (h2.y + l2.y) * kv[2 * t + 1];
                }
            } else {
                #pragma unroll
                for (int t = 0; t < 8; t++) {
                    float2 h2 = __bfloat1622float2(xh[t]);
                    float2 l2 = __bfloat1622float2(xl[t]);
                    nacc += h2.x + l2.x + h2.y + l2.y;
                }
            }
        }

        #pragma unroll
        for (int half = 0; half < 2; half++) {
            const u32 kb = half * 32;
            u32 ahr[MT][4], alr[MT][4];
            #pragma unroll
            for (int im = 0; im < MT; im++) {
                u32 abase = sb + (wm0 + im * 16) * (RS * 2) + kb + aoff_lane;
                ldsm4(ahr[im][0], ahr[im][1], ahr[im][2], ahr[im][3], abase);
                ldsm4(alr[im][0], alr[im][1], alr[im][2], alr[im][3], abase + APL);
            }
            #pragma unroll
            for (int npair = 0; npair < 2; npair++) {
                u32 bbase = sb + 2 * APL + (wn0 + npair * 16) * (RS * 2) + kb + boff_lane;
                u32 bh0, bh1, bh2_, bh3;
                ldsm4(bh0, bh1, bh2_, bh3, bbase);
                u32 bhA[2] = { bh0, bh1 }, bhB[2] = { bh2_, bh3 };
                const int iA = npair * 2, iB = npair * 2 + 1;
                #pragma unroll
                for (int im = 0; im < MT; im++) mma16<FT>(acc[im][iA], ahr[im], bhA);
                #pragma unroll
                for (int im = 0; im < MT; im++) mma16<FT>(acc[im][iB], ahr[im], bhB);
                #pragma unroll
                for (int im = 0; im < MT; im++) mma16<FT>(acc[im][iA], alr[im], bhA);
                #pragma unroll
                for (int im = 0; im < MT; im++) mma16<FT>(acc[im][iB], alr[im], bhB);
                if (XN == 3) {
                    u32 bl0, bl1, bl2_, bl3;
                    ldsm4(bl0, bl1, bl2_, bl3, bbase + BPL);
                    u32 blA[2] = { bl0, bl1 }, blB[2] = { bl2_, bl3 };
                    #pragma unroll
                    for (int im = 0; im < MT; im++) mma16<FT>(acc[im][iA], ahr[im], blA);
                    #pragma unroll
                    for (int im = 0; im < MT; im++) mma16<FT>(acc[im][iB], ahr[im], blB);
                }
            }
        }
    }
    __syncthreads();

    if (EPI == 4 || EPI == 8) { snorm[tid] = nacc; __syncthreads(); }
    if (EPI == 1) { ksums[tid] = 0.0f; __syncthreads(); }

    // ---------------- epilogue ----------------
    const int lh = wn0 >> 6;
    #pragma unroll
    for (int im = 0; im < MT; im++) {
        const int la = wm0 + im * 16 + (lane >> 2);
        const int lb = la + 8;
        const int rA = m0 + la, rB = m0 + lb;
        float hnA = 0.0f, hnB = 0.0f, invA = 1.0f, invB = 1.0f;
        float bA = 0.0f, bB = 0.0f;
        if (EPI == 2) {
            hnA = 0.5f * p.norm[(size_t)z * Sc + rA];
            hnB = 0.5f * p.norm[(size_t)z * Sc + rB];
        }
        if (EPI == 6) {
            bA = __ldg(p.bias + rA);
            bB = __ldg(p.bias + rB);
        }
        if (EPI == 4) {
            invA = 1.0f / (snorm[2 * la] + snorm[2 * la + 1] + 1e-6f);
            invB = 1.0f / (snorm[2 * lb] + snorm[2 * lb + 1] + 1e-6f);
        }
        float sA = 0.0f, sB = 0.0f;
        #pragma unroll
        for (int in_ = 0; in_ < 4; in_++) {
            const int n = n0 + wn0 + in_ * 8 + ((lane & 3) << 1);
            float v0 = acc[im][in_][0], v1 = acc[im][in_][1];
            float v2 = acc[im][in_][2], v3 = acc[im][in_][3];
            if (EPI == 0 || EPI == 1) {
                float b0 = __ldg(p.bias + n), b1 = __ldg(p.bias + n + 1);
                v0 += b0; v1 += b1; v2 += b0; v3 += b1;
            } else if (EPI == 6) {
                v0 += bA; v1 += bA; v2 += bB; v3 += bB;
            } else if (EPI == 2) {
                v0 = __expf(v0 - hnA); v1 = __expf(v1 - hnA);
                v2 = __expf(v2 - hnB); v3 = __expf(v3 - hnB);
            } else if (EPI == 5) {
                float hn0 = 0.5f * __ldg(p.norm + (size_t)z * Sc + n);
                float hn1 = 0.5f * __ldg(p.norm + (size_t)z * Sc + n + 1);
                v0 = __expf(v0 - hn0); v1 = __expf(v1 - hn1);
                v2 = __expf(v2 - hn0); v3 = __expf(v3 - hn1);
            } else if (EPI == 4) {
                v0 *= invA; v1 *= invA; v2 *= invB; v3 *= invB;
            }
            if (EPI == 1) { sA += v0 * v0 + v1 * v1; sB += v2 * v2 + v3 * v3; }
            if (EPI == 0) {
                *(float2*)(p.o0 + ooff + (size_t)rA * p.o_st + n) = make_float2(v0, v1);
                *(float2*)(p.o0 + ooff + (size_t)rB * p.o_st + n) = make_float2(v2, v3);
            } else if (EPI == 8) {
                float* b8 = p.o0 + (((size_t)z * 4 + chunk) << 14);
                *(float2*)(b8 + (size_t)rA * 64 + n) = make_float2(v0, v1);
                *(float2*)(b8 + (size_t)rB * 64 + n) = make_float2(v2, v3);
            } else {
                u16 h0, l0, h1, l1, h2, l2, h3, l3;
                if (OUT_BF) {
                    bsplit(v0, h0, l0); bsplit(v1, h1, l1);
                    bsplit(v2, h2, l2); bsplit(v3, h3, l3);
                } else {
                    hsplit(v0, h0, l0); hsplit(v1, h1, l1);
                    hsplit(v2, h2, l2); hsplit(v3, h3, l3);
                }
                size_t oA = ooff + (size_t)rA * p.o_st + n;
                size_t oB = ooff + (size_t)rB * p.o_st + n;
                *(u32*)(p.o_hi + oA) = (u32)h0 | ((u32)h1 << 16);
                *(u32*)(p.o_lo + oA) = (u32)l0 | ((u32)l1 << 16);
                *(u32*)(p.o_hi + oB) = (u32)h2 | ((u32)h3 << 16);
                *(u32*)(p.o_lo + oB) = (u32)l2 | ((u32)l3 << 16);
            }
        }
        if (EPI == 1) {
            atomicAdd(&ksums[la * 2 + lh], sA);
            atomicAdd(&ksums[lb * 2 + lh], sB);
        }
    }

    if (EPI == 1) {
        __syncthreads();
        int row = tid >> 1, hloc = tid & 1;
        int rg = m0 + row, b = rg >> 12, s = rg & 4095;
        int head = (n0 >> 6) + hloc;
        p.nrm_out[(size_t)(b * 16 + head) * Sc + s] = ksums[tid];
    }
    if (EPI == 8) {
        if (tid < 128)
            p.nrm_out[(((size_t)z * 4 + chunk) << 8) + m0 + tid] =
                snorm[2 * tid] + snorm[2 * tid + 1];
    }
}

// ---------------- kv final reduce (bf16 split out) ----------------
__global__ void kvfinal_kernel(const float* __restrict__ kvp, const float* __restrict__ ksp,
                               u16* __restrict__ kvth, u16* __restrict__ kvtl,
                               float* __restrict__ ks)
{
    size_t idx = (size_t)blockIdx.x * 256 + threadIdx.x;
    int r = (int)(idx & 255), d = (int)((idx >> 8) & 63), bh = (int)(idx >> 14);
    float s = 0.0f;
    #pragma unroll
    for (int c = 0; c < 4; c++)
        s += kvp[(((size_t)bh * 4 + c) << 14) + (r << 6) + d];
    u16 hv, lv; bsplit(s, hv, lv);
    size_t o = ((size_t)bh << 14) + (d << 8) + r;
    kvth[o] = hv; kvtl[o] = lv;
    if (idx < (size_t)64 * 256) {
        int bh2 = (int)(idx >> 8), r2 = (int)(idx & 255);
        float t = 0.0f;
        #pragma unroll
        for (int c = 0; c < 4; c++) t += ksp[((size_t)(bh2 * 4 + c) << 8) + r2];
        ks[idx] = t;
    }
}

// ---------------- launch ----------------
extern "C" void kernel_launch(void* const* d_in, const int* in_sizes, int n_in,
                              void* d_out, int out_size)
{
    (void)in_sizes; (void)n_in; (void)out_size;
    const float* x  = (const float*)d_in[0];
    const float* wq = (const float*)d_in[1];
    const float* bq = (const float*)d_in[2];
    const float* wk = (const float*)d_in[3];
    const float* bk = (const float*)d_in[4];
    const float* wv = (const float*)d_in[5];
    const float* bv = (const float*)d_in[6];
    const float* wo = (const float*)d_in[7];
    const float* bo = (const float*)d_in[8];
    const float* rf = (const float*)d_in[9];
    float* out = (float*)d_out;

    u16 *xh, *xl, *wqh, *wql, *wkh, *wkl, *wvh, *wvl, *woh, *wol;
    u16 *rfh, *rfl, *qh, *ql, *kh, *kl, *vth, *vtl, *qph, *qpl;
    u16 *kpth, *kptl, *kvth, *kvtl, *ath, *atl;
    float *nq, *nk, *kvp, *ksp, *ksum;
    cudaGetSymbolAddress((void**)&xh,  g_xh);   cudaGetSymbolAddress((void**)&xl,  g_xl);
    cudaGetSymbolAddress((void**)&wqh, g_wqh);  cudaGetSymbolAddress((void**)&wql, g_wql);
    cudaGetSymbolAddress((void**)&wkh, g_wkh);  cudaGetSymbolAddress((void**)&wkl, g_wkl);
    cudaGetSymbolAddress((void**)&wvh, g_wvh);  cudaGetSymbolAddress((void**)&wvl, g_wvl);
    cudaGetSymbolAddress((void**)&woh, g_woh);  cudaGetSymbolAddress((void**)&wol, g_wol);
    cudaGetSymbolAddress((void**)&rfh, g_rfh);  cudaGetSymbolAddress((void**)&rfl, g_rfl);
    cudaGetSymbolAddress((void**)&qh,  g_qh);   cudaGetSymbolAddress((void**)&ql,  g_ql);
    cudaGetSymbolAddress((void**)&kh,  g_kh);   cudaGetSymbolAddress((void**)&kl,  g_kl);
    cudaGetSymbolAddress((void**)&vth, g_vth);  cudaGetSymbolAddress((void**)&vtl, g_vtl);
    cudaGetSymbolAddress((void**)&nq,  g_nq);   cudaGetSymbolAddress((void**)&nk,  g_nk);
    cudaGetSymbolAddress((void**)&qph, g_qph);  cudaGetSymbolAddress((void**)&qpl, g_qpl);
    cudaGetSymbolAddress((void**)&kpth, g_kpth);cudaGetSymbolAddress((void**)&kptl, g_kptl);
    cudaGetSymbolAddress((void**)&kvp, g_kvp);  cudaGetSymbolAddress((void**)&ksp, g_ksp);
    cudaGetSymbolAddress((void**)&kvth, g_kvth);cudaGetSymbolAddress((void**)&kvtl, g_kvtl);
    cudaGetSymbolAddress((void**)&ksum, g_ksum);
    cudaGetSymbolAddress((void**)&ath, g_ath);  cudaGetSymbolAddress((void**)&atl, g_atl);

    // smem: 2 stages + 2KB epilogue scratch (occupancy 2)
    const int SM128 = 2 * (2 * 128 * RS * 2 + 2 * 128 * RS * 2) + 2048;  // 83968
    const int SM64  = 2 * (2 * 128 * RS * 2 + 2 * 64 * RS * 2) + 2048;   // 63488
    cudaFuncSetAttribute(tgemm<128, 0, 1, 2>, cudaFuncAttributeMaxDynamicSharedMemorySize, SM128);
    cudaFuncSetAttribute(tgemm<128, 1, 1, 3>, cudaFuncAttributeMaxDynamicSharedMemorySize, SM128);
    cudaFuncSetAttribute(tgemm<128, 2, 1, 3>, cudaFuncAttributeMaxDynamicSharedMemorySize, SM128);
    cudaFuncSetAttribute(tgemm<128, 5, 1, 3>, cudaFuncAttributeMaxDynamicSharedMemorySize, SM128);
    cudaFuncSetAttribute(tgemm<128, 6, 1, 2>, cudaFuncAttributeMaxDynamicSharedMemorySize, SM128);
    cudaFuncSetAttribute(tgemm<64, 4, 0, 3>,  cudaFuncAttributeMaxDynamicSharedMemorySize, SM64);
    cudaFuncSetAttribute(tgemm<64, 8, 0, 3>,  cudaFuncAttributeMaxDynamicSharedMemorySize, SM64);

    // splits (fp16 planes)
    split_kernel<<<2048, 256>>>((const float4*)x, xh, xl, Mtot * Dc / 4);
    split_kernel<<<512, 256>>>((const float4*)wq, wqh, wql, Dc * Dc / 4);
    split_kernel<<<512, 256>>>((const float4*)wk, wkh, wkl, Dc * Dc / 4);
    split_kernel<<<512, 256>>>((const float4*)wv, wvh, wvl, Dc * Dc / 4);
    split_kernel<<<512, 256>>>((const float4*)wo, woh, wol, Dc * Dc / 4);
    rft_kernel<<<(Hc * Rc * HDc + 255) / 256, 256>>>(rf, rfh, rfl);

    // Q/K projections (M=16384, N=1024, K=1024), fp16x3 -> fp16 split + rownorm
    dim3 gproj(Dc / 128, Mtot / 128, 1);
    TGP pj = {};
    pj.ah = xh; pj.al = xl; pj.a_ob = 0; pj.a_oh = 0; pj.a_st = Dc;
    pj.b_ob = 0; pj.b_oh = 0; pj.b_st = Dc; pj.K = Dc;
    pj.o_ob = 0; pj.o_oh = 0; pj.o_st = Dc;

    TGP pq = pj; pq.bh = wqh; pq.bl = wql; pq.bias = bq;
    pq.o_hi = qh; pq.o_lo = ql; pq.nrm_out = nq;
    tgemm<128, 1, 1, 3><<<gproj, 256, SM128>>>(pq);
    TGP pk = pj; pk.bh = wkh; pk.bl = wkl; pk.bias = bk;
    pk.o_hi = kh; pk.o_lo = kl; pk.nrm_out = nk;
    tgemm<128, 1, 1, 3><<<gproj, 256, SM128>>>(pk);

    // V projection TRANSPOSED: C[d, m] = wv * x^T, fp16x2 -> bf16 split
    dim3 gvt(Mtot / 128, Dc / 128, 1);
    TGP pv = {};
    pv.ah = wvh; pv.al = wvl; pv.a_ob = 0; pv.a_oh = 0; pv.a_st = Dc;
    pv.bh = xh;  pv.bl = xl;  pv.b_ob = 0; pv.b_oh = 0; pv.b_st = Dc;
    pv.K = Dc; pv.bias = bv;
    pv.o_hi = vth; pv.o_lo = vtl; pv.o_ob = 0; pv.o_oh = 0; pv.o_st = Mtot;
    tgemm<128, 6, 1, 2><<<gvt, 256, SM128>>>(pv);

    // feature-Q (per bh: M=4096 s, N=256 r, K=64), fp16x3 -> bf16 split
    dim3 gfeat(Rc / 128, Sc / 128, Bc * Hc);
    TGP pfq = {};
    pfq.ah = qh; pfq.al = ql;
    pfq.a_ob = (long long)Sc * Dc; pfq.a_oh = HDc; pfq.a_st = Dc;
    pfq.bh = rfh; pfq.bl = rfl;
    pfq.b_ob = 0; pfq.b_oh = (long long)Rc * HDc; pfq.b_st = HDc;
    pfq.K = HDc; pfq.norm = nq;
    pfq.o_hi = qph; pfq.o_lo = qpl;
    pfq.o_ob = (long long)16 * Sc * Rc; pfq.o_oh = (long long)Sc * Rc; pfq.o_st = Rc;
    tgemm<128, 2, 1, 3><<<gfeat, 256, SM128>>>(pfq);

    // feature-K TRANSPOSED (per bh: M=256 r, N=4096 s, K=64), fp16x3 -> bf16 split
    dim3 gfkt(Sc / 128, Rc / 128, Bc * Hc);
    TGP pfk = {};
    pfk.ah = rfh; pfk.al = rfl;
    pfk.a_ob = 0; pfk.a_oh = (long long)Rc * HDc; pfk.a_st = HDc;
    pfk.bh = kh; pfk.bl = kl;
    pfk.b_ob = (long long)Sc * Dc; pfk.b_oh = HDc; pfk.b_st = Dc;
    pfk.K = HDc; pfk.norm = nk;
    pfk.o_hi = kpth; pfk.o_lo = kptl;
    pfk.o_ob = (long long)16 * Rc * Sc; pfk.o_oh = (long long)Rc * Sc; pfk.o_st = Sc;
    tgemm<128, 5, 1, 3><<<gfkt, 256, SM128>>>(pfk);

    // kv aggregation GEMM (per bh: M=256 r, N=64 d, K=4096 s, split-K x4), bf16x3
    dim3 gkv(4, Rc / 128, Bc * Hc);
    TGP pkv = {};
    pkv.ah = kpth; pkv.al = kptl;
    pkv.a_ob = (long long)16 * Rc * Sc; pkv.a_oh = (long long)Rc * Sc; pkv.a_st = Sc;
    pkv.bh = vth; pkv.bl = vtl;
    pkv.b_ob = 4096; pkv.b_oh = (long long)64 * Mtot; pkv.b_st = Mtot;
    pkv.K = 1024;
    pkv.o0 = kvp; pkv.nrm_out = ksp;
    tgemm<64, 8, 0, 3><<<gkv, 256, SM64>>>(pkv);

    kvfinal_kernel<<<4096, 256>>>(kvp, ksp, kvth, kvtl, ksum);

    // attention readout (per bh: M=4096 s, N=64 d, K=256 r), bf16x3 -> fp16 split
    dim3 gat(1, Sc / 128, Bc * Hc);
    TGP pa = {};
    pa.ah = qph; pa.al = qpl;
    pa.a_ob = (long long)16 * Sc * Rc; pa.a_oh = (long long)Sc * Rc; pa.a_st = Rc;
    pa.bh = kvth; pa.bl = kvtl;
    pa.b_ob = (long long)16 * HDc * Rc; pa.b_oh = (long long)HDc * Rc; pa.b_st = Rc;
    pa.K = Rc; pa.ksum = ksum;
    pa.o_hi = ath; pa.o_lo = atl;
    pa.o_ob = (long long)Sc * Dc; pa.o_oh = HDc; pa.o_st = Dc;
    tgemm<64, 4, 0, 3><<<gat, 256, SM64>>>(pa);

    // output projection, fp16x2 -> f32
    TGP po = pj; po.ah = ath; po.al = atl; po.bh = woh; po.bl = wol;
    po.bias = bo; po.o0 = out;
    tgemm<128, 0, 1, 2><<<gproj, 256, SM128>>>(po);
}

// round 14
// speedup vs baseline: 1.3196x; 1.0064x over previous
#include <cuda_runtime.h>
#include <cuda_bf16.h>
#include <cuda_fp16.h>
#include <cstdint>
#include <math.h>

#define Bc 4
#define Sc 4096
#define Dc 1024
#define Hc 16
#define Rc 256
#define HDc 64
#define Mtot (Bc * Sc)
#define BK 32
#define RS 40      // smem row stride in u16 (32 data + 8 pad = 80B)

typedef unsigned short u16;
typedef uint32_t u32;

// ---------------- scratch (device globals) ----------------
__device__ u16 g_xh[(size_t)Mtot * Dc],  g_xl[(size_t)Mtot * Dc];
__device__ u16 g_wqh[Dc * Dc], g_wql[Dc * Dc];
__device__ u16 g_wkh[Dc * Dc], g_wkl[Dc * Dc];
__device__ u16 g_wvh[Dc * Dc], g_wvl[Dc * Dc];
__device__ u16 g_woh[Dc * Dc], g_wol[Dc * Dc];
__device__ u16 g_rfh[(size_t)Hc * Rc * HDc], g_rfl[(size_t)Hc * Rc * HDc];
__device__ u16 g_qh[(size_t)Mtot * Dc],  g_ql[(size_t)Mtot * Dc];
__device__ u16 g_kh[(size_t)Mtot * Dc],  g_kl[(size_t)Mtot * Dc];
__device__ u16 g_ath[(size_t)Mtot * Dc], g_atl[(size_t)Mtot * Dc];
// bf16 split planes (exp outputs exceed fp16 range)
__device__ u16 g_vth[(size_t)Mtot * Dc], g_vtl[(size_t)Mtot * Dc];   // V^T [d][m]
__device__ u16 g_qph[(size_t)Bc * Hc * Sc * Rc], g_qpl[(size_t)Bc * Hc * Sc * Rc];
__device__ u16 g_kpth[(size_t)Bc * Hc * Rc * Sc], g_kptl[(size_t)Bc * Hc * Rc * Sc];
__device__ u16 g_kvth[(size_t)Bc * Hc * HDc * Rc], g_kvtl[(size_t)Bc * Hc * HDc * Rc];
// fp32
__device__ float g_nq[(size_t)Bc * Hc * Sc], g_nk[(size_t)Bc * Hc * Sc];
__device__ float g_kvp[(size_t)Bc * Hc * 4 * Rc * HDc];
__device__ float g_ksp[(size_t)Bc * Hc * 4 * Rc];
__device__ float g_ksum[(size_t)Bc * Hc * Rc];

// ---------------- helpers ----------------
__device__ __forceinline__ u32 smem_u32(const void* p) {
    u32 a;
    asm("{ .reg .u64 t; cvta.to.shared.u64 t, %1; cvt.u32.u64 %0, t; }" : "=r"(a) : "l"(p));
    return a;
}
__device__ __forceinline__ void bsplit(float a, u16& h, u16& l) {
    __nv_bfloat16 hb = __float2bfloat16_rn(a);
    float lf = a - __bfloat162float(hb);
    __nv_bfloat16 lb = __float2bfloat16_rn(lf);
    h = __bfloat16_as_ushort(hb);
    l = __bfloat16_as_ushort(lb);
}
__device__ __forceinline__ void hsplit(float a, u16& h, u16& l) {
    __half hb = __float2half_rn(a);
    float lf = a - __half2float(hb);
    __half lb = __float2half_rn(lf);
    h = __half_as_ushort(hb);
    l = __half_as_ushort(lb);
}
__device__ __forceinline__ void cpa16(u32 dst, const void* src) {
    asm volatile("cp.async.cg.shared.global [%0], [%1], 16;"
                 :: "r"(dst), "l"(__cvta_generic_to_global(src)) : "memory");
}
__device__ __forceinline__ void mma_bf16(float* c, const u32* A, const u32* B) {
    asm volatile(
        "mma.sync.aligned.m16n8k16.row.col.f32.bf16.bf16.f32 "
        "{%0,%1,%2,%3}, {%4,%5,%6,%7}, {%8,%9}, {%0,%1,%2,%3};"
        : "+f"(c[0]), "+f"(c[1]), "+f"(c[2]), "+f"(c[3])
        : "r"(A[0]), "r"(A[1]), "r"(A[2]), "r"(A[3]), "r"(B[0]), "r"(B[1]));
}
__device__ __forceinline__ void mma_f16(float* c, const u32* A, const u32* B) {
    asm volatile(
        "mma.sync.aligned.m16n8k16.row.col.f32.f16.f16.f32 "
        "{%0,%1,%2,%3}, {%4,%5,%6,%7}, {%8,%9}, {%0,%1,%2,%3};"
        : "+f"(c[0]), "+f"(c[1]), "+f"(c[2]), "+f"(c[3])
        : "r"(A[0]), "r"(A[1]), "r"(A[2]), "r"(A[3]), "r"(B[0]), "r"(B[1]));
}
template<int FT>
__device__ __forceinline__ void mma16(float* c, const u32* A, const u32* B) {
    if (FT == 0) mma_bf16(c, A, B);
    else         mma_f16(c, A, B);
}
__device__ __forceinline__ void ldsm4(u32& r0, u32& r1, u32& r2, u32& r3, u32 addr) {
    asm volatile("ldmatrix.sync.aligned.m8n8.x4.shared.b16 {%0,%1,%2,%3}, [%4];"
                 : "=r"(r0), "=r"(r1), "=r"(r2), "=r"(r3) : "r"(addr));
}

// ---------------- fused split: x + 4 weight matrices in one launch ----------------
struct SplitJobs {
    const float4 *x, *wq, *wk, *wv, *wo;
    u16 *xh, *xl, *wqh, *wql, *wkh, *wkl, *wvh, *wvl, *woh, *wol;
};
__global__ void split_all_kernel(SplitJobs j)
{
    const float4* src;
    u16 *hi, *lo;
    int base, n4;
    int bx = blockIdx.x;
    if (bx < 2048)      { src = j.x;  hi = j.xh;  lo = j.xl;  base = bx;        n4 = Mtot * Dc / 4; }
    else if (bx < 2560) { src = j.wq; hi = j.wqh; lo = j.wql; base = bx - 2048; n4 = Dc * Dc / 4; }
    else if (bx < 3072) { src = j.wk; hi = j.wkh; lo = j.wkl; base = bx - 2560; n4 = Dc * Dc / 4; }
    else if (bx < 3584) { src = j.wv; hi = j.wvh; lo = j.wvl; base = bx - 3072; n4 = Dc * Dc / 4; }
    else                { src = j.wo; hi = j.woh; lo = j.wol; base = bx - 3584; n4 = Dc * Dc / 4; }
    const int stride = (bx < 2048) ? 2048 * 256 : 512 * 256;
    for (int i = base * 256 + threadIdx.x; i < n4; i += stride) {
        float4 a = src[i];
        ushort4 hv, lv;
        hsplit(a.x, hv.x, lv.x); hsplit(a.y, hv.y, lv.y);
        hsplit(a.z, hv.z, lv.z); hsplit(a.w, hv.w, lv.w);
        *(ushort4*)(hi + (size_t)i * 4) = hv;
        *(ushort4*)(lo + (size_t)i * 4) = lv;
    }
}
__global__ void rft_kernel(const float* __restrict__ rf, u16* __restrict__ oh,
                           u16* __restrict__ ol)
{
    int idx = blockIdx.x * blockDim.x + threadIdx.x;
    if (idx >= Hc * Rc * HDc) return;
    int d = idx & 63, r = (idx >> 6) & 255, h = idx >> 14;
    float a = rf[((size_t)(h * HDc + d)) * Rc + r];
    u16 hv, lv; hsplit(a, hv, lv);
    oh[idx] = hv; ol[idx] = lv;
}

// ---------------- split-precision tensor GEMM engine ----------------
// C[128 x NTILE] per CTA; C = A * B^T (fp32 accum).
// FT: 0=bf16 operands, 1=fp16.  XN: 3 = hh+lh+hl, 2 = hh+lh.
// EPI: 0 +bias(col)->f32 | 1 +bias(col)->fp16 split + per-head rownorm
//      2 exp(v-0.5*norm[row])->bf16 split | 4 normalize by in-loop (A.ksum)->fp16 split
//      5 exp(v-0.5*norm[col])->bf16 split | 6 +bias(row)->bf16 split
//      8 split-K partial: raw f32 out + in-loop A-rowsum partial (chunk=blockIdx.x)
struct TGP {
    const u16 *ah, *al, *bh, *bl;
    long long a_ob, a_oh, b_ob, b_oh, o_ob, o_oh;
    int a_st, b_st, o_st, K;
    const float *bias, *norm, *ksum;
    float* o0;
    u16 *o_hi, *o_lo;
    float* nrm_out;
};

template<int NTILE, int EPI, int FT, int XN>
__global__ void __launch_bounds__(256, 2) tgemm(TGP p)
{
    extern __shared__ char smc[];
    const int tid = threadIdx.x, lane = tid & 31, wid = tid >> 5;
    const int z = blockIdx.z;
    const int m0 = blockIdx.y << 7;
    const int chunk = (EPI == 8) ? blockIdx.x : 0;
    const int n0 = (EPI == 8) ? 0 : blockIdx.x * NTILE;

    constexpr int MT = (NTILE == 128) ? 4 : 2;
    constexpr bool OUT_BF = (EPI == 2 || EPI == 5 || EPI == 6);
    const int wm0 = (NTILE == 128) ? ((wid & 1) << 6) : ((wid & 3) << 5);
    const int wn0 = (NTILE == 128) ? ((wid >> 1) << 5) : ((wid >> 2) << 5);

    constexpr int APL = 128 * RS * 2;
    constexpr int BPL = NTILE * RS * 2;
    constexpr int BLK = 2 * APL + 2 * BPL;
    const u32 su = smem_u32(smc);
    float* const ksums = (float*)(smc + 2 * BLK);
    float* const snorm = ksums + 256;

    size_t aoff = (size_t)p.a_ob * (z >> 4) + (size_t)p.a_oh * (z & 15);
    size_t boff = (size_t)p.b_ob * (z >> 4) + (size_t)p.b_oh * (z & 15);
    const size_t ooff = (size_t)p.o_ob * (z >> 4) + (size_t)p.o_oh * (z & 15);
    if (EPI == 8) { aoff += (size_t)chunk * 1024; boff += (size_t)chunk * 1024; }

    if (EPI == 4) ksums[tid] = p.ksum[(size_t)z * Rc + tid];

    const int steps = p.K / BK;

    auto issue = [&](int step) {
        const int k0 = step * BK;
        const u32 sb = su + (step & 1) * BLK;
        const u16* agh = p.ah + aoff + k0;
        const u16* agl = p.al + aoff + k0;
        const u16* bgh = p.bh + boff + k0;
        const u16* bgl = p.bl + boff + k0;
        #pragma unroll
        for (int j = tid; j < 512; j += 256) {
            int row = j >> 2, ch = j & 3;
            size_t gs = (size_t)(m0 + row) * p.a_st + ch * 8;
            u32 so = row * (RS * 2) + ch * 16;
            cpa16(sb + so, agh + gs);
            cpa16(sb + APL + so, agl + gs);
        }
        #pragma unroll
        for (int j = tid; j < NTILE * 4; j += 256) {
            int row = j >> 2, ch = j & 3;
            size_t gs = (size_t)(n0 + row) * p.b_st + ch * 8;
            u32 so = row * (RS * 2) + ch * 16;
            cpa16(sb + 2 * APL + so, bgh + gs);
            if (XN == 3) cpa16(sb + 2 * APL + BPL + so, bgl + gs);
        }
        asm volatile("cp.async.commit_group;" ::: "memory");
    };

    issue(0);

    float acc[MT][4][4];
    #pragma unroll
    for (int i = 0; i < MT; i++)
        #pragma unroll
        for (int j = 0; j < 4; j++)
            #pragma unroll
            for (int c = 0; c < 4; c++) acc[i][j][c] = 0.0f;
    float nacc = 0.0f;

    const u32 aoff_lane = (lane & 15) * (RS * 2) + (lane >> 4) * 16;
    const u32 boff_lane = ((lane & 7) + ((lane >> 4) << 3)) * (RS * 2) + ((lane >> 3) & 1) * 16;

    for (int i = 0; i < steps; i++) {
        asm volatile("cp.async.wait_group 0;" ::: "memory");
        __syncthreads();
        if (i + 1 < steps) issue(i + 1);

        const int buf = i & 1;
        const u32 sb = su + buf * BLK;

        if (EPI == 4 || EPI == 8) {
            int row = tid >> 1, half16 = tid & 1;
            const __nv_bfloat162* xh = (const __nv_bfloat162*)(smc + buf * BLK
                                        + row * (RS * 2) + half16 * 32);
            const __nv_bfloat162* xl = (const __nv_bfloat162*)(smc + buf * BLK + APL
                                        + row * (RS * 2) + half16 * 32);
            if (EPI == 4) {
                const float* kv = ksums + i * BK + half16 * 16;
                #pragma unroll
                for (int t = 0; t < 8; t++) {
                    float2 h2 = __bfloat1622float2(xh[t]);
                    float2 l2 = __bfloat1622float2(xl[t]);
                    nacc += (h2.x + l2.x) * kv[2 * t] + (h2.y + l2.y) * kv[2 * t + 1];
                }
            } else {
                #pragma unroll
                for (int t = 0; t < 8; t++) {
                    float2 h2 = __bfloat1622float2(xh[t]);
                    float2 l2 = __bfloat1622float2(xl[t]);
                    nacc += h2.x + l2.x + h2.y + l2.y;
                }
            }
        }

        #pragma unroll
        for (int half = 0; half < 2; half++) {
            const u32 kb = half * 32;
            u32 ahr[MT][4], alr[MT][4];
            #pragma unroll
            for (int im = 0; im < MT; im++) {
                u32 abase = sb + (wm0 + im * 16) * (RS * 2) + kb + aoff_lane;
                ldsm4(ahr[im][0], ahr[im][1], ahr[im][2], ahr[im][3], abase);
                ldsm4(alr[im][0], alr[im][1], alr[im][2], alr[im][3], abase + APL);
            }
            #pragma unroll
            for (int npair = 0; npair < 2; npair++) {
                u32 bbase = sb + 2 * APL + (wn0 + npair * 16) * (RS * 2) + kb + boff_lane;
                u32 bh0, bh1, bh2_, bh3;
                ldsm4(bh0, bh1, bh2_, bh3, bbase);
                u32 bhA[2] = { bh0, bh1 }, bhB[2] = { bh2_, bh3 };
                const int iA = npair * 2, iB = npair * 2 + 1;
                #pragma unroll
                for (int im = 0; im < MT; im++) mma16<FT>(acc[im][iA], ahr[im], bhA);
                #pragma unroll
                for (int im = 0; im < MT; im++) mma16<FT>(acc[im][iB], ahr[im], bhB);
                #pragma unroll
                for (int im = 0; im < MT; im++) mma16<FT>(acc[im][iA], alr[im], bhA);
                #pragma unroll
                for (int im = 0; im < MT; im++) mma16<FT>(acc[im][iB], alr[im], bhB);
                if (XN == 3) {
                    u32 bl0, bl1, bl2_, bl3;
                    ldsm4(bl0, bl1, bl2_, bl3, bbase + BPL);
                    u32 blA[2] = { bl0, bl1 }, blB[2] = { bl2_, bl3 };
                    #pragma unroll
                    for (int im = 0; im < MT; im++) mma16<FT>(acc[im][iA], ahr[im], blA);
                    #pragma unroll
                    for (int im = 0; im < MT; im++) mma16<FT>(acc[im][iB], ahr[im], blB);
                }
            }
        }
    }
    __syncthreads();

    if (EPI == 4 || EPI == 8) { snorm[tid] = nacc; __syncthreads(); }
    if (EPI == 1) { ksums[tid] = 0.0f; __syncthreads(); }

    // ---------------- epilogue ----------------
    const int lh = wn0 >> 6;
    #pragma unroll
    for (int im = 0; im < MT; im++) {
        const int la = wm0 + im * 16 + (lane >> 2);
        const int lb = la + 8;
        const int rA = m0 + la, rB = m0 + lb;
        float hnA = 0.0f, hnB = 0.0f, invA = 1.0f, invB = 1.0f;
        float bA = 0.0f, bB = 0.0f;
        if (EPI == 2) {
            hnA = 0.5f * p.norm[(size_t)z * Sc + rA];
            hnB = 0.5f * p.norm[(size_t)z * Sc + rB];
        }
        if (EPI == 6) {
            bA = __ldg(p.bias + rA);
            bB = __ldg(p.bias + rB);
        }
        if (EPI == 4) {
            invA = 1.0f / (snorm[2 * la] + snorm[2 * la + 1] + 1e-6f);
            invB = 1.0f / (snorm[2 * lb] + snorm[2 * lb + 1] + 1e-6f);
        }
        float sA = 0.0f, sB = 0.0f;
        #pragma unroll
        for (int in_ = 0; in_ < 4; in_++) {
            const int n = n0 + wn0 + in_ * 8 + ((lane & 3) << 1);
            float v0 = acc[im][in_][0], v1 = acc[im][in_][1];
            float v2 = acc[im][in_][2], v3 = acc[im][in_][3];
            if (EPI == 0 || EPI == 1) {
                float b0 = __ldg(p.bias + n), b1 = __ldg(p.bias + n + 1);
                v0 += b0; v1 += b1; v2 += b0; v3 += b1;
            } else if (EPI == 6) {
                v0 += bA; v1 += bA; v2 += bB; v3 += bB;
            } else if (EPI == 2) {
                v0 = __expf(v0 - hnA); v1 = __expf(v1 - hnA);
                v2 = __expf(v2 - hnB); v3 = __expf(v3 - hnB);
            } else if (EPI == 5) {
                float hn0 = 0.5f * __ldg(p.norm + (size_t)z * Sc + n);
                float hn1 = 0.5f * __ldg(p.norm + (size_t)z * Sc + n + 1);
                v0 = __expf(v0 - hn0); v1 = __expf(v1 - hn1);
                v2 = __expf(v2 - hn0); v3 = __expf(v3 - hn1);
            } else if (EPI == 4) {
                v0 *= invA; v1 *= invA; v2 *= invB; v3 *= invB;
            }
            if (EPI == 1) { sA += v0 * v0 + v1 * v1; sB += v2 * v2 + v3 * v3; }
            if (EPI == 0) {
                *(float2*)(p.o0 + ooff + (size_t)rA * p.o_st + n) = make_float2(v0, v1);
                *(float2*)(p.o0 + ooff + (size_t)rB * p.o_st + n) = make_float2(v2, v3);
            } else if (EPI == 8) {
                float* b8 = p.o0 + (((size_t)z * 4 + chunk) << 14);
                *(float2*)(b8 + (size_t)rA * 64 + n) = make_float2(v0, v1);
                *(float2*)(b8 + (size_t)rB * 64 + n) = make_float2(v2, v3);
            } else {
                u16 h0, l0, h1, l1, h2, l2, h3, l3;
                if (OUT_BF) {
                    bsplit(v0, h0, l0); bsplit(v1, h1, l1);
                    bsplit(v2, h2, l2); bsplit(v3, h3, l3);
                } else {
                    hsplit(v0, h0, l0); hsplit(v1, h1, l1);
                    hsplit(v2, h2, l2); hsplit(v3, h3, l3);
                }
                size_t oA = ooff + (size_t)rA * p.o_st + n;
                size_t oB = ooff + (size_t)rB * p.o_st + n;
                *(u32*)(p.o_hi + oA) = (u32)h0 | ((u32)h1 << 16);
                *(u32*)(p.o_lo + oA) = (u32)l0 | ((u32)l1 << 16);
                *(u32*)(p.o_hi + oB) = (u32)h2 | ((u32)h3 << 16);
                *(u32*)(p.o_lo + oB) = (u32)l2 | ((u32)l3 << 16);
            }
        }
        if (EPI == 1) {
            atomicAdd(&ksums[la * 2 + lh], sA);
            atomicAdd(&ksums[lb * 2 + lh], sB);
        }
    }

    if (EPI == 1) {
        __syncthreads();
        int row = tid >> 1, hloc = tid & 1;
        int rg = m0 + row, b = rg >> 12, s = rg & 4095;
        int head = (n0 >> 6) + hloc;
        p.nrm_out[(size_t)(b * 16 + head) * Sc + s] = ksums[tid];
    }
    if (EPI == 8) {
        if (tid < 128)
            p.nrm_out[(((size_t)z * 4 + chunk) << 8) + m0 + tid] =
                snorm[2 * tid] + snorm[2 * tid + 1];
    }
}

// ---------------- kv final reduce ----------------
__global__ void kvfinal_kernel(const float* __restrict__ kvp, const float* __restrict__ ksp,
                               u16* __restrict__ kvth, u16* __restrict__ kvtl,
                               float* __restrict__ ks)
{
    size_t idx = (size_t)blockIdx.x * 256 + threadIdx.x;
    int r = (int)(idx & 255), d = (int)((idx >> 8) & 63), bh = (int)(idx >> 14);
    float s = 0.0f;
    #pragma unroll
    for (int c = 0; c < 4; c++)
        s += kvp[(((size_t)bh * 4 + c) << 14) + (r << 6) + d];
    u16 hv, lv; bsplit(s, hv, lv);
    size_t o = ((size_t)bh << 14) + (d << 8) + r;
    kvth[o] = hv; kvtl[o] = lv;
    if (idx < (size_t)64 * 256) {
        int bh2 = (int)(idx >> 8), r2 = (int)(idx & 255);
        float t = 0.0f;
        #pragma unroll
        for (int c = 0; c < 4; c++) t += ksp[((size_t)(bh2 * 4 + c) << 8) + r2];
        ks[idx] = t;
    }
}

// ---------------- launch ----------------
extern "C" void kernel_launch(void* const* d_in, const int* in_sizes, int n_in,
                              void* d_out, int out_size)
{
    (void)in_sizes; (void)n_in; (void)out_size;
    const float* x  = (const float*)d_in[0];
    const float* wq = (const float*)d_in[1];
    const float* bq = (const float*)d_in[2];
    const float* wk = (const float*)d_in[3];
    const float* bk = (const float*)d_in[4];
    const float* wv = (const float*)d_in[5];
    const float* bv = (const float*)d_in[6];
    const float* wo = (const float*)d_in[7];
    const float* bo = (const float*)d_in[8];
    const float* rf = (const float*)d_in[9];
    float* out = (float*)d_out;

    u16 *xh, *xl, *wqh, *wql, *wkh, *wkl, *wvh, *wvl, *woh, *wol;
    u16 *rfh, *rfl, *qh, *ql, *kh, *kl, *vth, *vtl, *qph, *qpl;
    u16 *kpth, *kptl, *kvth, *kvtl, *ath, *atl;
    float *nq, *nk, *kvp, *ksp, *ksum;
    cudaGetSymbolAddress((void**)&xh,  g_xh);   cudaGetSymbolAddress((void**)&xl,  g_xl);
    cudaGetSymbolAddress((void**)&wqh, g_wqh);  cudaGetSymbolAddress((void**)&wql, g_wql);
    cudaGetSymbolAddress((void**)&wkh, g_wkh);  cudaGetSymbolAddress((void**)&wkl, g_wkl);
    cudaGetSymbolAddress((void**)&wvh, g_wvh);  cudaGetSymbolAddress((void**)&wvl, g_wvl);
    cudaGetSymbolAddress((void**)&woh, g_woh);  cudaGetSymbolAddress((void**)&wol, g_wol);
    cudaGetSymbolAddress((void**)&rfh, g_rfh);  cudaGetSymbolAddress((void**)&rfl, g_rfl);
    cudaGetSymbolAddress((void**)&qh,  g_qh);   cudaGetSymbolAddress((void**)&ql,  g_ql);
    cudaGetSymbolAddress((void**)&kh,  g_kh);   cudaGetSymbolAddress((void**)&kl,  g_kl);
    cudaGetSymbolAddress((void**)&vth, g_vth);  cudaGetSymbolAddress((void**)&vtl, g_vtl);
    cudaGetSymbolAddress((void**)&nq,  g_nq);   cudaGetSymbolAddress((void**)&nk,  g_nk);
    cudaGetSymbolAddress((void**)&qph, g_qph);  cudaGetSymbolAddress((void**)&qpl, g_qpl);
    cudaGetSymbolAddress((void**)&kpth, g_kpth);cudaGetSymbolAddress((void**)&kptl, g_kptl);
    cudaGetSymbolAddress((void**)&kvp, g_kvp);  cudaGetSymbolAddress((void**)&ksp, g_ksp);
    cudaGetSymbolAddress((void**)&kvth, g_kvth);cudaGetSymbolAddress((void**)&kvtl, g_kvtl);
    cudaGetSymbolAddress((void**)&ksum, g_ksum);
    cudaGetSymbolAddress((void**)&ath, g_ath);  cudaGetSymbolAddress((void**)&atl, g_atl);

    const int SM128 = 2 * (2 * 128 * RS * 2 + 2 * 128 * RS * 2) + 2048;  // 83968
    const int SM64  = 2 * (2 * 128 * RS * 2 + 2 * 64 * RS * 2) + 2048;   // 63488
    cudaFuncSetAttribute(tgemm<128, 0, 1, 2>, cudaFuncAttributeMaxDynamicSharedMemorySize, SM128);
    cudaFuncSetAttribute(tgemm<128, 1, 1, 3>, cudaFuncAttributeMaxDynamicSharedMemorySize, SM128);
    cudaFuncSetAttribute(tgemm<128, 2, 1, 3>, cudaFuncAttributeMaxDynamicSharedMemorySize, SM128);
    cudaFuncSetAttribute(tgemm<128, 5, 1, 3>, cudaFuncAttributeMaxDynamicSharedMemorySize, SM128);
    cudaFuncSetAttribute(tgemm<128, 6, 1, 2>, cudaFuncAttributeMaxDynamicSharedMemorySize, SM128);
    cudaFuncSetAttribute(tgemm<64, 4, 0, 3>,  cudaFuncAttributeMaxDynamicSharedMemorySize, SM64);
    cudaFuncSetAttribute(tgemm<64, 8, 0, 3>,  cudaFuncAttributeMaxDynamicSharedMemorySize, SM64);

    // fused splits (1 launch) + rft
    SplitJobs sj = { (const float4*)x, (const float4*)wq, (const float4*)wk,
                     (const float4*)wv, (const float4*)wo,
                     xh, xl, wqh, wql, wkh, wkl, wvh, wvl, woh, wol };
    split_all_kernel<<<4096, 256>>>(sj);
    rft_kernel<<<(Hc * Rc * HDc + 255) / 256, 256>>>(rf, rfh, rfl);

    // Q/K projections (M=16384, N=1024, K=1024), fp16x3 -> fp16 split + rownorm
    dim3 gproj(Dc / 128, Mtot / 128, 1);
    TGP pj = {};
    pj.ah = xh; pj.al = xl; pj.a_ob = 0; pj.a_oh = 0; pj.a_st = Dc;
    pj.b_ob = 0; pj.b_oh = 0; pj.b_st = Dc; pj.K = Dc;
    pj.o_ob = 0; pj.o_oh = 0; pj.o_st = Dc;

    TGP pq = pj; pq.bh = wqh; pq.bl = wql; pq.bias = bq;
    pq.o_hi = qh; pq.o_lo = ql; pq.nrm_out = nq;
    tgemm<128, 1, 1, 3><<<gproj, 256, SM128>>>(pq);
    TGP pk = pj; pk.bh = wkh; pk.bl = wkl; pk.bias = bk;
    pk.o_hi = kh; pk.o_lo = kl; pk.nrm_out = nk;
    tgemm<128, 1, 1, 3><<<gproj, 256, SM128>>>(pk);

    // V projection TRANSPOSED: C[d, m] = wv * x^T, fp16x2 -> bf16 split
    dim3 gvt(Mtot / 128, Dc / 128, 1);
    TGP pv = {};
    pv.ah = wvh; pv.al = wvl; pv.a_ob = 0; pv.a_oh = 0; pv.a_st = Dc;
    pv.bh = xh;  pv.bl = xl;  pv.b_ob = 0; pv.b_oh = 0; pv.b_st = Dc;
    pv.K = Dc; pv.bias = bv;
    pv.o_hi = vth; pv.o_lo = vtl; pv.o_ob = 0; pv.o_oh = 0; pv.o_st = Mtot;
    tgemm<128, 6, 1, 2><<<gvt, 256, SM128>>>(pv);

    // feature-Q (per bh: M=4096 s, N=256 r, K=64), fp16x3 -> bf16 split
    dim3 gfeat(Rc / 128, Sc / 128, Bc * Hc);
    TGP pfq = {};
    pfq.ah = qh; pfq.al = ql;
    pfq.a_ob = (long long)Sc * Dc; pfq.a_oh = HDc; pfq.a_st = Dc;
    pfq.bh = rfh; pfq.bl = rfl;
    pfq.b_ob = 0; pfq.b_oh = (long long)Rc * HDc; pfq.b_st = HDc;
    pfq.K = HDc; pfq.norm = nq;
    pfq.o_hi = qph; pfq.o_lo = qpl;
    pfq.o_ob = (long long)16 * Sc * Rc; pfq.o_oh = (long long)Sc * Rc; pfq.o_st = Rc;
    tgemm<128, 2, 1, 3><<<gfeat, 256, SM128>>>(pfq);

    // feature-K TRANSPOSED (per bh: M=256 r, N=4096 s, K=64), fp16x3 -> bf16 split
    dim3 gfkt(Sc / 128, Rc / 128, Bc * Hc);
    TGP pfk = {};
    pfk.ah = rfh; pfk.al = rfl;
    pfk.a_ob = 0; pfk.a_oh = (long long)Rc * HDc; pfk.a_st = HDc;
    pfk.bh = kh; pfk.bl = kl;
    pfk.b_ob = (long long)Sc * Dc; pfk.b_oh = HDc; pfk.b_st = Dc;
    pfk.K = HDc; pfk.norm = nk;
    pfk.o_hi = kpth; pfk.o_lo = kptl;
    pfk.o_ob = (long long)16 * Rc * Sc; pfk.o_oh = (long long)Rc * Sc; pfk.o_st = Sc;
    tgemm<128, 5, 1, 3><<<gfkt, 256, SM128>>>(pfk);

    // kv aggregation GEMM (per bh: M=256 r, N=64 d, K=4096 s, split-K x4), bf16x3
    dim3 gkv(4, Rc / 128, Bc * Hc);
    TGP pkv = {};
    pkv.ah = kpth; pkv.al = kptl;
    pkv.a_ob = (long long)16 * Rc * Sc; pkv.a_oh = (long long)Rc * Sc; pkv.a_st = Sc;
    pkv.bh = vth; pkv.bl = vtl;
    pkv.b_ob = 4096; pkv.b_oh = (long long)64 * Mtot; pkv.b_st = Mtot;
    pkv.K = 1024;
    pkv.o0 = kvp; pkv.nrm_out = ksp;
    tgemm<64, 8, 0, 3><<<gkv, 256, SM64>>>(pkv);

    kvfinal_kernel<<<4096, 256>>>(kvp, ksp, kvth, kvtl, ksum);

    // attention readout (per bh: M=4096 s, N=64 d, K=256 r), bf16x3 -> fp16 split
    dim3 gat(1, Sc / 128, Bc * Hc);
    TGP pa = {};
    pa.ah = qph; pa.al = qpl;
    pa.a_ob = (long long)16 * Sc * Rc; pa.a_oh = (long long)Sc * Rc; pa.a_st = Rc;
    pa.bh = kvth; pa.bl = kvtl;
    pa.b_ob = (long long)16 * HDc * Rc; pa.b_oh = (long long)HDc * Rc; pa.b_st = Rc;
    pa.K = Rc; pa.ksum = ksum;
    pa.o_hi = ath; pa.o_lo = atl;
    pa.o_ob = (long long)Sc * Dc; pa.o_oh = HDc; pa.o_st = Dc;
    tgemm<64, 4, 0, 3><<<gat, 256, SM64>>>(pa);

    // output projection, fp16x2 -> f32
    TGP po = pj; po.ah = ath; po.al = atl; po.bh = woh; po.bl = wol;
    po.bias = bo; po.o0 = out;
    tgemm<128, 0, 1, 2><<<gproj, 256, SM128>>>(po);
}

// round 15
// speedup vs baseline: 1.3333x; 1.0104x over previous
#include <cuda_runtime.h>
#include <cuda_bf16.h>
#include <cuda_fp16.h>
#include <cstdint>
#include <math.h>

#define Bc 4
#define Sc 4096
#define Dc 1024
#define Hc 16
#define Rc 256
#define HDc 64
#define Mtot (Bc * Sc)
#define BK 32
#define RS 40      // smem row stride in u16 (32 data + 8 pad = 80B)

typedef unsigned short u16;
typedef uint32_t u32;

// ---------------- scratch (device globals) ----------------
__device__ u16 g_xh[(size_t)Mtot * Dc],  g_xl[(size_t)Mtot * Dc];
__device__ u16 g_wqh[Dc * Dc], g_wql[Dc * Dc];
__device__ u16 g_wkh[Dc * Dc], g_wkl[Dc * Dc];
__device__ u16 g_wvh[Dc * Dc], g_wvl[Dc * Dc];
__device__ u16 g_woh[Dc * Dc], g_wol[Dc * Dc];
__device__ u16 g_rfh[(size_t)Hc * Rc * HDc], g_rfl[(size_t)Hc * Rc * HDc];
__device__ u16 g_qh[(size_t)Mtot * Dc],  g_ql[(size_t)Mtot * Dc];
__device__ u16 g_kh[(size_t)Mtot * Dc],  g_kl[(size_t)Mtot * Dc];
__device__ u16 g_ath[(size_t)Mtot * Dc], g_atl[(size_t)Mtot * Dc];
// bf16 split planes (exp outputs exceed fp16 range)
__device__ u16 g_vth[(size_t)Mtot * Dc], g_vtl[(size_t)Mtot * Dc];   // V^T [d][m]
__device__ u16 g_qph[(size_t)Bc * Hc * Sc * Rc], g_qpl[(size_t)Bc * Hc * Sc * Rc];
__device__ u16 g_kpth[(size_t)Bc * Hc * Rc * Sc], g_kptl[(size_t)Bc * Hc * Rc * Sc];
__device__ u16 g_kvth[(size_t)Bc * Hc * HDc * Rc], g_kvtl[(size_t)Bc * Hc * HDc * Rc];
// fp32
__device__ float g_nq[(size_t)Bc * Hc * Sc], g_nk[(size_t)Bc * Hc * Sc];
__device__ float g_kvp[(size_t)Bc * Hc * 4 * Rc * HDc];
__device__ float g_ksp[(size_t)Bc * Hc * 4 * Rc];
__device__ float g_ksum[(size_t)Bc * Hc * Rc];

// ---------------- helpers ----------------
__device__ __forceinline__ u32 smem_u32(const void* p) {
    u32 a;
    asm("{ .reg .u64 t; cvta.to.shared.u64 t, %1; cvt.u32.u64 %0, t; }" : "=r"(a) : "l"(p));
    return a;
}
__device__ __forceinline__ void bsplit(float a, u16& h, u16& l) {
    __nv_bfloat16 hb = __float2bfloat16_rn(a);
    float lf = a - __bfloat162float(hb);
    __nv_bfloat16 lb = __float2bfloat16_rn(lf);
    h = __bfloat16_as_ushort(hb);
    l = __bfloat16_as_ushort(lb);
}
__device__ __forceinline__ void hsplit(float a, u16& h, u16& l) {
    __half hb = __float2half_rn(a);
    float lf = a - __half2float(hb);
    __half lb = __float2half_rn(lf);
    h = __half_as_ushort(hb);
    l = __half_as_ushort(lb);
}
__device__ __forceinline__ void cpa16(u32 dst, const void* src) {
    asm volatile("cp.async.cg.shared.global [%0], [%1], 16;"
                 :: "r"(dst), "l"(__cvta_generic_to_global(src)) : "memory");
}
__device__ __forceinline__ void mma_bf16(float* c, const u32* A, const u32* B) {
    asm volatile(
        "mma.sync.aligned.m16n8k16.row.col.f32.bf16.bf16.f32 "
        "{%0,%1,%2,%3}, {%4,%5,%6,%7}, {%8,%9}, {%0,%1,%2,%3};"
        : "+f"(c[0]), "+f"(c[1]), "+f"(c[2]), "+f"(c[3])
        : "r"(A[0]), "r"(A[1]), "r"(A[2]), "r"(A[3]), "r"(B[0]), "r"(B[1]));
}
__device__ __forceinline__ void mma_f16(float* c, const u32* A, const u32* B) {
    asm volatile(
        "mma.sync.aligned.m16n8k16.row.col.f32.f16.f16.f32 "
        "{%0,%1,%2,%3}, {%4,%5,%6,%7}, {%8,%9}, {%0,%1,%2,%3};"
        : "+f"(c[0]), "+f"(c[1]), "+f"(c[2]), "+f"(c[3])
        : "r"(A[0]), "r"(A[1]), "r"(A[2]), "r"(A[3]), "r"(B[0]), "r"(B[1]));
}
template<int FT>
__device__ __forceinline__ void mma16(float* c, const u32* A, const u32* B) {
    if (FT == 0) mma_bf16(c, A, B);
    else         mma_f16(c, A, B);
}
__device__ __forceinline__ void ldsm4(u32& r0, u32& r1, u32& r2, u32& r3, u32 addr) {
    asm volatile("ldmatrix.sync.aligned.m8n8.x4.shared.b16 {%0,%1,%2,%3}, [%4];"
                 : "=r"(r0), "=r"(r1), "=r"(r2), "=r"(r3) : "r"(addr));
}

// ---------------- fused split: x + 4 weights + rf-transpose in ONE launch ----------
struct SplitJobs {
    const float4 *x, *wq, *wk, *wv, *wo;
    const float* rf;
    u16 *xh, *xl, *wqh, *wql, *wkh, *wkl, *wvh, *wvl, *woh, *wol, *rfh, *rfl;
};
__global__ void split_all_kernel(SplitJobs j)
{
    int bx = blockIdx.x;
    if (bx >= 4096) {   // rf transpose: blocks 4096..5119 cover 262144 elems
        int idx = (bx - 4096) * 256 + threadIdx.x;
        if (idx < Hc * Rc * HDc) {
            int d = idx & 63, r = (idx >> 6) & 255, h = idx >> 14;
            float a = j.rf[((size_t)(h * HDc + d)) * Rc + r];
            u16 hv, lv; hsplit(a, hv, lv);
            j.rfh[idx] = hv; j.rfl[idx] = lv;
        }
        return;
    }
    const float4* src;
    u16 *hi, *lo;
    int base, n4;
    if (bx < 2048)      { src = j.x;  hi = j.xh;  lo = j.xl;  base = bx;        n4 = Mtot * Dc / 4; }
    else if (bx < 2560) { src = j.wq; hi = j.wqh; lo = j.wql; base = bx - 2048; n4 = Dc * Dc / 4; }
    else if (bx < 3072) { src = j.wk; hi = j.wkh; lo = j.wkl; base = bx - 2560; n4 = Dc * Dc / 4; }
    else if (bx < 3584) { src = j.wv; hi = j.wvh; lo = j.wvl; base = bx - 3072; n4 = Dc * Dc / 4; }
    else                { src = j.wo; hi = j.woh; lo = j.wol; base = bx - 3584; n4 = Dc * Dc / 4; }
    const int stride = (bx < 2048) ? 2048 * 256 : 512 * 256;
    for (int i = base * 256 + threadIdx.x; i < n4; i += stride) {
        float4 a = src[i];
        ushort4 hv, lv;
        hsplit(a.x, hv.x, lv.x); hsplit(a.y, hv.y, lv.y);
        hsplit(a.z, hv.z, lv.z); hsplit(a.w, hv.w, lv.w);
        *(ushort4*)(hi + (size_t)i * 4) = hv;
        *(ushort4*)(lo + (size_t)i * 4) = lv;
    }
}

// ---------------- split-precision tensor GEMM engine ----------------
// C[128 x NTILE] per CTA; C = A * B^T (fp32 accum).
// FT: 0=bf16 operands, 1=fp16.  XN: 3 = hh+lh+hl, 2 = hh+lh.
// EPI: 0 +bias(col)->f32 | 1 +bias(col)->fp16 split + per-head rownorm
//        (EPI 1 uses blockIdx.z to select param set {bh2,...} for fused Q/K)
//      2 exp(v-0.5*norm[row])->bf16 split | 4 normalize by in-loop (A.ksum)->fp16 split
//      5 exp(v-0.5*norm[col])->bf16 split | 6 +bias(row)->bf16 split
//      8 split-K partial: raw f32 out + in-loop A-rowsum partial (chunk=blockIdx.x)
struct TGP {
    const u16 *ah, *al, *bh, *bl;
    long long a_ob, a_oh, b_ob, b_oh, o_ob, o_oh;
    int a_st, b_st, o_st, K;
    const float *bias, *norm, *ksum;
    float* o0;
    u16 *o_hi, *o_lo;
    float* nrm_out;
    // second param set (EPI 1 fused Q/K, selected by blockIdx.z==1)
    const u16 *bh2, *bl2;
    const float* bias2;
    u16 *o_hi2, *o_lo2;
    float* nrm_out2;
};

template<int NTILE, int EPI, int FT, int XN>
__global__ void __launch_bounds__(256, 2) tgemm(TGP p)
{
    extern __shared__ char smc[];
    const int tid = threadIdx.x, lane = tid & 31, wid = tid >> 5;
    const int z = blockIdx.z;
    const int m0 = blockIdx.y << 7;
    const int chunk = (EPI == 8) ? blockIdx.x : 0;
    const int n0 = (EPI == 8) ? 0 : blockIdx.x * NTILE;

    if (EPI == 1 && z == 1) {
        p.bh = p.bh2; p.bl = p.bl2; p.bias = p.bias2;
        p.o_hi = p.o_hi2; p.o_lo = p.o_lo2; p.nrm_out = p.nrm_out2;
    }

    constexpr int MT = (NTILE == 128) ? 4 : 2;
    constexpr bool OUT_BF = (EPI == 2 || EPI == 5 || EPI == 6);
    const int wm0 = (NTILE == 128) ? ((wid & 1) << 6) : ((wid & 3) << 5);
    const int wn0 = (NTILE == 128) ? ((wid >> 1) << 5) : ((wid >> 2) << 5);

    constexpr int APL = 128 * RS * 2;
    constexpr int BPL = NTILE * RS * 2;
    constexpr int BLK = 2 * APL + 2 * BPL;
    const u32 su = smem_u32(smc);
    float* const ksums = (float*)(smc + 2 * BLK);
    float* const snorm = ksums + 256;

    const int zz = (EPI == 1) ? 0 : z;
    size_t aoff = (size_t)p.a_ob * (zz >> 4) + (size_t)p.a_oh * (zz & 15);
    size_t boff = (size_t)p.b_ob * (zz >> 4) + (size_t)p.b_oh * (zz & 15);
    const size_t ooff = (size_t)p.o_ob * (zz >> 4) + (size_t)p.o_oh * (zz & 15);
    if (EPI == 8) { aoff += (size_t)chunk * 1024; boff += (size_t)chunk * 1024; }

    if (EPI == 4) ksums[tid] = p.ksum[(size_t)z * Rc + tid];

    const int steps = p.K / BK;

    auto issue = [&](int step) {
        const int k0 = step * BK;
        const u32 sb = su + (step & 1) * BLK;
        const u16* agh = p.ah + aoff + k0;
        const u16* agl = p.al + aoff + k0;
        const u16* bgh = p.bh + boff + k0;
        const u16* bgl = p.bl + boff + k0;
        #pragma unroll
        for (int j = tid; j < 512; j += 256) {
            int row = j >> 2, ch = j & 3;
            size_t gs = (size_t)(m0 + row) * p.a_st + ch * 8;
            u32 so = row * (RS * 2) + ch * 16;
            cpa16(sb + so, agh + gs);
            cpa16(sb + APL + so, agl + gs);
        }
        #pragma unroll
        for (int j = tid; j < NTILE * 4; j += 256) {
            int row = j >> 2, ch = j & 3;
            size_t gs = (size_t)(n0 + row) * p.b_st + ch * 8;
            u32 so = row * (RS * 2) + ch * 16;
            cpa16(sb + 2 * APL + so, bgh + gs);
            if (XN == 3) cpa16(sb + 2 * APL + BPL + so, bgl + gs);
        }
        asm volatile("cp.async.commit_group;" ::: "memory");
    };

    issue(0);

    float acc[MT][4][4];
    #pragma unroll
    for (int i = 0; i < MT; i++)
        #pragma unroll
        for (int j = 0; j < 4; j++)
            #pragma unroll
            for (int c = 0; c < 4; c++) acc[i][j][c] = 0.0f;
    float nacc = 0.0f;

    const u32 aoff_lane = (lane & 15) * (RS * 2) + (lane >> 4) * 16;
    const u32 boff_lane = ((lane & 7) + ((lane >> 4) << 3)) * (RS * 2) + ((lane >> 3) & 1) * 16;

    for (int i = 0; i < steps; i++) {
        asm volatile("cp.async.wait_group 0;" ::: "memory");
        __syncthreads();
        if (i + 1 < steps) issue(i + 1);

        const int buf = i & 1;
        const u32 sb = su + buf * BLK;

        if (EPI == 4 || EPI == 8) {
            int row = tid >> 1, half16 = tid & 1;
            const __nv_bfloat162* xh = (const __nv_bfloat162*)(smc + buf * BLK
                                        + row * (RS * 2) + half16 * 32);
            const __nv_bfloat162* xl = (const __nv_bfloat162*)(smc + buf * BLK + APL
                                        + row * (RS * 2) + half16 * 32);
            if (EPI == 4) {
                const float* kv = ksums + i * BK + half16 * 16;
                #pragma unroll
                for (int t = 0; t < 8; t++) {
                    float2 h2 = __bfloat1622float2(xh[t]);
                    float2 l2 = __bfloat1622float2(xl[t]);
                    nacc += (h2.x + l2.x) * kv[2 * t] + (h2.y + l2.y) * kv[2 * t + 1];
                }
            } else {
                #pragma unroll
                for (int t = 0; t < 8; t++) {
                    float2 h2 = __bfloat1622float2(xh[t]);
                    float2 l2 = __bfloat1622float2(xl[t]);
                    nacc += h2.x + l2.x + h2.y + l2.y;
                }
            }
        }

        #pragma unroll
        for (int half = 0; half < 2; half++) {
            const u32 kb = half * 32;
            u32 ahr[MT][4], alr[MT][4];
            #pragma unroll
            for (int im = 0; im < MT; im++) {
                u32 abase = sb + (wm0 + im * 16) * (RS * 2) + kb + aoff_lane;
                ldsm4(ahr[im][0], ahr[im][1], ahr[im][2], ahr[im][3], abase);
                ldsm4(alr[im][0], alr[im][1], alr[im][2], alr[im][3], abase + APL);
            }
            #pragma unroll
            for (int npair = 0; npair < 2; npair++) {
                u32 bbase = sb + 2 * APL + (wn0 + npair * 16) * (RS * 2) + kb + boff_lane;
                u32 bh0, bh1, bh2_, bh3;
                ldsm4(bh0, bh1, bh2_, bh3, bbase);
                u32 bhA[2] = { bh0, bh1 }, bhB[2] = { bh2_, bh3 };
                const int iA = npair * 2, iB = npair * 2 + 1;
                #pragma unroll
                for (int im = 0; im < MT; im++) mma16<FT>(acc[im][iA], ahr[im], bhA);
                #pragma unroll
                for (int im = 0; im < MT; im++) mma16<FT>(acc[im][iB], ahr[im], bhB);
                #pragma unroll
                for (int im = 0; im < MT; im++) mma16<FT>(acc[im][iA], alr[im], bhA);
                #pragma unroll
                for (int im = 0; im < MT; im++) mma16<FT>(acc[im][iB], alr[im], bhB);
                if (XN == 3) {
                    u32 bl0, bl1, bl2_, bl3;
                    ldsm4(bl0, bl1, bl2_, bl3, bbase + BPL);
                    u32 blA[2] = { bl0, bl1 }, blB[2] = { bl2_, bl3 };
                    #pragma unroll
                    for (int im = 0; im < MT; im++) mma16<FT>(acc[im][iA], ahr[im], blA);
                    #pragma unroll
                    for (int im = 0; im < MT; im++) mma16<FT>(acc[im][iB], ahr[im], blB);
                }
            }
        }
    }
    __syncthreads();

    if (EPI == 4 || EPI == 8) { snorm[tid] = nacc; __syncthreads(); }
    if (EPI == 1) { ksums[tid] = 0.0f; __syncthreads(); }

    // ---------------- epilogue ----------------
    const int lh = wn0 >> 6;
    #pragma unroll
    for (int im = 0; im < MT; im++) {
        const int la = wm0 + im * 16 + (lane >> 2);
        const int lb = la + 8;
        const int rA = m0 + la, rB = m0 + lb;
        float hnA = 0.0f, hnB = 0.0f, invA = 1.0f, invB = 1.0f;
        float bA = 0.0f, bB = 0.0f;
        if (EPI == 2) {
            hnA = 0.5f * p.norm[(size_t)z * Sc + rA];
            hnB = 0.5f * p.norm[(size_t)z * Sc + rB];
        }
        if (EPI == 6) {
            bA = __ldg(p.bias + rA);
            bB = __ldg(p.bias + rB);
        }
        if (EPI == 4) {
            invA = 1.0f / (snorm[2 * la] + snorm[2 * la + 1] + 1e-6f);
            invB = 1.0f / (snorm[2 * lb] + snorm[2 * lb + 1] + 1e-6f);
        }
        float sA = 0.0f, sB = 0.0f;
        #pragma unroll
        for (int in_ = 0; in_ < 4; in_++) {
            const int n = n0 + wn0 + in_ * 8 + ((lane & 3) << 1);
            float v0 = acc[im][in_][0], v1 = acc[im][in_][1];
            float v2 = acc[im][in_][2], v3 = acc[im][in_][3];
            if (EPI == 0 || EPI == 1) {
                float b0 = __ldg(p.bias + n), b1 = __ldg(p.bias + n + 1);
                v0 += b0; v1 += b1; v2 += b0; v3 += b1;
            } else if (EPI == 6) {
                v0 += bA; v1 += bA; v2 += bB; v3 += bB;
            } else if (EPI == 2) {
                v0 = __expf(v0 - hnA); v1 = __expf(v1 - hnA);
                v2 = __expf(v2 - hnB); v3 = __expf(v3 - hnB);
            } else if (EPI == 5) {
                float hn0 = 0.5f * __ldg(p.norm + (size_t)z * Sc + n);
                float hn1 = 0.5f * __ldg(p.norm + (size_t)z * Sc + n + 1);
                v0 = __expf(v0 - hn0); v1 = __expf(v1 - hn1);
                v2 = __expf(v2 - hn0); v3 = __expf(v3 - hn1);
            } else if (EPI == 4) {
                v0 *= invA; v1 *= invA; v2 *= invB; v3 *= invB;
            }
            if (EPI == 1) { sA += v0 * v0 + v1 * v1; sB += v2 * v2 + v3 * v3; }
            if (EPI == 0) {
                *(float2*)(p.o0 + ooff + (size_t)rA * p.o_st + n) = make_float2(v0, v1);
                *(float2*)(p.o0 + ooff + (size_t)rB * p.o_st + n) = make_float2(v2, v3);
            } else if (EPI == 8) {
                float* b8 = p.o0 + (((size_t)z * 4 + chunk) << 14);
                *(float2*)(b8 + (size_t)rA * 64 + n) = make_float2(v0, v1);
                *(float2*)(b8 + (size_t)rB * 64 + n) = make_float2(v2, v3);
            } else {
                u16 h0, l0, h1, l1, h2, l2, h3, l3;
                if (OUT_BF) {
                    bsplit(v0, h0, l0); bsplit(v1, h1, l1);
                    bsplit(v2, h2, l2); bsplit(v3, h3, l3);
                } else {
                    hsplit(v0, h0, l0); hsplit(v1, h1, l1);
                    hsplit(v2, h2, l2); hsplit(v3, h3, l3);
                }
                size_t oA = ooff + (size_t)rA * p.o_st + n;
                size_t oB = ooff + (size_t)rB * p.o_st + n;
                *(u32*)(p.o_hi + oA) = (u32)h0 | ((u32)h1 << 16);
                *(u32*)(p.o_lo + oA) = (u32)l0 | ((u32)l1 << 16);
                *(u32*)(p.o_hi + oB) = (u32)h2 | ((u32)h3 << 16);
                *(u32*)(p.o_lo + oB) = (u32)l2 | ((u32)l3 << 16);
            }
        }
        if (EPI == 1) {
            atomicAdd(&ksums[la * 2 + lh], sA);
            atomicAdd(&ksums[lb * 2 + lh], sB);
        }
    }

    if (EPI == 1) {
        __syncthreads();
        int row = tid >> 1, hloc = tid & 1;
        int rg = m0 + row, b = rg >> 12, s = rg & 4095;
        int head = (n0 >> 6) + hloc;
        p.nrm_out[(size_t)(b * 16 + head) * Sc + s] = ksums[tid];
    }
    if (EPI == 8) {
        if (tid < 128)
            p.nrm_out[(((size_t)z * 4 + chunk) << 8) + m0 + tid] =
                snorm[2 * tid] + snorm[2 * tid + 1];
    }
}

// ---------------- kv final reduce ----------------
__global__ void kvfinal_kernel(const float* __restrict__ kvp, const float* __restrict__ ksp,
                               u16* __restrict__ kvth, u16* __restrict__ kvtl,
                               float* __restrict__ ks)
{
    size_t idx = (size_t)blockIdx.x * 256 + threadIdx.x;
    int r = (int)(idx & 255), d = (int)((idx >> 8) & 63), bh = (int)(idx >> 14);
    float s = 0.0f;
    #pragma unroll
    for (int c = 0; c < 4; c++)
        s += kvp[(((size_t)bh * 4 + c) << 14) + (r << 6) + d];
    u16 hv, lv; bsplit(s, hv, lv);
    size_t o = ((size_t)bh << 14) + (d << 8) + r;
    kvth[o] = hv; kvtl[o] = lv;
    if (idx < (size_t)64 * 256) {
        int bh2 = (int)(idx >> 8), r2 = (int)(idx & 255);
        float t = 0.0f;
        #pragma unroll
        for (int c = 0; c < 4; c++) t += ksp[((size_t)(bh2 * 4 + c) << 8) + r2];
        ks[idx] = t;
    }
}

// ---------------- launch ----------------
extern "C" void kernel_launch(void* const* d_in, const int* in_sizes, int n_in,
                              void* d_out, int out_size)
{
    (void)in_sizes; (void)n_in; (void)out_size;
    const float* x  = (const float*)d_in[0];
    const float* wq = (const float*)d_in[1];
    const float* bq = (const float*)d_in[2];
    const float* wk = (const float*)d_in[3];
    const float* bk = (const float*)d_in[4];
    const float* wv = (const float*)d_in[5];
    const float* bv = (const float*)d_in[6];
    const float* wo = (const float*)d_in[7];
    const float* bo = (const float*)d_in[8];
    const float* rf = (const float*)d_in[9];
    float* out = (float*)d_out;

    u16 *xh, *xl, *wqh, *wql, *wkh, *wkl, *wvh, *wvl, *woh, *wol;
    u16 *rfh, *rfl, *qh, *ql, *kh, *kl, *vth, *vtl, *qph, *qpl;
    u16 *kpth, *kptl, *kvth, *kvtl, *ath, *atl;
    float *nq, *nk, *kvp, *ksp, *ksum;
    cudaGetSymbolAddress((void**)&xh,  g_xh);   cudaGetSymbolAddress((void**)&xl,  g_xl);
    cudaGetSymbolAddress((void**)&wqh, g_wqh);  cudaGetSymbolAddress((void**)&wql, g_wql);
    cudaGetSymbolAddress((void**)&wkh, g_wkh);  cudaGetSymbolAddress((void**)&wkl, g_wkl);
    cudaGetSymbolAddress((void**)&wvh, g_wvh);  cudaGetSymbolAddress((void**)&wvl, g_wvl);
    cudaGetSymbolAddress((void**)&woh, g_woh);  cudaGetSymbolAddress((void**)&wol, g_wol);
    cudaGetSymbolAddress((void**)&rfh, g_rfh);  cudaGetSymbolAddress((void**)&rfl, g_rfl);
    cudaGetSymbolAddress((void**)&qh,  g_qh);   cudaGetSymbolAddress((void**)&ql,  g_ql);
    cudaGetSymbolAddress((void**)&kh,  g_kh);   cudaGetSymbolAddress((void**)&kl,  g_kl);
    cudaGetSymbolAddress((void**)&vth, g_vth);  cudaGetSymbolAddress((void**)&vtl, g_vtl);
    cudaGetSymbolAddress((void**)&nq,  g_nq);   cudaGetSymbolAddress((void**)&nk,  g_nk);
    cudaGetSymbolAddress((void**)&qph, g_qph);  cudaGetSymbolAddress((void**)&qpl, g_qpl);
    cudaGetSymbolAddress((void**)&kpth, g_kpth);cudaGetSymbolAddress((void**)&kptl, g_kptl);
    cudaGetSymbolAddress((void**)&kvp, g_kvp);  cudaGetSymbolAddress((void**)&ksp, g_ksp);
    cudaGetSymbolAddress((void**)&kvth, g_kvth);cudaGetSymbolAddress((void**)&kvtl, g_kvtl);
    cudaGetSymbolAddress((void**)&ksum, g_ksum);
    cudaGetSymbolAddress((void**)&ath, g_ath);  cudaGetSymbolAddress((void**)&atl, g_atl);

    const int SM128 = 2 * (2 * 128 * RS * 2 + 2 * 128 * RS * 2) + 2048;  // 83968
    const int SM64  = 2 * (2 * 128 * RS * 2 + 2 * 64 * RS * 2) + 2048;   // 63488
    cudaFuncSetAttribute(tgemm<128, 0, 1, 2>, cudaFuncAttributeMaxDynamicSharedMemorySize, SM128);
    cudaFuncSetAttribute(tgemm<128, 1, 1, 3>, cudaFuncAttributeMaxDynamicSharedMemorySize, SM128);
    cudaFuncSetAttribute(tgemm<128, 2, 1, 3>, cudaFuncAttributeMaxDynamicSharedMemorySize, SM128);
    cudaFuncSetAttribute(tgemm<128, 5, 1, 3>, cudaFuncAttributeMaxDynamicSharedMemorySize, SM128);
    cudaFuncSetAttribute(tgemm<128, 6, 1, 2>, cudaFuncAttributeMaxDynamicSharedMemorySize, SM128);
    cudaFuncSetAttribute(tgemm<64, 4, 0, 3>,  cudaFuncAttributeMaxDynamicSharedMemorySize, SM64);
    cudaFuncSetAttribute(tgemm<64, 8, 0, 3>,  cudaFuncAttributeMaxDynamicSharedMemorySize, SM64);

    // fused splits + rf transpose (one launch)
    SplitJobs sj = { (const float4*)x, (const float4*)wq, (const float4*)wk,
                     (const float4*)wv, (const float4*)wo, rf,
                     xh, xl, wqh, wql, wkh, wkl, wvh, wvl, woh, wol, rfh, rfl };
    split_all_kernel<<<5120, 256>>>(sj);

    // FUSED Q+K projections (M=16384, N=1024, K=1024), fp16x3, z selects Q/K
    dim3 gqk(Dc / 128, Mtot / 128, 2);
    TGP pqk = {};
    pqk.ah = xh; pqk.al = xl; pqk.a_ob = 0; pqk.a_oh = 0; pqk.a_st = Dc;
    pqk.b_ob = 0; pqk.b_oh = 0; pqk.b_st = Dc; pqk.K = Dc;
    pqk.o_ob = 0; pqk.o_oh = 0; pqk.o_st = Dc;
    pqk.bh = wqh; pqk.bl = wql; pqk.bias = bq;
    pqk.o_hi = qh; pqk.o_lo = ql; pqk.nrm_out = nq;
    pqk.bh2 = wkh; pqk.bl2 = wkl; pqk.bias2 = bk;
    pqk.o_hi2 = kh; pqk.o_lo2 = kl; pqk.nrm_out2 = nk;
    tgemm<128, 1, 1, 3><<<gqk, 256, SM128>>>(pqk);

    // V projection TRANSPOSED: C[d, m] = wv * x^T, fp16x2 -> bf16 split
    dim3 gvt(Mtot / 128, Dc / 128, 1);
    TGP pv = {};
    pv.ah = wvh; pv.al = wvl; pv.a_ob = 0; pv.a_oh = 0; pv.a_st = Dc;
    pv.bh = xh;  pv.bl = xl;  pv.b_ob = 0; pv.b_oh = 0; pv.b_st = Dc;
    pv.K = Dc; pv.bias = bv;
    pv.o_hi = vth; pv.o_lo = vtl; pv.o_ob = 0; pv.o_oh = 0; pv.o_st = Mtot;
    tgemm<128, 6, 1, 2><<<gvt, 256, SM128>>>(pv);

    // feature-Q (per bh: M=4096 s, N=256 r, K=64), fp16x3 -> bf16 split
    dim3 gfeat(Rc / 128, Sc / 128, Bc * Hc);
    TGP pfq = {};
    pfq.ah = qh; pfq.al = ql;
    pfq.a_ob = (long long)Sc * Dc; pfq.a_oh = HDc; pfq.a_st = Dc;
    pfq.bh = rfh; pfq.bl = rfl;
    pfq.b_ob = 0; pfq.b_oh = (long long)Rc * HDc; pfq.b_st = HDc;
    pfq.K = HDc; pfq.norm = nq;
    pfq.o_hi = qph; pfq.o_lo = qpl;
    pfq.o_ob = (long long)16 * Sc * Rc; pfq.o_oh = (long long)Sc * Rc; pfq.o_st = Rc;
    tgemm<128, 2, 1, 3><<<gfeat, 256, SM128>>>(pfq);

    // feature-K TRANSPOSED (per bh: M=256 r, N=4096 s, K=64), fp16x3 -> bf16 split
    dim3 gfkt(Sc / 128, Rc / 128, Bc * Hc);
    TGP pfk = {};
    pfk.ah = rfh; pfk.al = rfl;
    pfk.a_ob = 0; pfk.a_oh = (long long)Rc * HDc; pfk.a_st = HDc;
    pfk.bh = kh; pfk.bl = kl;
    pfk.b_ob = (long long)Sc * Dc; pfk.b_oh = HDc; pfk.b_st = Dc;
    pfk.K = HDc; pfk.norm = nk;
    pfk.o_hi = kpth; pfk.o_lo = kptl;
    pfk.o_ob = (long long)16 * Rc * Sc; pfk.o_oh = (long long)Rc * Sc; pfk.o_st = Sc;
    tgemm<128, 5, 1, 3><<<gfkt, 256, SM128>>>(pfk);

    // kv aggregation GEMM (per bh: M=256 r, N=64 d, K=4096 s, split-K x4), bf16x3
    dim3 gkv(4, Rc / 128, Bc * Hc);
    TGP pkv = {};
    pkv.ah = kpth; pkv.al = kptl;
    pkv.a_ob = (long long)16 * Rc * Sc; pkv.a_oh = (long long)Rc * Sc; pkv.a_st = Sc;
    pkv.bh = vth; pkv.bl = vtl;
    pkv.b_ob = 4096; pkv.b_oh = (long long)64 * Mtot; pkv.b_st = Mtot;
    pkv.K = 1024;
    pkv.o0 = kvp; pkv.nrm_out = ksp;
    tgemm<64, 8, 0, 3><<<gkv, 256, SM64>>>(pkv);

    kvfinal_kernel<<<4096, 256>>>(kvp, ksp, kvth, kvtl, ksum);

    // attention readout (per bh: M=4096 s, N=64 d, K=256 r), bf16x3 -> fp16 split
    dim3 gat(1, Sc / 128, Bc * Hc);
    TGP pa = {};
    pa.ah = qph; pa.al = qpl;
    pa.a_ob = (long long)16 * Sc * Rc; pa.a_oh = (long long)Sc * Rc; pa.a_st = Rc;
    pa.bh = kvth; pa.bl = kvtl;
    pa.b_ob = (long long)16 * HDc * Rc; pa.b_oh = (long long)HDc * Rc; pa.b_st = Rc;
    pa.K = Rc; pa.ksum = ksum;
    pa.o_hi = ath; pa.o_lo = atl;
    pa.o_ob = (long long)Sc * Dc; pa.o_oh = HDc; pa.o_st = Dc;
    tgemm<64, 4, 0, 3><<<gat, 256, SM64>>>(pa);

    // output projection, fp16x2 -> f32
    TGP po = {};
    po.ah = ath; po.al = atl; po.a_ob = 0; po.a_oh = 0; po.a_st = Dc;
    po.bh = woh; po.bl = wol; po.b_ob = 0; po.b_oh = 0; po.b_st = Dc;
    po.K = Dc; po.bias = bo; po.o0 = out;
    po.o_ob = 0; po.o_oh = 0; po.o_st = Dc;
    dim3 gproj(Dc / 128, Mtot / 128, 1);
    tgemm<128, 0, 1, 2><<<gproj, 256, SM128>>>(po);
}

// round 16
// speedup vs baseline: 1.3456x; 1.0092x over previous
#include <cuda_runtime.h>
#include <cuda_bf16.h>
#include <cuda_fp16.h>
#include <cstdint>
#include <math.h>

#define Bc 4
#define Sc 4096
#define Dc 1024
#define Hc 16
#define Rc 256
#define HDc 64
#define Mtot (Bc * Sc)
#define BK 32
#define RS 40      // smem row stride in u16 (32 data + 8 pad = 80B)

typedef unsigned short u16;
typedef uint32_t u32;

// ---------------- scratch (device globals) ----------------
__device__ u16 g_xh[(size_t)Mtot * Dc],  g_xl[(size_t)Mtot * Dc];
__device__ u16 g_wqh[Dc * Dc], g_wql[Dc * Dc];
__device__ u16 g_wkh[Dc * Dc], g_wkl[Dc * Dc];
__device__ u16 g_wvh[Dc * Dc], g_wvl[Dc * Dc];
__device__ u16 g_woh[Dc * Dc], g_wol[Dc * Dc];
__device__ u16 g_rfh[(size_t)Hc * Rc * HDc], g_rfl[(size_t)Hc * Rc * HDc];
__device__ u16 g_qh[(size_t)Mtot * Dc],  g_ql[(size_t)Mtot * Dc];
__device__ u16 g_kh[(size_t)Mtot * Dc],  g_kl[(size_t)Mtot * Dc];
__device__ u16 g_ath[(size_t)Mtot * Dc], g_atl[(size_t)Mtot * Dc];
// bf16 split planes (exp outputs exceed fp16 range)
__device__ u16 g_vth[(size_t)Mtot * Dc], g_vtl[(size_t)Mtot * Dc];   // V^T [d][m]
__device__ u16 g_qph[(size_t)Bc * Hc * Sc * Rc], g_qpl[(size_t)Bc * Hc * Sc * Rc];
__device__ u16 g_kpth[(size_t)Bc * Hc * Rc * Sc], g_kptl[(size_t)Bc * Hc * Rc * Sc];
__device__ u16 g_kvth[(size_t)Bc * Hc * HDc * Rc], g_kvtl[(size_t)Bc * Hc * HDc * Rc];
// fp32
__device__ float g_nq[(size_t)Bc * Hc * Sc], g_nk[(size_t)Bc * Hc * Sc];
__device__ float g_kvp[(size_t)Bc * Hc * 4 * Rc * HDc];
__device__ float g_ksp[(size_t)Bc * Hc * 4 * Rc];
__device__ float g_ksum[(size_t)Bc * Hc * Rc];

// ---------------- helpers ----------------
__device__ __forceinline__ u32 smem_u32(const void* p) {
    u32 a;
    asm("{ .reg .u64 t; cvta.to.shared.u64 t, %1; cvt.u32.u64 %0, t; }" : "=r"(a) : "l"(p));
    return a;
}
__device__ __forceinline__ void hsplit(float a, u16& h, u16& l) {
    __half hb = __float2half_rn(a);
    float lf = a - __half2float(hb);
    __half lb = __float2half_rn(lf);
    h = __half_as_ushort(hb);
    l = __half_as_ushort(lb);
}
__device__ __forceinline__ void bsplit(float a, u16& h, u16& l) {
    __nv_bfloat16 hb = __float2bfloat16_rn(a);
    float lf = a - __bfloat162float(hb);
    __nv_bfloat16 lb = __float2bfloat16_rn(lf);
    h = __bfloat16_as_ushort(hb);
    l = __bfloat16_as_ushort(lb);
}
// packed bf16 split of (v0, v1): hp = {hi=bf16(v1), lo=bf16(v0)}, lp likewise for residuals
__device__ __forceinline__ void bsplit2(float v0, float v1, u32& hp, u32& lp) {
    asm("cvt.rn.bf16x2.f32 %0, %1, %2;" : "=r"(hp) : "f"(v1), "f"(v0));
    float h0f = __uint_as_float(hp << 16);
    float h1f = __uint_as_float(hp & 0xffff0000u);
    asm("cvt.rn.bf16x2.f32 %0, %1, %2;" : "=r"(lp) : "f"(v1 - h1f), "f"(v0 - h0f));
}
__device__ __forceinline__ void cpa16(u32 dst, const void* src) {
    asm volatile("cp.async.cg.shared.global [%0], [%1], 16;"
                 :: "r"(dst), "l"(__cvta_generic_to_global(src)) : "memory");
}
__device__ __forceinline__ void mma_bf16(float* c, const u32* A, const u32* B) {
    asm volatile(
        "mma.sync.aligned.m16n8k16.row.col.f32.bf16.bf16.f32 "
        "{%0,%1,%2,%3}, {%4,%5,%6,%7}, {%8,%9}, {%0,%1,%2,%3};"
        : "+f"(c[0]), "+f"(c[1]), "+f"(c[2]), "+f"(c[3])
        : "r"(A[0]), "r"(A[1]), "r"(A[2]), "r"(A[3]), "r"(B[0]), "r"(B[1]));
}
__device__ __forceinline__ void mma_f16(float* c, const u32* A, const u32* B) {
    asm volatile(
        "mma.sync.aligned.m16n8k16.row.col.f32.f16.f16.f32 "
        "{%0,%1,%2,%3}, {%4,%5,%6,%7}, {%8,%9}, {%0,%1,%2,%3};"
        : "+f"(c[0]), "+f"(c[1]), "+f"(c[2]), "+f"(c[3])
        : "r"(A[0]), "r"(A[1]), "r"(A[2]), "r"(A[3]), "r"(B[0]), "r"(B[1]));
}
template<int FT>
__device__ __forceinline__ void mma16(float* c, const u32* A, const u32* B) {
    if (FT == 0) mma_bf16(c, A, B);
    else         mma_f16(c, A, B);
}
__device__ __forceinline__ void ldsm4(u32& r0, u32& r1, u32& r2, u32& r3, u32 addr) {
    asm volatile("ldmatrix.sync.aligned.m8n8.x4.shared.b16 {%0,%1,%2,%3}, [%4];"
                 : "=r"(r0), "=r"(r1), "=r"(r2), "=r"(r3) : "r"(addr));
}

// ---------------- fused split: x + 4 weights + rf-transpose in ONE launch ----------
struct SplitJobs {
    const float4 *x, *wq, *wk, *wv, *wo;
    const float* rf;
    u16 *xh, *xl, *wqh, *wql, *wkh, *wkl, *wvh, *wvl, *woh, *wol, *rfh, *rfl;
};
__global__ void split_all_kernel(SplitJobs j)
{
    int bx = blockIdx.x;
    if (bx >= 4096) {
        int idx = (bx - 4096) * 256 + threadIdx.x;
        if (idx < Hc * Rc * HDc) {
            int d = idx & 63, r = (idx >> 6) & 255, h = idx >> 14;
            float a = j.rf[((size_t)(h * HDc + d)) * Rc + r];
            u16 hv, lv; hsplit(a, hv, lv);
            j.rfh[idx] = hv; j.rfl[idx] = lv;
        }
        return;
    }
    const float4* src;
    u16 *hi, *lo;
    int base, n4;
    if (bx < 2048)      { src = j.x;  hi = j.xh;  lo = j.xl;  base = bx;        n4 = Mtot * Dc / 4; }
    else if (bx < 2560) { src = j.wq; hi = j.wqh; lo = j.wql; base = bx - 2048; n4 = Dc * Dc / 4; }
    else if (bx < 3072) { src = j.wk; hi = j.wkh; lo = j.wkl; base = bx - 2560; n4 = Dc * Dc / 4; }
    else if (bx < 3584) { src = j.wv; hi = j.wvh; lo = j.wvl; base = bx - 3072; n4 = Dc * Dc / 4; }
    else                { src = j.wo; hi = j.woh; lo = j.wol; base = bx - 3584; n4 = Dc * Dc / 4; }
    const int stride = (bx < 2048) ? 2048 * 256 : 512 * 256;
    for (int i = base * 256 + threadIdx.x; i < n4; i += stride) {
        float4 a = src[i];
        ushort4 hv, lv;
        hsplit(a.x, hv.x, lv.x); hsplit(a.y, hv.y, lv.y);
        hsplit(a.z, hv.z, lv.z); hsplit(a.w, hv.w, lv.w);
        *(ushort4*)(hi + (size_t)i * 4) = hv;
        *(ushort4*)(lo + (size_t)i * 4) = lv;
    }
}

// ---------------- split-precision tensor GEMM engine ----------------
// C[128 x NTILE] per CTA; C = A * B^T (fp32 accum).
// FT: 0=bf16 operands, 1=fp16.  XN: 3 = hh+lh+hl, 2 = hh+lh.
// EPI: 0 +bias(col)->f32 | 1 +bias(col)->fp16 split + per-head rownorm (z picks Q/K set)
//      4 normalize by in-loop (A.ksum)->fp16 split | 6 +bias(row)->bf16 split
//      7 fused feature maps: z<64 Q-mode exp(v-0.5*norm[row]); z>=64 K-mode
//        exp(v-0.5*norm[col]); second param set used for K-mode.  -> bf16 split
//      8 split-K partial: raw f32 out + in-loop A-rowsum partial (chunk=blockIdx.x)
struct TGP {
    const u16 *ah, *al, *bh, *bl;
    long long a_ob, a_oh, b_ob, b_oh, o_ob, o_oh;
    int a_st, b_st, o_st, K;
    const float *bias, *norm, *ksum;
    float* o0;
    u16 *o_hi, *o_lo;
    float* nrm_out;
    // second param set (EPI 1 fused Q/K; EPI 7 K-mode)
    const u16 *ah2, *al2, *bh2, *bl2;
    long long a_ob2, a_oh2, b_ob2, b_oh2, o_ob2, o_oh2;
    int a_st2, b_st2, o_st2;
    const float *bias2, *norm2;
    u16 *o_hi2, *o_lo2;
    float* nrm_out2;
};

template<int NTILE, int EPI, int FT, int XN>
__global__ void __launch_bounds__(256, (NTILE == 64) ? 3 : 2) tgemm(TGP p)
{
    extern __shared__ char smc[];
    const int tid = threadIdx.x, lane = tid & 31, wid = tid >> 5;
    const int z = blockIdx.z;
    const int chunk = (EPI == 8) ? blockIdx.x : 0;
    const int mode7 = (EPI == 7) ? (z >> 6) : 0;

    int m0, n0;
    if (EPI == 7) {
        if (mode7 == 0) { m0 = blockIdx.x << 7; n0 = blockIdx.y << 7; }
        else            { m0 = blockIdx.y << 7; n0 = blockIdx.x << 7; }
    } else {
        m0 = blockIdx.y << 7;
        n0 = (EPI == 8) ? 0 : blockIdx.x * NTILE;
    }

    if (EPI == 1 && z == 1) {
        p.bh = p.bh2; p.bl = p.bl2; p.bias = p.bias2;
        p.o_hi = p.o_hi2; p.o_lo = p.o_lo2; p.nrm_out = p.nrm_out2;
    }
    if (EPI == 7 && mode7 == 1) {
        p.ah = p.ah2; p.al = p.al2; p.bh = p.bh2; p.bl = p.bl2;
        p.a_ob = p.a_ob2; p.a_oh = p.a_oh2; p.a_st = p.a_st2;
        p.b_ob = p.b_ob2; p.b_oh = p.b_oh2; p.b_st = p.b_st2;
        p.o_ob = p.o_ob2; p.o_oh = p.o_oh2; p.o_st = p.o_st2;
        p.norm = p.norm2; p.o_hi = p.o_hi2; p.o_lo = p.o_lo2;
    }

    constexpr int MT = (NTILE == 128) ? 4 : 2;
    constexpr bool OUT_BF = (EPI == 6 || EPI == 7);
    const int wm0 = (NTILE == 128) ? ((wid & 1) << 6) : ((wid & 3) << 5);
    const int wn0 = (NTILE == 128) ? ((wid >> 1) << 5) : ((wid >> 2) << 5);

    constexpr int APL = 128 * RS * 2;
    constexpr int BPL = NTILE * RS * 2;
    constexpr int BLK = 2 * APL + 2 * BPL;
    const u32 su = smem_u32(smc);
    float* const ksums = (float*)(smc + 2 * BLK);
    float* const snorm = ksums + 256;

    const int zz = (EPI == 1) ? 0 : ((EPI == 7) ? (z & 63) : z);
    size_t aoff = (size_t)p.a_ob * (zz >> 4) + (size_t)p.a_oh * (zz & 15);
    size_t boff = (size_t)p.b_ob * (zz >> 4) + (size_t)p.b_oh * (zz & 15);
    const size_t ooff = (size_t)p.o_ob * (zz >> 4) + (size_t)p.o_oh * (zz & 15);
    if (EPI == 8) { aoff += (size_t)chunk * 1024; boff += (size_t)chunk * 1024; }

    if (EPI == 4) ksums[tid] = p.ksum[(size_t)z * Rc + tid];

    const int steps = p.K / BK;

    auto issue = [&](int step) {
        const int k0 = step * BK;
        const u32 sb = su + (step & 1) * BLK;
        const u16* agh = p.ah + aoff + k0;
        const u16* agl = p.al + aoff + k0;
        const u16* bgh = p.bh + boff + k0;
        const u16* bgl = p.bl + boff + k0;
        #pragma unroll
        for (int j = tid; j < 512; j += 256) {
            int row = j >> 2, ch = j & 3;
            size_t gs = (size_t)(m0 + row) * p.a_st + ch * 8;
            u32 so = row * (RS * 2) + ch * 16;
            cpa16(sb + so, agh + gs);
            cpa16(sb + APL + so, agl + gs);
        }
        #pragma unroll
        for (int j = tid; j < NTILE * 4; j += 256) {
            int row = j >> 2, ch = j & 3;
            size_t gs = (size_t)(n0 + row) * p.b_st + ch * 8;
            u32 so = row * (RS * 2) + ch * 16;
            cpa16(sb + 2 * APL + so, bgh + gs);
            if (XN == 3) cpa16(sb + 2 * APL + BPL + so, bgl + gs);
        }
        asm volatile("cp.async.commit_group;" ::: "memory");
    };

    issue(0);

    float acc[MT][4][4];
    #pragma unroll
    for (int i = 0; i < MT; i++)
        #pragma unroll
        for (int j = 0; j < 4; j++)
            #pragma unroll
            for (int c = 0; c < 4; c++) acc[i][j][c] = 0.0f;
    float nacc = 0.0f;

    const u32 aoff_lane = (lane & 15) * (RS * 2) + (lane >> 4) * 16;
    const u32 boff_lane = ((lane & 7) + ((lane >> 4) << 3)) * (RS * 2) + ((lane >> 3) & 1) * 16;

    for (int i = 0; i < steps; i++) {
        asm volatile("cp.async.wait_group 0;" ::: "memory");
        __syncthreads();
        if (i + 1 < steps) issue(i + 1);

        const int buf = i & 1;
        const u32 sb = su + buf * BLK;

        if (EPI == 4 || EPI == 8) {
            int row = tid >> 1, half16 = tid & 1;
            const __nv_bfloat162* xh = (const __nv_bfloat162*)(smc + buf * BLK
                                        + row * (RS * 2) + half16 * 32);
            const __nv_bfloat162* xl = (const __nv_bfloat162*)(smc + buf * BLK + APL
                                        + row * (RS * 2) + half16 * 32);
            if (EPI == 4) {
                const float* kv = ksums + i * BK + half16 * 16;
                #pragma unroll
                for (int t = 0; t < 8; t++) {
                    float2 h2 = __bfloat1622float2(xh[t]);
                    float2 l2 = __bfloat1622float2(xl[t]);
                    nacc += (h2.x + l2.x) * kv[2 * t] + (h2.y + l2.y) * kv[2 * t + 1];
                }
            } else {
                #pragma unroll
                for (int t = 0; t < 8; t++) {
                    float2 h2 = __bfloat1622float2(xh[t]);
                    float2 l2 = __bfloat1622float2(xl[t]);
                    nacc += h2.x + l2.x + h2.y + l2.y;
                }
            }
        }

        #pragma unroll
        for (int half = 0; half < 2; half++) {
            const u32 kb = half * 32;
            u32 ahr[MT][4], alr[MT][4];
            #pragma unroll
            for (int im = 0; im < MT; im++) {
                u32 abase = sb + (wm0 + im * 16) * (RS * 2) + kb + aoff_lane;
                ldsm4(ahr[im][0], ahr[im][1], ahr[im][2], ahr[im][3], abase);
                ldsm4(alr[im][0], alr[im][1], alr[im][2], alr[im][3], abase + APL);
            }
            #pragma unroll
            for (int npair = 0; npair < 2; npair++) {
                u32 bbase = sb + 2 * APL + (wn0 + npair * 16) * (RS * 2) + kb + boff_lane;
                u32 bh0, bh1, bh2_, bh3;
                ldsm4(bh0, bh1, bh2_, bh3, bbase);
                u32 bhA[2] = { bh0, bh1 }, bhB[2] = { bh2_, bh3 };
                const int iA = npair * 2, iB = npair * 2 + 1;
                #pragma unroll
                for (int im = 0; im < MT; im++) mma16<FT>(acc[im][iA], ahr[im], bhA);
                #pragma unroll
                for (int im = 0; im < MT; im++) mma16<FT>(acc[im][iB], ahr[im], bhB);
                #pragma unroll
                for (int im = 0; im < MT; im++) mma16<FT>(acc[im][iA], alr[im], bhA);
                #pragma unroll
                for (int im = 0; im < MT; im++) mma16<FT>(acc[im][iB], alr[im], bhB);
                if (XN == 3) {
                    u32 bl0, bl1, bl2_, bl3;
                    ldsm4(bl0, bl1, bl2_, bl3, bbase + BPL);
                    u32 blA[2] = { bl0, bl1 }, blB[2] = { bl2_, bl3 };
                    #pragma unroll
                    for (int im = 0; im < MT; im++) mma16<FT>(acc[im][iA], ahr[im], blA);
                    #pragma unroll
                    for (int im = 0; im < MT; im++) mma16<FT>(acc[im][iB], ahr[im], blB);
                }
            }
        }
    }
    __syncthreads();

    if (EPI == 4 || EPI == 8) { snorm[tid] = nacc; __syncthreads(); }
    if (EPI == 1) { ksums[tid] = 0.0f; __syncthreads(); }

    // ---------------- epilogue ----------------
    const int lh = wn0 >> 6;
    #pragma unroll
    for (int im = 0; im < MT; im++) {
        const int la = wm0 + im * 16 + (lane >> 2);
        const int lb = la + 8;
        const int rA = m0 + la, rB = m0 + lb;
        float hnA = 0.0f, hnB = 0.0f, invA = 1.0f, invB = 1.0f;
        float bA = 0.0f, bB = 0.0f;
        if (EPI == 7 && mode7 == 0) {
            hnA = 0.5f * p.norm[(size_t)zz * Sc + rA];
            hnB = 0.5f * p.norm[(size_t)zz * Sc + rB];
        }
        if (EPI == 6) {
            bA = __ldg(p.bias + rA);
            bB = __ldg(p.bias + rB);
        }
        if (EPI == 4) {
            invA = 1.0f / (snorm[2 * la] + snorm[2 * la + 1] + 1e-6f);
            invB = 1.0f / (snorm[2 * lb] + snorm[2 * lb + 1] + 1e-6f);
        }
        float sA = 0.0f, sB = 0.0f;
        #pragma unroll
        for (int in_ = 0; in_ < 4; in_++) {
            const int n = n0 + wn0 + in_ * 8 + ((lane & 3) << 1);
            float v0 = acc[im][in_][0], v1 = acc[im][in_][1];
            float v2 = acc[im][in_][2], v3 = acc[im][in_][3];
            if (EPI == 0 || EPI == 1) {
                float b0 = __ldg(p.bias + n), b1 = __ldg(p.bias + n + 1);
                v0 += b0; v1 += b1; v2 += b0; v3 += b1;
            } else if (EPI == 6) {
                v0 += bA; v1 += bA; v2 += bB; v3 += bB;
            } else if (EPI == 7) {
                if (mode7 == 0) {
                    v0 = __expf(v0 - hnA); v1 = __expf(v1 - hnA);
                    v2 = __expf(v2 - hnB); v3 = __expf(v3 - hnB);
                } else {
                    float hn0 = 0.5f * __ldg(p.norm + (size_t)zz * Sc + n);
                    float hn1 = 0.5f * __ldg(p.norm + (size_t)zz * Sc + n + 1);
                    v0 = __expf(v0 - hn0); v1 = __expf(v1 - hn1);
                    v2 = __expf(v2 - hn0); v3 = __expf(v3 - hn1);
                }
            } else if (EPI == 4) {
                v0 *= invA; v1 *= invA; v2 *= invB; v3 *= invB;
            }
            if (EPI == 1) { sA += v0 * v0 + v1 * v1; sB += v2 * v2 + v3 * v3; }
            if (EPI == 0) {
                *(float2*)(p.o0 + ooff + (size_t)rA * p.o_st + n) = make_float2(v0, v1);
                *(float2*)(p.o0 + ooff + (size_t)rB * p.o_st + n) = make_float2(v2, v3);
            } else if (EPI == 8) {
                float* b8 = p.o0 + (((size_t)z * 4 + chunk) << 14);
                *(float2*)(b8 + (size_t)rA * 64 + n) = make_float2(v0, v1);
                *(float2*)(b8 + (size_t)rB * 64 + n) = make_float2(v2, v3);
            } else {
                size_t oA = ooff + (size_t)rA * p.o_st + n;
                size_t oB = ooff + (size_t)rB * p.o_st + n;
                if (OUT_BF) {
                    u32 hpA, lpA, hpB, lpB;
                    bsplit2(v0, v1, hpA, lpA);
                    bsplit2(v2, v3, hpB, lpB);
                    *(u32*)(p.o_hi + oA) = hpA; *(u32*)(p.o_lo + oA) = lpA;
                    *(u32*)(p.o_hi + oB) = hpB; *(u32*)(p.o_lo + oB) = lpB;
                } else {
                    u16 h0, l0, h1, l1, h2, l2, h3, l3;
                    hsplit(v0, h0, l0); hsplit(v1, h1, l1);
                    hsplit(v2, h2, l2); hsplit(v3, h3, l3);
                    *(u32*)(p.o_hi + oA) = (u32)h0 | ((u32)h1 << 16);
                    *(u32*)(p.o_lo + oA) = (u32)l0 | ((u32)l1 << 16);
                    *(u32*)(p.o_hi + oB) = (u32)h2 | ((u32)h3 << 16);
                    *(u32*)(p.o_lo + oB) = (u32)l2 | ((u32)l3 << 16);
                }
            }
        }
        if (EPI == 1) {
            atomicAdd(&ksums[la * 2 + lh], sA);
            atomicAdd(&ksums[lb * 2 + lh], sB);
        }
    }

    if (EPI == 1) {
        __syncthreads();
        int row = tid >> 1, hloc = tid & 1;
        int rg = m0 + row, b = rg >> 12, s = rg & 4095;
        int head = (n0 >> 6) + hloc;
        p.nrm_out[(size_t)(b * 16 + head) * Sc + s] = ksums[tid];
    }
    if (EPI == 8) {
        if (tid < 128)
            p.nrm_out[(((size_t)z * 4 + chunk) << 8) + m0 + tid] =
                snorm[2 * tid] + snorm[2 * tid + 1];
    }
}

// ---------------- kv final reduce ----------------
__global__ void kvfinal_kernel(const float* __restrict__ kvp, const float* __restrict__ ksp,
                               u16* __restrict__ kvth, u16* __restrict__ kvtl,
                               float* __restrict__ ks)
{
    size_t idx = (size_t)blockIdx.x * 256 + threadIdx.x;
    int r = (int)(idx & 255), d = (int)((idx >> 8) & 63), bh = (int)(idx >> 14);
    float s = 0.0f;
    #pragma unroll
    for (int c = 0; c < 4; c++)
        s += kvp[(((size_t)bh * 4 + c) << 14) + (r << 6) + d];
    u16 hv, lv; bsplit(s, hv, lv);
    size_t o = ((size_t)bh << 14) + (d << 8) + r;
    kvth[o] = hv; kvtl[o] = lv;
    if (idx < (size_t)64 * 256) {
        int bh2 = (int)(idx >> 8), r2 = (int)(idx & 255);
        float t = 0.0f;
        #pragma unroll
        for (int c = 0; c < 4; c++) t += ksp[((size_t)(bh2 * 4 + c) << 8) + r2];
        ks[idx] = t;
    }
}

// ---------------- launch ----------------
extern "C" void kernel_launch(void* const* d_in, const int* in_sizes, int n_in,
                              void* d_out, int out_size)
{
    (void)in_sizes; (void)n_in; (void)out_size;
    const float* x  = (const float*)d_in[0];
    const float* wq = (const float*)d_in[1];
    const float* bq = (const float*)d_in[2];
    const float* wk = (const float*)d_in[3];
    const float* bk = (const float*)d_in[4];
    const float* wv = (const float*)d_in[5];
    const float* bv = (const float*)d_in[6];
    const float* wo = (const float*)d_in[7];
    const float* bo = (const float*)d_in[8];
    const float* rf = (const float*)d_in[9];
    float* out = (float*)d_out;

    u16 *xh, *xl, *wqh, *wql, *wkh, *wkl, *wvh, *wvl, *woh, *wol;
    u16 *rfh, *rfl, *qh, *ql, *kh, *kl, *vth, *vtl, *qph, *qpl;
    u16 *kpth, *kptl, *kvth, *kvtl, *ath, *atl;
    float *nq, *nk, *kvp, *ksp, *ksum;
    cudaGetSymbolAddress((void**)&xh,  g_xh);   cudaGetSymbolAddress((void**)&xl,  g_xl);
    cudaGetSymbolAddress((void**)&wqh, g_wqh);  cudaGetSymbolAddress((void**)&wql, g_wql);
    cudaGetSymbolAddress((void**)&wkh, g_wkh);  cudaGetSymbolAddress((void**)&wkl, g_wkl);
    cudaGetSymbolAddress((void**)&wvh, g_wvh);  cudaGetSymbolAddress((void**)&wvl, g_wvl);
    cudaGetSymbolAddress((void**)&woh, g_woh);  cudaGetSymbolAddress((void**)&wol, g_wol);
    cudaGetSymbolAddress((void**)&rfh, g_rfh);  cudaGetSymbolAddress((void**)&rfl, g_rfl);
    cudaGetSymbolAddress((void**)&qh,  g_qh);   cudaGetSymbolAddress((void**)&ql,  g_ql);
    cudaGetSymbolAddress((void**)&kh,  g_kh);   cudaGetSymbolAddress((void**)&kl,  g_kl);
    cudaGetSymbolAddress((void**)&vth, g_vth);  cudaGetSymbolAddress((void**)&vtl, g_vtl);
    cudaGetSymbolAddress((void**)&nq,  g_nq);   cudaGetSymbolAddress((void**)&nk,  g_nk);
    cudaGetSymbolAddress((void**)&qph, g_qph);  cudaGetSymbolAddress((void**)&qpl, g_qpl);
    cudaGetSymbolAddress((void**)&kpth, g_kpth);cudaGetSymbolAddress((void**)&kptl, g_kptl);
    cudaGetSymbolAddress((void**)&kvp, g_kvp);  cudaGetSymbolAddress((void**)&ksp, g_ksp);
    cudaGetSymbolAddress((void**)&kvth, g_kvth);cudaGetSymbolAddress((void**)&kvtl, g_kvtl);
    cudaGetSymbolAddress((void**)&ksum, g_ksum);
    cudaGetSymbolAddress((void**)&ath, g_ath);  cudaGetSymbolAddress((void**)&atl, g_atl);

    const int SM128 = 2 * (2 * 128 * RS * 2 + 2 * 128 * RS * 2) + 2048;  // 83968
    const int SM64  = 2 * (2 * 128 * RS * 2 + 2 * 64 * RS * 2) + 2048;   // 63488
    cudaFuncSetAttribute(tgemm<128, 0, 1, 2>, cudaFuncAttributeMaxDynamicSharedMemorySize, SM128);
    cudaFuncSetAttribute(tgemm<128, 1, 1, 3>, cudaFuncAttributeMaxDynamicSharedMemorySize, SM128);
    cudaFuncSetAttribute(tgemm<128, 7, 1, 3>, cudaFuncAttributeMaxDynamicSharedMemorySize, SM128);
    cudaFuncSetAttribute(tgemm<128, 6, 1, 2>, cudaFuncAttributeMaxDynamicSharedMemorySize, SM128);
    cudaFuncSetAttribute(tgemm<64, 4, 0, 3>,  cudaFuncAttributeMaxDynamicSharedMemorySize, SM64);
    cudaFuncSetAttribute(tgemm<64, 8, 0, 3>,  cudaFuncAttributeMaxDynamicSharedMemorySize, SM64);

    // fused splits + rf transpose (one launch)
    SplitJobs sj = { (const float4*)x, (const float4*)wq, (const float4*)wk,
                     (const float4*)wv, (const float4*)wo, rf,
                     xh, xl, wqh, wql, wkh, wkl, wvh, wvl, woh, wol, rfh, rfl };
    split_all_kernel<<<5120, 256>>>(sj);

    // FUSED Q+K projections (M=16384, N=1024, K=1024), fp16x3, z selects Q/K
    dim3 gqk(Dc / 128, Mtot / 128, 2);
    TGP pqk = {};
    pqk.ah = xh; pqk.al = xl; pqk.a_ob = 0; pqk.a_oh = 0; pqk.a_st = Dc;
    pqk.b_ob = 0; pqk.b_oh = 0; pqk.b_st = Dc; pqk.K = Dc;
    pqk.o_ob = 0; pqk.o_oh = 0; pqk.o_st = Dc;
    pqk.bh = wqh; pqk.bl = wql; pqk.bias = bq;
    pqk.o_hi = qh; pqk.o_lo = ql; pqk.nrm_out = nq;
    pqk.bh2 = wkh; pqk.bl2 = wkl; pqk.bias2 = bk;
    pqk.o_hi2 = kh; pqk.o_lo2 = kl; pqk.nrm_out2 = nk;
    tgemm<128, 1, 1, 3><<<gqk, 256, SM128>>>(pqk);

    // V projection TRANSPOSED: C[d, m] = wv * x^T, fp16x2 -> bf16 split
    dim3 gvt(Mtot / 128, Dc / 128, 1);
    TGP pv = {};
    pv.ah = wvh; pv.al = wvl; pv.a_ob = 0; pv.a_oh = 0; pv.a_st = Dc;
    pv.bh = xh;  pv.bl = xl;  pv.b_ob = 0; pv.b_oh = 0; pv.b_st = Dc;
    pv.K = Dc; pv.bias = bv;
    pv.o_hi = vth; pv.o_lo = vtl; pv.o_ob = 0; pv.o_oh = 0; pv.o_st = Mtot;
    tgemm<128, 6, 1, 2><<<gvt, 256, SM128>>>(pv);

    // FUSED feature maps (EPI 7): z<64 Q-mode, z>=64 K-mode
    dim3 gfeat(32, 2, 128);
    TGP pf = {};
    // Q-mode set: per bh M=4096 s, N=256 r, K=64; out qp [bh][s][r]
    pf.ah = qh; pf.al = ql;
    pf.a_ob = (long long)Sc * Dc; pf.a_oh = HDc; pf.a_st = Dc;
    pf.bh = rfh; pf.bl = rfl;
    pf.b_ob = 0; pf.b_oh = (long long)Rc * HDc; pf.b_st = HDc;
    pf.K = HDc; pf.norm = nq;
    pf.o_hi = qph; pf.o_lo = qpl;
    pf.o_ob = (long long)16 * Sc * Rc; pf.o_oh = (long long)Sc * Rc; pf.o_st = Rc;
    // K-mode set: per bh M=256 r, N=4096 s, K=64; out kp^T [bh][r][s]
    pf.ah2 = rfh; pf.al2 = rfl;
    pf.a_ob2 = 0; pf.a_oh2 = (long long)Rc * HDc; pf.a_st2 = HDc;
    pf.bh2 = kh; pf.bl2 = kl;
    pf.b_ob2 = (long long)Sc * Dc; pf.b_oh2 = HDc; pf.b_st2 = Dc;
    pf.norm2 = nk;
    pf.o_hi2 = kpth; pf.o_lo2 = kptl;
    pf.o_ob2 = (long long)16 * Rc * Sc; pf.o_oh2 = (long long)Rc * Sc; pf.o_st2 = Sc;
    tgemm<128, 7, 1, 3><<<gfeat, 256, SM128>>>(pf);

    // kv aggregation GEMM (per bh: M=256 r, N=64 d, K=4096 s, split-K x4), bf16x3
    dim3 gkv(4, Rc / 128, Bc * Hc);
    TGP pkv = {};
    pkv.ah = kpth; pkv.al = kptl;
    pkv.a_ob = (long long)16 * Rc * Sc; pkv.a_oh = (long long)Rc * Sc; pkv.a_st = Sc;
    pkv.bh = vth; pkv.bl = vtl;
    pkv.b_ob = 4096; pkv.b_oh = (long long)64 * Mtot; pkv.b_st = Mtot;
    pkv.K = 1024;
    pkv.o0 = kvp; pkv.nrm_out = ksp;
    tgemm<64, 8, 0, 3><<<gkv, 256, SM64>>>(pkv);

    kvfinal_kernel<<<4096, 256>>>(kvp, ksp, kvth, kvtl, ksum);

    // attention readout (per bh: M=4096 s, N=64 d, K=256 r), bf16x3 -> fp16 split
    dim3 gat(1, Sc / 128, Bc * Hc);
    TGP pa = {};
    pa.ah = qph; pa.al = qpl;
    pa.a_ob = (long long)16 * Sc * Rc; pa.a_oh = (long long)Sc * Rc; pa.a_st = Rc;
    pa.bh = kvth; pa.bl = kvtl;
    pa.b_ob = (long long)16 * HDc * Rc; pa.b_oh = (long long)HDc * Rc; pa.b_st = Rc;
    pa.K = Rc; pa.ksum = ksum;
    pa.o_hi = ath; pa.o_lo = atl;
    pa.o_ob = (long long)Sc * Dc; pa.o_oh = HDc; pa.o_st = Dc;
    tgemm<64, 4, 0, 3><<<gat, 256, SM64>>>(pa);

    // output projection, fp16x2 -> f32
    TGP po = {};
    po.ah = ath; po.al = atl; po.a_ob = 0; po.a_oh = 0; po.a_st = Dc;
    po.bh = woh; po.bl = wol; po.b_ob = 0; po.b_oh = 0; po.b_st = Dc;
    po.K = Dc; po.bias = bo; po.o0 = out;
    po.o_ob = 0; po.o_oh = 0; po.o_st = Dc;
    dim3 gproj(Dc / 128, Mtot / 128, 1);
    tgemm<128, 0, 1, 2><<<gproj, 256, SM128>>>(po);
}

// round 17
// speedup vs baseline: 1.3782x; 1.0242x over previous
#include <cuda_runtime.h>
#include <cuda_bf16.h>
#include <cuda_fp16.h>
#include <cstdint>
#include <math.h>

#define Bc 4
#define Sc 4096
#define Dc 1024
#define Hc 16
#define Rc 256
#define HDc 64
#define Mtot (Bc * Sc)
#define BK 32
#define RS 40      // smem row stride in u16 (32 data + 8 pad = 80B)

typedef unsigned short u16;
typedef uint32_t u32;

// ---------------- scratch (device globals) ----------------
__device__ u16 g_xh[(size_t)Mtot * Dc],  g_xl[(size_t)Mtot * Dc];
__device__ u16 g_wqh[Dc * Dc], g_wql[Dc * Dc];
__device__ u16 g_wkh[Dc * Dc], g_wkl[Dc * Dc];
__device__ u16 g_wvh[Dc * Dc], g_wvl[Dc * Dc];
__device__ u16 g_woh[Dc * Dc], g_wol[Dc * Dc];
__device__ u16 g_rfh[(size_t)Hc * Rc * HDc], g_rfl[(size_t)Hc * Rc * HDc];
__device__ u16 g_qh[(size_t)Mtot * Dc],  g_ql[(size_t)Mtot * Dc];
__device__ u16 g_kh[(size_t)Mtot * Dc],  g_kl[(size_t)Mtot * Dc];
__device__ u16 g_ath[(size_t)Mtot * Dc], g_atl[(size_t)Mtot * Dc];
__device__ u16 g_vth[(size_t)Mtot * Dc], g_vtl[(size_t)Mtot * Dc];   // V^T [d][m]
__device__ u16 g_qph[(size_t)Bc * Hc * Sc * Rc], g_qpl[(size_t)Bc * Hc * Sc * Rc];
__device__ u16 g_kpth[(size_t)Bc * Hc * Rc * Sc], g_kptl[(size_t)Bc * Hc * Rc * Sc];
__device__ u16 g_kvth[(size_t)Bc * Hc * HDc * Rc], g_kvtl[(size_t)Bc * Hc * HDc * Rc];
__device__ float g_nq[(size_t)Bc * Hc * Sc], g_nk[(size_t)Bc * Hc * Sc];
__device__ float g_kvp[(size_t)Bc * Hc * 4 * Rc * HDc];
__device__ float g_ksp[(size_t)Bc * Hc * 4 * Rc];
__device__ float g_ksum[(size_t)Bc * Hc * Rc];

// ---------------- helpers ----------------
__device__ __forceinline__ u32 smem_u32(const void* p) {
    u32 a;
    asm("{ .reg .u64 t; cvta.to.shared.u64 t, %1; cvt.u32.u64 %0, t; }" : "=r"(a) : "l"(p));
    return a;
}
__device__ __forceinline__ void hsplit(float a, u16& h, u16& l) {
    __half hb = __float2half_rn(a);
    float lf = a - __half2float(hb);
    __half lb = __float2half_rn(lf);
    h = __half_as_ushort(hb);
    l = __half_as_ushort(lb);
}
__device__ __forceinline__ void bsplit(float a, u16& h, u16& l) {
    __nv_bfloat16 hb = __float2bfloat16_rn(a);
    float lf = a - __bfloat162float(hb);
    __nv_bfloat16 lb = __float2bfloat16_rn(lf);
    h = __bfloat16_as_ushort(hb);
    l = __bfloat16_as_ushort(lb);
}
__device__ __forceinline__ void bsplit2(float v0, float v1, u32& hp, u32& lp) {
    asm("cvt.rn.bf16x2.f32 %0, %1, %2;" : "=r"(hp) : "f"(v1), "f"(v0));
    float h0f = __uint_as_float(hp << 16);
    float h1f = __uint_as_float(hp & 0xffff0000u);
    asm("cvt.rn.bf16x2.f32 %0, %1, %2;" : "=r"(lp) : "f"(v1 - h1f), "f"(v0 - h0f));
}
__device__ __forceinline__ void hsplit2(float v0, float v1, u32& hp, u32& lp) {
    asm("cvt.rn.f16x2.f32 %0, %1, %2;" : "=r"(hp) : "f"(v1), "f"(v0));
    __half2 h2 = *(__half2*)&hp;
    float2 hf = __half22float2(h2);
    asm("cvt.rn.f16x2.f32 %0, %1, %2;" : "=r"(lp) : "f"(v1 - hf.y), "f"(v0 - hf.x));
}
__device__ __forceinline__ void cpa16(u32 dst, const void* src) {
    asm volatile("cp.async.cg.shared.global [%0], [%1], 16;"
                 :: "r"(dst), "l"(__cvta_generic_to_global(src)) : "memory");
}
__device__ __forceinline__ void mma_bf16(float* c, const u32* A, const u32* B) {
    asm volatile(
        "mma.sync.aligned.m16n8k16.row.col.f32.bf16.bf16.f32 "
        "{%0,%1,%2,%3}, {%4,%5,%6,%7}, {%8,%9}, {%0,%1,%2,%3};"
        : "+f"(c[0]), "+f"(c[1]), "+f"(c[2]), "+f"(c[3])
        : "r"(A[0]), "r"(A[1]), "r"(A[2]), "r"(A[3]), "r"(B[0]), "r"(B[1]));
}
__device__ __forceinline__ void mma_f16(float* c, const u32* A, const u32* B) {
    asm volatile(
        "mma.sync.aligned.m16n8k16.row.col.f32.f16.f16.f32 "
        "{%0,%1,%2,%3}, {%4,%5,%6,%7}, {%8,%9}, {%0,%1,%2,%3};"
        : "+f"(c[0]), "+f"(c[1]), "+f"(c[2]), "+f"(c[3])
        : "r"(A[0]), "r"(A[1]), "r"(A[2]), "r"(A[3]), "r"(B[0]), "r"(B[1]));
}
template<int FT>
__device__ __forceinline__ void mma16(float* c, const u32* A, const u32* B) {
    if (FT == 0) mma_bf16(c, A, B);
    else         mma_f16(c, A, B);
}
__device__ __forceinline__ void ldsm4(u32& r0, u32& r1, u32& r2, u32& r3, u32 addr) {
    asm volatile("ldmatrix.sync.aligned.m8n8.x4.shared.b16 {%0,%1,%2,%3}, [%4];"
                 : "=r"(r0), "=r"(r1), "=r"(r2), "=r"(r3) : "r"(addr));
}

// ---------------- fused split: x + 4 weights + rf-transpose ----------------
struct SplitJobs {
    const float4 *x, *wq, *wk, *wv, *wo;
    const float* rf;
    u16 *xh, *xl, *wqh, *wql, *wkh, *wkl, *wvh, *wvl, *woh, *wol, *rfh, *rfl;
};
__global__ void split_all_kernel(SplitJobs j)
{
    int bx = blockIdx.x;
    if (bx >= 4096) {
        int idx = (bx - 4096) * 256 + threadIdx.x;
        if (idx < Hc * Rc * HDc) {
            int d = idx & 63, r = (idx >> 6) & 255, h = idx >> 14;
            float a = j.rf[((size_t)(h * HDc + d)) * Rc + r];
            u16 hv, lv; hsplit(a, hv, lv);
            j.rfh[idx] = hv; j.rfl[idx] = lv;
        }
        return;
    }
    const float4* src;
    u16 *hi, *lo;
    int base, n4;
    if (bx < 2048)      { src = j.x;  hi = j.xh;  lo = j.xl;  base = bx;        n4 = Mtot * Dc / 4; }
    else if (bx < 2560) { src = j.wq; hi = j.wqh; lo = j.wql; base = bx - 2048; n4 = Dc * Dc / 4; }
    else if (bx < 3072) { src = j.wk; hi = j.wkh; lo = j.wkl; base = bx - 2560; n4 = Dc * Dc / 4; }
    else if (bx < 3584) { src = j.wv; hi = j.wvh; lo = j.wvl; base = bx - 3072; n4 = Dc * Dc / 4; }
    else                { src = j.wo; hi = j.woh; lo = j.wol; base = bx - 3584; n4 = Dc * Dc / 4; }
    const int stride = (bx < 2048) ? 2048 * 256 : 512 * 256;
    for (int i = base * 256 + threadIdx.x; i < n4; i += stride) {
        float4 a = src[i];
        ushort4 hv, lv;
        hsplit(a.x, hv.x, lv.x); hsplit(a.y, hv.y, lv.y);
        hsplit(a.z, hv.z, lv.z); hsplit(a.w, hv.w, lv.w);
        *(ushort4*)(hi + (size_t)i * 4) = hv;
        *(ushort4*)(lo + (size_t)i * 4) = lv;
    }
}

// ---------------- split-precision tensor GEMM engine ----------------
// EPI: 0 +bias(col)->f32 | 1 +bias(col)->fp16 split + rownorm (z picks Q/K set)
//      4 normalize (A.ksum)->fp16 split | 6 +bias(row)->bf16 split
//      7 fused features (z<64 Q-mode row-norm, z>=64 K-mode col-norm) -> bf16 split
//      8 split-K partial f32 + A-rowsum
// NTILE==128 epilogues (0,1,6,7) stage stores through smem for coalesced STG.128.
struct TGP {
    const u16 *ah, *al, *bh, *bl;
    long long a_ob, a_oh, b_ob, b_oh, o_ob, o_oh;
    int a_st, b_st, o_st, K;
    const float *bias, *norm, *ksum;
    float* o0;
    u16 *o_hi, *o_lo;
    float* nrm_out;
    const u16 *ah2, *al2, *bh2, *bl2;
    long long a_ob2, a_oh2, b_ob2, b_oh2, o_ob2, o_oh2;
    int a_st2, b_st2, o_st2;
    const float *bias2, *norm2;
    u16 *o_hi2, *o_lo2;
    float* nrm_out2;
};

template<int NTILE, int EPI, int FT, int XN>
__global__ void __launch_bounds__(256, (NTILE == 64) ? 3 : 2) tgemm(TGP p)
{
    extern __shared__ char smc[];
    const int tid = threadIdx.x, lane = tid & 31, wid = tid >> 5;
    const int z = blockIdx.z;
    const int chunk = (EPI == 8) ? blockIdx.x : 0;
    const int mode7 = (EPI == 7) ? (z >> 6) : 0;

    int m0, n0;
    if (EPI == 7) {
        if (mode7 == 0) { m0 = blockIdx.x << 7; n0 = blockIdx.y << 7; }
        else            { m0 = blockIdx.y << 7; n0 = blockIdx.x << 7; }
    } else {
        m0 = blockIdx.y << 7;
        n0 = (EPI == 8) ? 0 : blockIdx.x * NTILE;
    }

    if (EPI == 1 && z == 1) {
        p.bh = p.bh2; p.bl = p.bl2; p.bias = p.bias2;
        p.o_hi = p.o_hi2; p.o_lo = p.o_lo2; p.nrm_out = p.nrm_out2;
    }
    if (EPI == 7 && mode7 == 1) {
        p.ah = p.ah2; p.al = p.al2; p.bh = p.bh2; p.bl = p.bl2;
        p.a_ob = p.a_ob2; p.a_oh = p.a_oh2; p.a_st = p.a_st2;
        p.b_ob = p.b_ob2; p.b_oh = p.b_oh2; p.b_st = p.b_st2;
        p.o_ob = p.o_ob2; p.o_oh = p.o_oh2; p.o_st = p.o_st2;
        p.norm = p.norm2; p.o_hi = p.o_hi2; p.o_lo = p.o_lo2;
    }

    constexpr int MT = (NTILE == 128) ? 4 : 2;
    constexpr bool OUT_BF = (EPI == 6 || EPI == 7);
    constexpr bool STAGED = (NTILE == 128) && (EPI == 0 || EPI == 1 || EPI == 6 || EPI == 7);
    const int wm0 = (NTILE == 128) ? ((wid & 1) << 6) : ((wid & 3) << 5);
    const int wn0 = (NTILE == 128) ? ((wid >> 1) << 5) : ((wid >> 2) << 5);

    constexpr int APL = 128 * RS * 2;
    constexpr int BPL = NTILE * RS * 2;
    constexpr int BLK = 2 * APL + 2 * BPL;
    const u32 su = smem_u32(smc);
    float* const ksums = (float*)(smc + 2 * BLK);
    float* const snorm = ksums + 256;
    // epilogue staging (reuses pipeline stages; <= 2*BLK bytes)
    u32* const stg_h = (u32*)smc;                       // 128 x 68 u32
    u32* const stg_l = (u32*)(smc + 128 * 68 * 4);
    float* const stg_f = (float*)smc;                   // 128 x 136 f32

    const int zz = (EPI == 1) ? 0 : ((EPI == 7) ? (z & 63) : z);
    size_t aoff = (size_t)p.a_ob * (zz >> 4) + (size_t)p.a_oh * (zz & 15);
    size_t boff = (size_t)p.b_ob * (zz >> 4) + (size_t)p.b_oh * (zz & 15);
    const size_t ooff = (size_t)p.o_ob * (zz >> 4) + (size_t)p.o_oh * (zz & 15);
    if (EPI == 8) { aoff += (size_t)chunk * 1024; boff += (size_t)chunk * 1024; }

    if (EPI == 4) ksums[tid] = p.ksum[(size_t)z * Rc + tid];

    const int steps = p.K / BK;

    auto issue = [&](int step) {
        const int k0 = step * BK;
        const u32 sb = su + (step & 1) * BLK;
        const u16* agh = p.ah + aoff + k0;
        const u16* agl = p.al + aoff + k0;
        const u16* bgh = p.bh + boff + k0;
        const u16* bgl = p.bl + boff + k0;
        #pragma unroll
        for (int j = tid; j < 512; j += 256) {
            int row = j >> 2, ch = j & 3;
            size_t gs = (size_t)(m0 + row) * p.a_st + ch * 8;
            u32 so = row * (RS * 2) + ch * 16;
            cpa16(sb + so, agh + gs);
            cpa16(sb + APL + so, agl + gs);
        }
        #pragma unroll
        for (int j = tid; j < NTILE * 4; j += 256) {
            int row = j >> 2, ch = j & 3;
            size_t gs = (size_t)(n0 + row) * p.b_st + ch * 8;
            u32 so = row * (RS * 2) + ch * 16;
            cpa16(sb + 2 * APL + so, bgh + gs);
            if (XN == 3) cpa16(sb + 2 * APL + BPL + so, bgl + gs);
        }
        asm volatile("cp.async.commit_group;" ::: "memory");
    };

    issue(0);

    float acc[MT][4][4];
    #pragma unroll
    for (int i = 0; i < MT; i++)
        #pragma unroll
        for (int j = 0; j < 4; j++)
            #pragma unroll
            for (int c = 0; c < 4; c++) acc[i][j][c] = 0.0f;
    float nacc = 0.0f;

    const u32 aoff_lane = (lane & 15) * (RS * 2) + (lane >> 4) * 16;
    const u32 boff_lane = ((lane & 7) + ((lane >> 4) << 3)) * (RS * 2) + ((lane >> 3) & 1) * 16;

    for (int i = 0; i < steps; i++) {
        asm volatile("cp.async.wait_group 0;" ::: "memory");
        __syncthreads();
        if (i + 1 < steps) issue(i + 1);

        const int buf = i & 1;
        const u32 sb = su + buf * BLK;

        if (EPI == 4 || EPI == 8) {
            int row = tid >> 1, half16 = tid & 1;
            const __nv_bfloat162* xh = (const __nv_bfloat162*)(smc + buf * BLK
                                        + row * (RS * 2) + half16 * 32);
            const __nv_bfloat162* xl = (const __nv_bfloat162*)(smc + buf * BLK + APL
                                        + row * (RS * 2) + half16 * 32);
            if (EPI == 4) {
                const float* kv = ksums + i * BK + half16 * 16;
                #pragma unroll
                for (int t = 0; t < 8; t++) {
                    float2 h2 = __bfloat1622float2(xh[t]);
                    float2 l2 = __bfloat1622float2(xl[t]);
                    nacc += (h2.x + l2.x) * kv[2 * t] + (h2.y + l2.y) * kv[2 * t + 1];
                }
            } else {
                #pragma unroll
                for (int t = 0; t < 8; t++) {
                    float2 h2 = __bfloat1622float2(xh[t]);
                    float2 l2 = __bfloat1622float2(xl[t]);
                    nacc += h2.x + l2.x + h2.y + l2.y;
                }
            }
        }

        #pragma unroll
        for (int half = 0; half < 2; half++) {
            const u32 kb = half * 32;
            u32 ahr[MT][4], alr[MT][4];
            #pragma unroll
            for (int im = 0; im < MT; im++) {
                u32 abase = sb + (wm0 + im * 16) * (RS * 2) + kb + aoff_lane;
                ldsm4(ahr[im][0], ahr[im][1], ahr[im][2], ahr[im][3], abase);
                ldsm4(alr[im][0], alr[im][1], alr[im][2], alr[im][3], abase + APL);
            }
            #pragma unroll
            for (int npair = 0; npair < 2; npair++) {
                u32 bbase = sb + 2 * APL + (wn0 + npair * 16) * (RS * 2) + kb + boff_lane;
                u32 bh0, bh1, bh2_, bh3;
                ldsm4(bh0, bh1, bh2_, bh3, bbase);
                u32 bhA[2] = { bh0, bh1 }, bhB[2] = { bh2_, bh3 };
                const int iA = npair * 2, iB = npair * 2 + 1;
                #pragma unroll
                for (int im = 0; im < MT; im++) mma16<FT>(acc[im][iA], ahr[im], bhA);
                #pragma unroll
                for (int im = 0; im < MT; im++) mma16<FT>(acc[im][iB], ahr[im], bhB);
                #pragma unroll
                for (int im = 0; im < MT; im++) mma16<FT>(acc[im][iA], alr[im], bhA);
                #pragma unroll
                for (int im = 0; im < MT; im++) mma16<FT>(acc[im][iB], alr[im], bhB);
                if (XN == 3) {
                    u32 bl0, bl1, bl2_, bl3;
                    ldsm4(bl0, bl1, bl2_, bl3, bbase + BPL);
                    u32 blA[2] = { bl0, bl1 }, blB[2] = { bl2_, bl3 };
                    #pragma unroll
                    for (int im = 0; im < MT; im++) mma16<FT>(acc[im][iA], ahr[im], blA);
                    #pragma unroll
                    for (int im = 0; im < MT; im++) mma16<FT>(acc[im][iB], ahr[im], blB);
                }
            }
        }
    }
    __syncthreads();

    if (EPI == 4 || EPI == 8) { snorm[tid] = nacc; __syncthreads(); }
    if (EPI == 1) { ksums[tid] = 0.0f; __syncthreads(); }

    // ---------------- epilogue: compute (+ stage) ----------------
    const int lh = wn0 >> 6;
    #pragma unroll
    for (int im = 0; im < MT; im++) {
        const int la = wm0 + im * 16 + (lane >> 2);
        const int lb = la + 8;
        const int rA = m0 + la, rB = m0 + lb;
        float hnA = 0.0f, hnB = 0.0f, invA = 1.0f, invB = 1.0f;
        float bA = 0.0f, bB = 0.0f;
        if (EPI == 7 && mode7 == 0) {
            hnA = 0.5f * p.norm[(size_t)zz * Sc + rA];
            hnB = 0.5f * p.norm[(size_t)zz * Sc + rB];
        }
        if (EPI == 6) {
            bA = __ldg(p.bias + rA);
            bB = __ldg(p.bias + rB);
        }
        if (EPI == 4) {
            invA = 1.0f / (snorm[2 * la] + snorm[2 * la + 1] + 1e-6f);
            invB = 1.0f / (snorm[2 * lb] + snorm[2 * lb + 1] + 1e-6f);
        }
        float sA = 0.0f, sB = 0.0f;
        #pragma unroll
        for (int in_ = 0; in_ < 4; in_++) {
            const int nl = wn0 + in_ * 8 + ((lane & 3) << 1);
            const int n = n0 + nl;
            float v0 = acc[im][in_][0], v1 = acc[im][in_][1];
            float v2 = acc[im][in_][2], v3 = acc[im][in_][3];
            if (EPI == 0 || EPI == 1) {
                float b0 = __ldg(p.bias + n), b1 = __ldg(p.bias + n + 1);
                v0 += b0; v1 += b1; v2 += b0; v3 += b1;
            } else if (EPI == 6) {
                v0 += bA; v1 += bA; v2 += bB; v3 += bB;
            } else if (EPI == 7) {
                if (mode7 == 0) {
                    v0 = __expf(v0 - hnA); v1 = __expf(v1 - hnA);
                    v2 = __expf(v2 - hnB); v3 = __expf(v3 - hnB);
                } else {
                    float hn0 = 0.5f * __ldg(p.norm + (size_t)zz * Sc + n);
                    float hn1 = 0.5f * __ldg(p.norm + (size_t)zz * Sc + n + 1);
                    v0 = __expf(v0 - hn0); v1 = __expf(v1 - hn1);
                    v2 = __expf(v2 - hn0); v3 = __expf(v3 - hn1);
                }
            } else if (EPI == 4) {
                v0 *= invA; v1 *= invA; v2 *= invB; v3 *= invB;
            }
            if (EPI == 1) { sA += v0 * v0 + v1 * v1; sB += v2 * v2 + v3 * v3; }
            if (STAGED) {
                if (EPI == 0) {
                    *(float2*)(stg_f + la * 136 + nl) = make_float2(v0, v1);
                    *(float2*)(stg_f + lb * 136 + nl) = make_float2(v2, v3);
                } else {
                    const int cu = nl >> 1;
                    u32 hpA, lpA, hpB, lpB;
                    if (OUT_BF) { bsplit2(v0, v1, hpA, lpA); bsplit2(v2, v3, hpB, lpB); }
                    else        { hsplit2(v0, v1, hpA, lpA); hsplit2(v2, v3, hpB, lpB); }
                    stg_h[la * 68 + cu] = hpA; stg_l[la * 68 + cu] = lpA;
                    stg_h[lb * 68 + cu] = hpB; stg_l[lb * 68 + cu] = lpB;
                }
            } else if (EPI == 8) {
                float* b8 = p.o0 + (((size_t)z * 4 + chunk) << 14);
                *(float2*)(b8 + (size_t)rA * 64 + n) = make_float2(v0, v1);
                *(float2*)(b8 + (size_t)rB * 64 + n) = make_float2(v2, v3);
            } else {  // EPI 4 (NTILE 64) unstaged fp16 split
                size_t oA = ooff + (size_t)rA * p.o_st + n;
                size_t oB = ooff + (size_t)rB * p.o_st + n;
                u16 h0, l0, h1, l1, h2, l2, h3, l3;
                hsplit(v0, h0, l0); hsplit(v1, h1, l1);
                hsplit(v2, h2, l2); hsplit(v3, h3, l3);
                *(u32*)(p.o_hi + oA) = (u32)h0 | ((u32)h1 << 16);
                *(u32*)(p.o_lo + oA) = (u32)l0 | ((u32)l1 << 16);
                *(u32*)(p.o_hi + oB) = (u32)h2 | ((u32)h3 << 16);
                *(u32*)(p.o_lo + oB) = (u32)l2 | ((u32)l3 << 16);
            }
        }
        if (EPI == 1) {
            atomicAdd(&ksums[la * 2 + lh], sA);
            atomicAdd(&ksums[lb * 2 + lh], sB);
        }
    }

    // ---------------- epilogue: coalesced copy-out ----------------
    if (STAGED) {
        __syncthreads();
        if (EPI == 0) {
            #pragma unroll
            for (int j = 0; j < 16; j++) {
                int flat = j * 256 + tid;           // 0..4095
                int row = flat >> 5, ui = flat & 31;
                *(float4*)(p.o0 + ooff + (size_t)(m0 + row) * p.o_st + n0 + ui * 4)
                    = *(float4*)(stg_f + row * 136 + ui * 4);
            }
        } else {
            #pragma unroll
            for (int j = 0; j < 8; j++) {
                int flat = j * 256 + tid;           // 0..2047
                int row = flat >> 4, ui = flat & 15;
                size_t go = ooff + (size_t)(m0 + row) * p.o_st + n0 + ui * 8;
                *(uint4*)(p.o_hi + go) = *(uint4*)(stg_h + row * 68 + ui * 4);
                *(uint4*)(p.o_lo + go) = *(uint4*)(stg_l + row * 68 + ui * 4);
            }
        }
    }

    if (EPI == 1) {
        __syncthreads();
        int row = tid >> 1, hloc = tid & 1;
        int rg = m0 + row, b = rg >> 12, s = rg & 4095;
        int head = (n0 >> 6) + hloc;
        p.nrm_out[(size_t)(b * 16 + head) * Sc + s] = ksums[tid];
    }
    if (EPI == 8) {
        if (tid < 128)
            p.nrm_out[(((size_t)z * 4 + chunk) << 8) + m0 + tid] =
                snorm[2 * tid] + snorm[2 * tid + 1];
    }
}

// ---------------- kv final reduce ----------------
__global__ void kvfinal_kernel(const float* __restrict__ kvp, const float* __restrict__ ksp,
                               u16* __restrict__ kvth, u16* __restrict__ kvtl,
                               float* __restrict__ ks)
{
    size_t idx = (size_t)blockIdx.x * 256 + threadIdx.x;
    int r = (int)(idx & 255), d = (int)((idx >> 8) & 63), bh = (int)(idx >> 14);
    float s = 0.0f;
    #pragma unroll
    for (int c = 0; c < 4; c++)
        s += kvp[(((size_t)bh * 4 + c) << 14) + (r << 6) + d];
    u16 hv, lv; bsplit(s, hv, lv);
    size_t o = ((size_t)bh << 14) + (d << 8) + r;
    kvth[o] = hv; kvtl[o] = lv;
    if (idx < (size_t)64 * 256) {
        int bh2 = (int)(idx >> 8), r2 = (int)(idx & 255);
        float t = 0.0f;
        #pragma unroll
        for (int c = 0; c < 4; c++) t += ksp[((size_t)(bh2 * 4 + c) << 8) + r2];
        ks[idx] = t;
    }
}

// ---------------- launch ----------------
extern "C" void kernel_launch(void* const* d_in, const int* in_sizes, int n_in,
                              void* d_out, int out_size)
{
    (void)in_sizes; (void)n_in; (void)out_size;
    const float* x  = (const float*)d_in[0];
    const float* wq = (const float*)d_in[1];
    const float* bq = (const float*)d_in[2];
    const float* wk = (const float*)d_in[3];
    const float* bk = (const float*)d_in[4];
    const float* wv = (const float*)d_in[5];
    const float* bv = (const float*)d_in[6];
    const float* wo = (const float*)d_in[7];
    const float* bo = (const float*)d_in[8];
    const float* rf = (const float*)d_in[9];
    float* out = (float*)d_out;

    u16 *xh, *xl, *wqh, *wql, *wkh, *wkl, *wvh, *wvl, *woh, *wol;
    u16 *rfh, *rfl, *qh, *ql, *kh, *kl, *vth, *vtl, *qph, *qpl;
    u16 *kpth, *kptl, *kvth, *kvtl, *ath, *atl;
    float *nq, *nk, *kvp, *ksp, *ksum;
    cudaGetSymbolAddress((void**)&xh,  g_xh);   cudaGetSymbolAddress((void**)&xl,  g_xl);
    cudaGetSymbolAddress((void**)&wqh, g_wqh);  cudaGetSymbolAddress((void**)&wql, g_wql);
    cudaGetSymbolAddress((void**)&wkh, g_wkh);  cudaGetSymbolAddress((void**)&wkl, g_wkl);
    cudaGetSymbolAddress((void**)&wvh, g_wvh);  cudaGetSymbolAddress((void**)&wvl, g_wvl);
    cudaGetSymbolAddress((void**)&woh, g_woh);  cudaGetSymbolAddress((void**)&wol, g_wol);
    cudaGetSymbolAddress((void**)&rfh, g_rfh);  cudaGetSymbolAddress((void**)&rfl, g_rfl);
    cudaGetSymbolAddress((void**)&qh,  g_qh);   cudaGetSymbolAddress((void**)&ql,  g_ql);
    cudaGetSymbolAddress((void**)&kh,  g_kh);   cudaGetSymbolAddress((void**)&kl,  g_kl);
    cudaGetSymbolAddress((void**)&vth, g_vth);  cudaGetSymbolAddress((void**)&vtl, g_vtl);
    cudaGetSymbolAddress((void**)&nq,  g_nq);   cudaGetSymbolAddress((void**)&nk,  g_nk);
    cudaGetSymbolAddress((void**)&qph, g_qph);  cudaGetSymbolAddress((void**)&qpl, g_qpl);
    cudaGetSymbolAddress((void**)&kpth, g_kpth);cudaGetSymbolAddress((void**)&kptl, g_kptl);
    cudaGetSymbolAddress((void**)&kvp, g_kvp);  cudaGetSymbolAddress((void**)&ksp, g_ksp);
    cudaGetSymbolAddress((void**)&kvth, g_kvth);cudaGetSymbolAddress((void**)&kvtl, g_kvtl);
    cudaGetSymbolAddress((void**)&ksum, g_ksum);
    cudaGetSymbolAddress((void**)&ath, g_ath);  cudaGetSymbolAddress((void**)&atl, g_atl);

    const int SM128 = 2 * (2 * 128 * RS * 2 + 2 * 128 * RS * 2) + 2048;  // 83968
    const int SM64  = 2 * (2 * 128 * RS * 2 + 2 * 64 * RS * 2) + 2048;   // 63488
    cudaFuncSetAttribute(tgemm<128, 0, 1, 2>, cudaFuncAttributeMaxDynamicSharedMemorySize, SM128);
    cudaFuncSetAttribute(tgemm<128, 1, 1, 3>, cudaFuncAttributeMaxDynamicSharedMemorySize, SM128);
    cudaFuncSetAttribute(tgemm<128, 7, 1, 3>, cudaFuncAttributeMaxDynamicSharedMemorySize, SM128);
    cudaFuncSetAttribute(tgemm<128, 6, 1, 2>, cudaFuncAttributeMaxDynamicSharedMemorySize, SM128);
    cudaFuncSetAttribute(tgemm<64, 4, 0, 3>,  cudaFuncAttributeMaxDynamicSharedMemorySize, SM64);
    cudaFuncSetAttribute(tgemm<64, 8, 0, 3>,  cudaFuncAttributeMaxDynamicSharedMemorySize, SM64);

    SplitJobs sj = { (const float4*)x, (const float4*)wq, (const float4*)wk,
                     (const float4*)wv, (const float4*)wo, rf,
                     xh, xl, wqh, wql, wkh, wkl, wvh, wvl, woh, wol, rfh, rfl };
    split_all_kernel<<<5120, 256>>>(sj);

    // FUSED Q+K projections
    dim3 gqk(Dc / 128, Mtot / 128, 2);
    TGP pqk = {};
    pqk.ah = xh; pqk.al = xl; pqk.a_ob = 0; pqk.a_oh = 0; pqk.a_st = Dc;
    pqk.b_ob = 0; pqk.b_oh = 0; pqk.b_st = Dc; pqk.K = Dc;
    pqk.o_ob = 0; pqk.o_oh = 0; pqk.o_st = Dc;
    pqk.bh = wqh; pqk.bl = wql; pqk.bias = bq;
    pqk.o_hi = qh; pqk.o_lo = ql; pqk.nrm_out = nq;
    pqk.bh2 = wkh; pqk.bl2 = wkl; pqk.bias2 = bk;
    pqk.o_hi2 = kh; pqk.o_lo2 = kl; pqk.nrm_out2 = nk;
    tgemm<128, 1, 1, 3><<<gqk, 256, SM128>>>(pqk);

    // V projection TRANSPOSED
    dim3 gvt(Mtot / 128, Dc / 128, 1);
    TGP pv = {};
    pv.ah = wvh; pv.al = wvl; pv.a_ob = 0; pv.a_oh = 0; pv.a_st = Dc;
    pv.bh = xh;  pv.bl = xl;  pv.b_ob = 0; pv.b_oh = 0; pv.b_st = Dc;
    pv.K = Dc; pv.bias = bv;
    pv.o_hi = vth; pv.o_lo = vtl; pv.o_ob = 0; pv.o_oh = 0; pv.o_st = Mtot;
    tgemm<128, 6, 1, 2><<<gvt, 256, SM128>>>(pv);

    // FUSED feature maps
    dim3 gfeat(32, 2, 128);
    TGP pf = {};
    pf.ah = qh; pf.al = ql;
    pf.a_ob = (long long)Sc * Dc; pf.a_oh = HDc; pf.a_st = Dc;
    pf.bh = rfh; pf.bl = rfl;
    pf.b_ob = 0; pf.b_oh = (long long)Rc * HDc; pf.b_st = HDc;
    pf.K = HDc; pf.norm = nq;
    pf.o_hi = qph; pf.o_lo = qpl;
    pf.o_ob = (long long)16 * Sc * Rc; pf.o_oh = (long long)Sc * Rc; pf.o_st = Rc;
    pf.ah2 = rfh; pf.al2 = rfl;
    pf.a_ob2 = 0; pf.a_oh2 = (long long)Rc * HDc; pf.a_st2 = HDc;
    pf.bh2 = kh; pf.bl2 = kl;
    pf.b_ob2 = (long long)Sc * Dc; pf.b_oh2 = HDc; pf.b_st2 = Dc;
    pf.norm2 = nk;
    pf.o_hi2 = kpth; pf.o_lo2 = kptl;
    pf.o_ob2 = (long long)16 * Rc * Sc; pf.o_oh2 = (long long)Rc * Sc; pf.o_st2 = Sc;
    tgemm<128, 7, 1, 3><<<gfeat, 256, SM128>>>(pf);

    // kv aggregation GEMM (split-K x4)
    dim3 gkv(4, Rc / 128, Bc * Hc);
    TGP pkv = {};
    pkv.ah = kpth; pkv.al = kptl;
    pkv.a_ob = (long long)16 * Rc * Sc; pkv.a_oh = (long long)Rc * Sc; pkv.a_st = Sc;
    pkv.bh = vth; pkv.bl = vtl;
    pkv.b_ob = 4096; pkv.b_oh = (long long)64 * Mtot; pkv.b_st = Mtot;
    pkv.K = 1024;
    pkv.o0 = kvp; pkv.nrm_out = ksp;
    tgemm<64, 8, 0, 3><<<gkv, 256, SM64>>>(pkv);

    kvfinal_kernel<<<4096, 256>>>(kvp, ksp, kvth, kvtl, ksum);

    // attention readout + normalize
    dim3 gat(1, Sc / 128, Bc * Hc);
    TGP pa = {};
    pa.ah = qph; pa.al = qpl;
    pa.a_ob = (long long)16 * Sc * Rc; pa.a_oh = (long long)Sc * Rc; pa.a_st = Rc;
    pa.bh = kvth; pa.bl = kvtl;
    pa.b_ob = (long long)16 * HDc * Rc; pa.b_oh = (long long)HDc * Rc; pa.b_st = Rc;
    pa.K = Rc; pa.ksum = ksum;
    pa.o_hi = ath; pa.o_lo = atl;
    pa.o_ob = (long long)Sc * Dc; pa.o_oh = HDc; pa.o_st = Dc;
    tgemm<64, 4, 0, 3><<<gat, 256, SM64>>>(pa);

    // output projection
    TGP po = {};
    po.ah = ath; po.al = atl; po.a_ob = 0; po.a_oh = 0; po.a_st = Dc;
    po.bh = woh; po.bl = wol; po.b_ob = 0; po.b_oh = 0; po.b_st = Dc;
    po.K = Dc; po.bias = bo; po.o0 = out;
    po.o_ob = 0; po.o_oh = 0; po.o_st = Dc;
    dim3 gproj(Dc / 128, Mtot / 128, 1);
    tgemm<128, 0, 1, 2><<<gproj, 256, SM128>>>(po);
}